// round 6
// baseline (speedup 1.0000x reference)
#include <cuda_runtime.h>
#include <math.h>

#define HH   200
#define DD   300
#define TW   50
#define NS   2560
#define ND   256
#define DT   10
#define GG   600
#define GXW  1200
#define VOC  50000

// ---------------- device scratch ----------------
__device__ float g_P[VOC * GXW];        // emb @ [wf_ih; wb_ih]^T
__device__ float g_gxs[NS * GXW];       // sentence-level input gates
// pre-duplicated recurrent weights: wA[k*HH+j]=(r,r,z,z)  wB[k*HH+j]=(n,n)
// index 0=word-fwd 1=word-bwd 2=sent-fwd 3=sent-bwd
__device__ __align__(16) float4 g_wA[4][HH * HH];
__device__ __align__(8)  float2 g_wB[4][HH * HH];
__device__ float g_pool[NS * 2 * HH];
__device__ float g_poold[ND * 2 * HH];
__device__ int   g_slen[NS];
__device__ int   g_offs[ND];

// ---------------- helpers ----------------
typedef unsigned long long ull;
__device__ __forceinline__ ull pack1(float a) {
    ull r; asm("mov.b64 %0, {%1, %1};" : "=l"(r) : "f"(a)); return r;
}
__device__ __forceinline__ void fma2(ull& d, ull a, ull b) {
    asm("fma.rn.f32x2 %0, %1, %2, %0;" : "+l"(d) : "l"(a), "l"(b));
}
__device__ __forceinline__ void unpack2(ull v, float& a, float& b) {
    asm("mov.b64 {%0, %1}, %2;" : "=f"(a), "=f"(b) : "l"(v));
}
__device__ __forceinline__ float sigmoidf_(float x) {
    return __fdividef(1.f, 1.f + __expf(-x));
}
__device__ __forceinline__ float tanhf_(float x) {
    return 2.f * __fdividef(1.f, 1.f + __expf(-2.f * x)) - 1.f;
}

// ---------------- C[M,N](ldc) = A[M,K] @ B[N,K]^T  (fp32, f32x2) ----------------
__global__ __launch_bounds__(256) void gemm_bt(const float* __restrict__ A,
                                               const float* __restrict__ B,
                                               float* __restrict__ C,
                                               int M, int N, int K, int ldc) {
    __shared__ __align__(16) float As[20][132];
    __shared__ __align__(16) float Bs[20][68];
    int tid = threadIdx.x;
    int mb = blockIdx.y * 128, nb = blockIdx.x * 64;
    int tn = tid & 15, tm = tid >> 4;

    ull acc[4][4];
#pragma unroll
    for (int i = 0; i < 4; i++)
#pragma unroll
        for (int j = 0; j < 4; j++) acc[i][j] = 0ull;

    for (int k0 = 0; k0 < K; k0 += 20) {
#pragma unroll
        for (int l = 0; l < 10; l++) {
            int idx = tid + l * 256;
            int m = idx / 20, k = idx % 20;
            int gm = mb + m;
            As[k][m] = (gm < M) ? A[(size_t)gm * K + k0 + k] : 0.f;
        }
#pragma unroll
        for (int l = 0; l < 5; l++) {
            int idx = tid + l * 256;
            int n = idx / 20, k = idx % 20;
            int gn = nb + n;
            Bs[k][n] = (gn < N) ? B[(size_t)gn * K + k0 + k] : 0.f;
        }
        __syncthreads();
#pragma unroll
        for (int k = 0; k < 20; k++) {
            ulonglong2 a01 = *(const ulonglong2*)&As[k][tm * 8];
            ulonglong2 a23 = *(const ulonglong2*)&As[k][tm * 8 + 4];
            float4 bv = *(const float4*)&Bs[k][tn * 4];
            ull b0 = pack1(bv.x), b1 = pack1(bv.y), b2 = pack1(bv.z), b3 = pack1(bv.w);
            ull av[4] = {a01.x, a01.y, a23.x, a23.y};
#pragma unroll
            for (int i = 0; i < 4; i++) {
                fma2(acc[i][0], av[i], b0);
                fma2(acc[i][1], av[i], b1);
                fma2(acc[i][2], av[i], b2);
                fma2(acc[i][3], av[i], b3);
            }
        }
        __syncthreads();
    }
    int n0 = nb + tn * 4;
    if (n0 < N) {
#pragma unroll
        for (int i = 0; i < 4; i++) {
            int r0 = mb + tm * 8 + 2 * i;
            float v[2][4];
            unpack2(acc[i][0], v[0][0], v[1][0]);
            unpack2(acc[i][1], v[0][1], v[1][1]);
            unpack2(acc[i][2], v[0][2], v[1][2]);
            unpack2(acc[i][3], v[0][3], v[1][3]);
#pragma unroll
            for (int l = 0; l < 2; l++)
                if (r0 + l < M)
                    *(float4*)&C[(size_t)(r0 + l) * ldc + n0] =
                        make_float4(v[l][0], v[l][1], v[l][2], v[l][3]);
        }
    }
}

// ---------------- persistent GRU over all timesteps ----------------
// Threads 0..199 compute; threads 200..255 stream gx into smem via cp.async.
template <int BROWS, bool WORD>
__global__ __launch_bounds__(256, 2) void gru_seq(
    const int* __restrict__ toks, const int* __restrict__ dlens,
    const float* __restrict__ bi_f, const float* __restrict__ bh_f,
    const float* __restrict__ bi_b, const float* __restrict__ bh_b) {
    constexpr int BP = BROWS / 2;
    constexpr int TLEN = WORD ? TW : DT;
    constexpr int NCHUNK = BROWS * 150;  // float4 chunks of gx per step
    const float* gxsrc = WORD ? g_P : g_gxs;
    float* poolg = WORD ? g_pool : g_poold;

    extern __shared__ __align__(16) char sm_[];
    float2* hsT = (float2*)sm_;                                     // [HH*BP]
    float*  gxs_ = (float*)(sm_ + HH * BP * sizeof(float2));        // [BROWS*600]
    int* gxb = (int*)(sm_ + HH * BP * 8 + BROWS * 600 * 4);         // [TLEN*BROWS]
    int* sln = gxb + TLEN * BROWS;                                  // [BROWS]

    int dir = blockIdx.y;
    int b0 = blockIdx.x * BROWS;
    int widx = (WORD ? 0 : 2) + dir;
    const ulonglong2* wA = (const ulonglong2*)g_wA[widx];
    const ull* wB = (const ull*)g_wB[widx];
    const float* bi = dir ? bi_b : bi_f;
    const float* bh = dir ? bh_b : bh_f;
    int tid = threadIdx.x;

    for (int idx = tid; idx < HH * BP; idx += 256) hsT[idx] = make_float2(0.f, 0.f);
    for (int idx = tid; idx < TLEN * BROWS; idx += 256) {
        int t = idx / BROWS, b = idx % BROWS;
        int tt = dir ? (TLEN - 1 - t) : t;
        int bg = b0 + b;
        int row = WORD ? toks[bg * TLEN + tt] : (bg * TLEN + tt);
        gxb[idx] = row * GXW + dir * GG;
    }
    if (tid < BROWS) sln[tid] = WORD ? g_slen[b0 + tid] : dlens[b0 + tid];
    __syncthreads();

    int j = tid;
    float br = 0, bz = 0, bin = 0, bhn = 0;
    float pool_r[BROWS];
#pragma unroll
    for (int b = 0; b < BROWS; b++) pool_r[b] = 0.f;
    if (j < HH) {
        br = bi[j] + bh[j];
        bz = bi[HH + j] + bh[HH + j];
        bin = bi[2 * HH + j];
        bhn = bh[2 * HH + j];
    }

    for (int t = 0; t < TLEN; t++) {
        int tt = dir ? (TLEN - 1 - t) : t;
        // ---- issuers: prefetch this step's gx rows into smem ----
        if (tid >= 200) {
            const int* gq = gxb + t * BROWS;
            for (int c = tid - 200; c < NCHUNK; c += 56) {
                int b = c / 150, off = (c % 150) * 4;
                const float* src = gxsrc + gq[b] + off;
                unsigned int dst =
                    (unsigned int)__cvta_generic_to_shared(gxs_ + b * 600 + off);
                asm volatile("cp.async.cg.shared.global [%0], [%1], 16;"
                             :: "r"(dst), "l"(src));
            }
            asm volatile("cp.async.commit_group;");
        }
        // ---- compute: h @ W_hh (all rows) ----
        ull aR[BP], aZ[BP], aN[BP];
        if (j < HH) {
#pragma unroll
            for (int p = 0; p < BP; p++) { aR[p] = 0; aZ[p] = 0; aN[p] = 0; }
            const ulonglong2* wpA = wA + j;
            const ull* wpB = wB + j;
            ulonglong2 ra[4]; ull rb[4];
#pragma unroll
            for (int i = 0; i < 4; i++) { ra[i] = wpA[i * HH]; rb[i] = wpB[i * HH]; }
#pragma unroll 4
            for (int k = 0; k < HH; k++) {
                ulonglong2 wa = ra[k & 3];
                ull wn = rb[k & 3];
                int kp = k + 4;
                if (kp < HH) { ra[k & 3] = wpA[kp * HH]; rb[k & 3] = wpB[kp * HH]; }
#pragma unroll
                for (int q = 0; q < BP / 2; q++) {
                    ulonglong2 hq = *(const ulonglong2*)&hsT[k * BP + 2 * q];
                    fma2(aR[2 * q], hq.x, wa.x);
                    fma2(aZ[2 * q], hq.x, wa.y);
                    fma2(aN[2 * q], hq.x, wn);
                    fma2(aR[2 * q + 1], hq.y, wa.x);
                    fma2(aZ[2 * q + 1], hq.y, wa.y);
                    fma2(aN[2 * q + 1], hq.y, wn);
                }
            }
        }
        if (tid >= 200) asm volatile("cp.async.wait_group 0;");
        __syncthreads();   // matvec reads done; gx staged
        if (j < HH) {
#pragma unroll
            for (int p = 0; p < BP; p++) {
                float hr[2], hz[2], hn[2], hnew[2];
                unpack2(aR[p], hr[0], hr[1]);
                unpack2(aZ[p], hz[0], hz[1]);
                unpack2(aN[p], hn[0], hn[1]);
                float2 hold = hsT[j * BP + p];
#pragma unroll
                for (int l = 0; l < 2; l++) {
                    int b = 2 * p + l;
                    const float* gx = gxs_ + b * 600;
                    float r = sigmoidf_(gx[j] + hr[l] + br);
                    float z = sigmoidf_(gx[HH + j] + hz[l] + bz);
                    float nn = tanhf_(gx[2 * HH + j] + bin + r * (hn[l] + bhn));
                    float ho = l ? hold.y : hold.x;
                    hnew[l] = (1.f - z) * nn + z * ho;
                    if (tt < sln[b]) pool_r[b] += hnew[l];
                }
                hsT[j * BP + p] = make_float2(hnew[0], hnew[1]);
            }
        }
        __syncthreads();   // new h visible; gx buffer reusable
    }

    if (j < HH) {
#pragma unroll
        for (int b = 0; b < BROWS; b++) {
            int l = sln[b];
            poolg[(size_t)(b0 + b) * (2 * HH) + (size_t)dir * HH + j] =
                l ? pool_r[b] / (float)l : 0.f;
        }
    }
}

// ---------------- prep: weight packing (pre-duplicated), sent lens ----------------
__global__ void k_prep(const int* __restrict__ x,
                       const float* __restrict__ wf_hh, const float* __restrict__ wb_hh,
                       const float* __restrict__ sf_hh, const float* __restrict__ sb_hh) {
    int i0 = blockIdx.x * blockDim.x + threadIdx.x;
    int gs = gridDim.x * blockDim.x;
    const float* ws[4] = {wf_hh, wb_hh, sf_hh, sb_hh};
    for (int idx = i0; idx < HH * HH; idx += gs) {
        int k = idx / HH, j = idx % HH;
#pragma unroll
        for (int a = 0; a < 4; a++) {
            float r = ws[a][j * HH + k];
            float z = ws[a][(HH + j) * HH + k];
            float n = ws[a][(2 * HH + j) * HH + k];
            g_wA[a][idx] = make_float4(r, r, z, z);
            g_wB[a][idx] = make_float2(n, n);
        }
    }
    for (int s = i0; s < NS; s += gs) {
        int c = 0;
        for (int t = 0; t < TW; t++) c += (x[s * TW + t] != 0);
        g_slen[s] = c;
    }
}

__global__ void k_scan(const int* __restrict__ dl) {
    if (threadIdx.x == 0) {
        int a = 0;
        for (int i = 0; i < ND; i++) { g_offs[i] = a; a += dl[i]; }
    }
}

__global__ __launch_bounds__(128) void k_final(const int* __restrict__ dl,
                                               const float* __restrict__ doc_w,
                                               const float* __restrict__ doc_b,
                                               const float* __restrict__ sent_w,
                                               const float* __restrict__ sent_b,
                                               float* __restrict__ out) {
    __shared__ float d[2 * HH];
    __shared__ float redw[4];
    int doc = blockIdx.x, tid = threadIdx.x;
    int l = dl[doc];
    for (int f = tid; f < 2 * HH; f += 128)
        d[f] = g_poold[doc * 2 * HH + f];   // already averaged
    __syncthreads();
    for (int r = 0; r < 11; r++) {
        const float* w = (r == 0) ? doc_w : sent_w + (r - 1) * 2 * HH;
        float p = 0.f;
        for (int f = tid; f < 2 * HH; f += 128) p += d[f] * w[f];
        for (int o = 16; o; o >>= 1) p += __shfl_down_sync(0xFFFFFFFFu, p, o);
        if ((tid & 31) == 0) redw[tid >> 5] = p;
        __syncthreads();
        if (tid == 0) {
            float s = redw[0] + redw[1] + redw[2] + redw[3];
            if (r == 0) out[doc] = sigmoidf_(s + doc_b[0]);
            else if (r - 1 < l) out[ND + g_offs[doc] + (r - 1)] = sigmoidf_(s + sent_b[r - 1]);
        }
        __syncthreads();
    }
}

// ---------------- host ----------------
extern "C" void kernel_launch(void* const* d_in, const int* in_sizes, int n_in,
                              void* d_out, int out_size) {
    int base = (n_in >= 24) ? 1 : 0;  // doc_nums scalar present or not
    const int*   x        = (const int*)d_in[0];
    const int*   doc_lens = (const int*)d_in[1 + base];
    const float* emb      = (const float*)d_in[2 + base];
    const float* wf_ih    = (const float*)d_in[3 + base];
    const float* wf_hh    = (const float*)d_in[4 + base];
    const float* wf_bi    = (const float*)d_in[5 + base];
    const float* wf_bh    = (const float*)d_in[6 + base];
    const float* wb_ih    = (const float*)d_in[7 + base];
    const float* wb_hh    = (const float*)d_in[8 + base];
    const float* wb_bi    = (const float*)d_in[9 + base];
    const float* wb_bh    = (const float*)d_in[10 + base];
    const float* sf_ih    = (const float*)d_in[11 + base];
    const float* sf_hh    = (const float*)d_in[12 + base];
    const float* sf_bi    = (const float*)d_in[13 + base];
    const float* sf_bh    = (const float*)d_in[14 + base];
    const float* sb_ih    = (const float*)d_in[15 + base];
    const float* sb_hh    = (const float*)d_in[16 + base];
    const float* sb_bi    = (const float*)d_in[17 + base];
    const float* sb_bh    = (const float*)d_in[18 + base];
    const float* doc_w    = (const float*)d_in[19 + base];
    const float* doc_b    = (const float*)d_in[20 + base];
    const float* sent_w   = (const float*)d_in[21 + base];
    const float* sent_b   = (const float*)d_in[22 + base];
    float* out = (float*)d_out;

    float *P, *gxs, *pool;
    cudaGetSymbolAddress((void**)&P, g_P);
    cudaGetSymbolAddress((void**)&gxs, g_gxs);
    cudaGetSymbolAddress((void**)&pool, g_pool);

    // dynamic smem sizes
    const int SMW = HH * 10 * 8 + 20 * 600 * 4 + TW * 20 * 4 + 20 * 4;   // 68080
    const int SMS = HH * 4 * 8 + 8 * 600 * 4 + DT * 8 * 4 + 8 * 4;      // 25952
    cudaFuncSetAttribute(gru_seq<20, true>,
                         cudaFuncAttributeMaxDynamicSharedMemorySize, SMW);
    cudaFuncSetAttribute(gru_seq<8, false>,
                         cudaFuncAttributeMaxDynamicSharedMemorySize, SMS);

    k_prep<<<256, 256>>>(x, wf_hh, wb_hh, sf_hh, sb_hh);

    // P = emb @ [wf_ih; wb_ih]^T   (50000 x 1200)
    dim3 gP((600 + 63) / 64, (VOC + 127) / 128);
    gemm_bt<<<gP, 256>>>(emb, wf_ih, P, VOC, 600, DD, GXW);
    gemm_bt<<<gP, 256>>>(emb, wb_ih, P + 600, VOC, 600, DD, GXW);

    // word-level BiGRU: single persistent launch (128 x 2 blocks)
    gru_seq<20, true><<<dim3(NS / 20, 2), 256, SMW>>>(
        x, doc_lens, wf_bi, wf_bh, wb_bi, wb_bh);

    // sentence-level gates: gxs = s @ [sf_ih; sb_ih]^T   (2560 x 1200, K=400)
    dim3 gS((600 + 63) / 64, (NS + 127) / 128);
    gemm_bt<<<gS, 256>>>(pool, sf_ih, gxs, NS, 600, 2 * HH, GXW);
    gemm_bt<<<gS, 256>>>(pool, sb_ih, gxs + 600, NS, 600, 2 * HH, GXW);

    // sentence-level BiGRU: single persistent launch (32 x 2 blocks)
    gru_seq<8, false><<<dim3(ND / 8, 2), 256, SMS>>>(
        nullptr, doc_lens, sf_bi, sf_bh, sb_bi, sb_bh);

    k_scan<<<1, 32>>>(doc_lens);
    k_final<<<ND, 128>>>(doc_lens, doc_w, doc_b, sent_w, sent_b, out);
}

// round 7
// speedup vs baseline: 1.1829x; 1.1829x over previous
#include <cuda_runtime.h>
#include <math.h>

#define HH   200
#define DD   300
#define TW   50
#define NS   2560
#define ND   256
#define DT   10
#define GG   600
#define GXW  1200
#define VOC  50000

// ---------------- device scratch ----------------
__device__ float g_P[VOC * GXW];        // emb @ [wf_ih; wb_ih]^T
__device__ float g_gxs[NS * GXW];       // sentence-level input gates
// packed recurrent weights: [k*HH+j] -> float4(w_r, w_z, w_n, 0)
// index 0=word-fwd 1=word-bwd 2=sent-fwd 3=sent-bwd
__device__ __align__(16) float4 g_wP[4][HH * HH];
__device__ float g_pool[NS * 2 * HH];
__device__ float g_poold[ND * 2 * HH];
__device__ int   g_slen[NS];
__device__ int   g_offs[ND];

// ---------------- helpers ----------------
typedef unsigned long long ull;
__device__ __forceinline__ ull pack1(float a) {
    ull r; asm("mov.b64 %0, {%1, %1};" : "=l"(r) : "f"(a)); return r;
}
__device__ __forceinline__ void fma2(ull& d, ull a, ull b) {
    asm("fma.rn.f32x2 %0, %1, %2, %0;" : "+l"(d) : "l"(a), "l"(b));
}
__device__ __forceinline__ void unpack2(ull v, float& a, float& b) {
    asm("mov.b64 {%0, %1}, %2;" : "=f"(a), "=f"(b) : "l"(v));
}
__device__ __forceinline__ float sigmoidf_(float x) {
    return __fdividef(1.f, 1.f + __expf(-x));
}
__device__ __forceinline__ float tanhf_(float x) {
    return 2.f * __fdividef(1.f, 1.f + __expf(-2.f * x)) - 1.f;
}

// ---------------- C[M,N](ldc) = A[M,K] @ B[N,K]^T  (fp32, f32x2) ----------------
__global__ __launch_bounds__(256) void gemm_bt(const float* __restrict__ A,
                                               const float* __restrict__ B,
                                               float* __restrict__ C,
                                               int M, int N, int K, int ldc) {
    __shared__ __align__(16) float As[20][132];
    __shared__ __align__(16) float Bs[20][68];
    int tid = threadIdx.x;
    int mb = blockIdx.y * 128, nb = blockIdx.x * 64;
    int tn = tid & 15, tm = tid >> 4;

    ull acc[4][4];
#pragma unroll
    for (int i = 0; i < 4; i++)
#pragma unroll
        for (int j = 0; j < 4; j++) acc[i][j] = 0ull;

    for (int k0 = 0; k0 < K; k0 += 20) {
#pragma unroll
        for (int l = 0; l < 10; l++) {
            int idx = tid + l * 256;
            int m = idx / 20, k = idx % 20;
            int gm = mb + m;
            As[k][m] = (gm < M) ? A[(size_t)gm * K + k0 + k] : 0.f;
        }
#pragma unroll
        for (int l = 0; l < 5; l++) {
            int idx = tid + l * 256;
            int n = idx / 20, k = idx % 20;
            int gn = nb + n;
            Bs[k][n] = (gn < N) ? B[(size_t)gn * K + k0 + k] : 0.f;
        }
        __syncthreads();
#pragma unroll
        for (int k = 0; k < 20; k++) {
            ulonglong2 a01 = *(const ulonglong2*)&As[k][tm * 8];
            ulonglong2 a23 = *(const ulonglong2*)&As[k][tm * 8 + 4];
            float4 bv = *(const float4*)&Bs[k][tn * 4];
            ull b0 = pack1(bv.x), b1 = pack1(bv.y), b2 = pack1(bv.z), b3 = pack1(bv.w);
            ull av[4] = {a01.x, a01.y, a23.x, a23.y};
#pragma unroll
            for (int i = 0; i < 4; i++) {
                fma2(acc[i][0], av[i], b0);
                fma2(acc[i][1], av[i], b1);
                fma2(acc[i][2], av[i], b2);
                fma2(acc[i][3], av[i], b3);
            }
        }
        __syncthreads();
    }
    int n0 = nb + tn * 4;
    if (n0 < N) {
#pragma unroll
        for (int i = 0; i < 4; i++) {
            int r0 = mb + tm * 8 + 2 * i;
            float v[2][4];
            unpack2(acc[i][0], v[0][0], v[1][0]);
            unpack2(acc[i][1], v[0][1], v[1][1]);
            unpack2(acc[i][2], v[0][2], v[1][2]);
            unpack2(acc[i][3], v[0][3], v[1][3]);
#pragma unroll
            for (int l = 0; l < 2; l++)
                if (r0 + l < M)
                    *(float4*)&C[(size_t)(r0 + l) * ldc + n0] =
                        make_float4(v[l][0], v[l][1], v[l][2], v[l][3]);
        }
    }
}

// ---------------- persistent GRU, 512 threads = two independent 256-halves ----
// Halves share the weight stream (same addresses -> L1 dedup) but own
// disjoint rows. Named barriers keep halves decoupled.
template <int BROWS, bool WORD>
__global__ __launch_bounds__(512, 1) void gru_seq(
    const int* __restrict__ toks, const int* __restrict__ dlens,
    const float* __restrict__ bi_f, const float* __restrict__ bh_f,
    const float* __restrict__ bi_b, const float* __restrict__ bh_b) {
    constexpr int PW = BROWS / 2;       // row-pairs total (hsT width)
    constexpr int BP = PW / 2;          // row-pairs per thread (per half)
    constexpr int TLEN = WORD ? TW : DT;
    const float* gxsrc = WORD ? g_P : g_gxs;
    float* poolg = WORD ? g_pool : g_poold;

    extern __shared__ __align__(16) char sm_[];
    float2* hsT   = (float2*)sm_;                                   // [HH*PW]
    float* pool_s = (float*)(sm_ + HH * PW * sizeof(float2));       // [BROWS*HH]
    int* gxb = (int*)(sm_ + HH * PW * 8 + BROWS * HH * 4);          // [TLEN*BROWS]
    int* sln = gxb + TLEN * BROWS;                                  // [BROWS]

    int dir = blockIdx.y;
    int b0 = blockIdx.x * BROWS;
    const float4* wP = g_wP[(WORD ? 0 : 2) + dir];
    const float* bi = dir ? bi_b : bi_f;
    const float* bh = dir ? bh_b : bh_f;
    int tid = threadIdx.x;
    int half = tid >> 8;
    int j = tid & 255;
    int pbase = half * BP;

    for (int idx = tid; idx < HH * PW; idx += 512) hsT[idx] = make_float2(0.f, 0.f);
    for (int idx = tid; idx < BROWS * HH; idx += 512) pool_s[idx] = 0.f;
    for (int idx = tid; idx < TLEN * BROWS; idx += 512) {
        int t = idx / BROWS, b = idx % BROWS;
        int tt = dir ? (TLEN - 1 - t) : t;
        int bg = b0 + b;
        int row = WORD ? toks[bg * TLEN + tt] : (bg * TLEN + tt);
        gxb[idx] = row * GXW + dir * GG;
    }
    if (tid < BROWS) sln[tid] = WORD ? g_slen[b0 + tid] : dlens[b0 + tid];
    __syncthreads();

    float br = 0, bz = 0, bin = 0, bhn = 0;
    if (j < HH) {
        br = bi[j] + bh[j];
        bz = bi[HH + j] + bh[HH + j];
        bin = bi[2 * HH + j];
        bhn = bh[2 * HH + j];
    }

    for (int t = 0; t < TLEN; t++) {
        int tt = dir ? (TLEN - 1 - t) : t;
        ull aR[BP], aZ[BP], aN[BP];
        if (j < HH) {
#pragma unroll
            for (int p = 0; p < BP; p++) { aR[p] = 0; aZ[p] = 0; aN[p] = 0; }
            const float4* wp = wP + j;
            float4 ra[4];
#pragma unroll
            for (int i = 0; i < 4; i++) ra[i] = wp[i * HH];
#pragma unroll 4
            for (int k = 0; k < HH; k++) {
                float4 wc = ra[k & 3];
                int kp = k + 4;
                if (kp < HH) ra[k & 3] = wp[kp * HH];
                ull w0 = pack1(wc.x), w1 = pack1(wc.y), w2 = pack1(wc.z);
#pragma unroll
                for (int q = 0; q < BP / 2; q++) {
                    ulonglong2 hq =
                        *(const ulonglong2*)&hsT[k * PW + pbase + 2 * q];
                    fma2(aR[2 * q], hq.x, w0);
                    fma2(aZ[2 * q], hq.x, w1);
                    fma2(aN[2 * q], hq.x, w2);
                    fma2(aR[2 * q + 1], hq.y, w0);
                    fma2(aZ[2 * q + 1], hq.y, w1);
                    fma2(aN[2 * q + 1], hq.y, w2);
                }
            }
        }
        asm volatile("bar.sync %0, 256;" :: "r"(1 + half) : "memory");
        if (j < HH) {
#pragma unroll
            for (int p = 0; p < BP; p++) {
                int gp = pbase + p;
                float hr[2], hz[2], hn[2], hnew[2];
                unpack2(aR[p], hr[0], hr[1]);
                unpack2(aZ[p], hz[0], hz[1]);
                unpack2(aN[p], hn[0], hn[1]);
                float2 hold = hsT[j * PW + gp];
#pragma unroll
                for (int l = 0; l < 2; l++) {
                    int b = 2 * gp + l;
                    const float* gx = gxsrc + gxb[t * BROWS + b];
                    float r = sigmoidf_(gx[j] + hr[l] + br);
                    float z = sigmoidf_(gx[HH + j] + hz[l] + bz);
                    float nn = tanhf_(gx[2 * HH + j] + bin + r * (hn[l] + bhn));
                    float ho = l ? hold.y : hold.x;
                    hnew[l] = (1.f - z) * nn + z * ho;
                    if (tt < sln[b]) pool_s[b * HH + j] += hnew[l];
                }
                hsT[j * PW + gp] = make_float2(hnew[0], hnew[1]);
            }
        }
        asm volatile("bar.sync %0, 256;" :: "r"(1 + half) : "memory");
    }

    if (j < HH) {
#pragma unroll
        for (int p = 0; p < BP; p++) {
#pragma unroll
            for (int l = 0; l < 2; l++) {
                int b = 2 * (pbase + p) + l;
                int ln = sln[b];
                float v = pool_s[b * HH + j];
                poolg[(size_t)(b0 + b) * (2 * HH) + (size_t)dir * HH + j] =
                    ln ? v / (float)ln : 0.f;
            }
        }
    }
}

// ---------------- prep: weight packing, sent lens ----------------
__global__ void k_prep(const int* __restrict__ x,
                       const float* __restrict__ wf_hh, const float* __restrict__ wb_hh,
                       const float* __restrict__ sf_hh, const float* __restrict__ sb_hh) {
    int i0 = blockIdx.x * blockDim.x + threadIdx.x;
    int gs = gridDim.x * blockDim.x;
    const float* ws[4] = {wf_hh, wb_hh, sf_hh, sb_hh};
    for (int idx = i0; idx < HH * HH; idx += gs) {
        int k = idx / HH, j = idx % HH;
#pragma unroll
        for (int a = 0; a < 4; a++) {
            g_wP[a][idx] = make_float4(ws[a][j * HH + k],
                                       ws[a][(HH + j) * HH + k],
                                       ws[a][(2 * HH + j) * HH + k], 0.f);
        }
    }
    for (int s = i0; s < NS; s += gs) {
        int c = 0;
        for (int t = 0; t < TW; t++) c += (x[s * TW + t] != 0);
        g_slen[s] = c;
    }
}

__global__ void k_scan(const int* __restrict__ dl) {
    if (threadIdx.x == 0) {
        int a = 0;
        for (int i = 0; i < ND; i++) { g_offs[i] = a; a += dl[i]; }
    }
}

__global__ __launch_bounds__(128) void k_final(const int* __restrict__ dl,
                                               const float* __restrict__ doc_w,
                                               const float* __restrict__ doc_b,
                                               const float* __restrict__ sent_w,
                                               const float* __restrict__ sent_b,
                                               float* __restrict__ out) {
    __shared__ float d[2 * HH];
    __shared__ float redw[4];
    int doc = blockIdx.x, tid = threadIdx.x;
    int l = dl[doc];
    for (int f = tid; f < 2 * HH; f += 128)
        d[f] = g_poold[doc * 2 * HH + f];   // already averaged
    __syncthreads();
    for (int r = 0; r < 11; r++) {
        const float* w = (r == 0) ? doc_w : sent_w + (r - 1) * 2 * HH;
        float p = 0.f;
        for (int f = tid; f < 2 * HH; f += 128) p += d[f] * w[f];
        for (int o = 16; o; o >>= 1) p += __shfl_down_sync(0xFFFFFFFFu, p, o);
        if ((tid & 31) == 0) redw[tid >> 5] = p;
        __syncthreads();
        if (tid == 0) {
            float s = redw[0] + redw[1] + redw[2] + redw[3];
            if (r == 0) out[doc] = sigmoidf_(s + doc_b[0]);
            else if (r - 1 < l) out[ND + g_offs[doc] + (r - 1)] = sigmoidf_(s + sent_b[r - 1]);
        }
        __syncthreads();
    }
}

// ---------------- host ----------------
extern "C" void kernel_launch(void* const* d_in, const int* in_sizes, int n_in,
                              void* d_out, int out_size) {
    int base = (n_in >= 24) ? 1 : 0;  // doc_nums scalar present or not
    const int*   x        = (const int*)d_in[0];
    const int*   doc_lens = (const int*)d_in[1 + base];
    const float* emb      = (const float*)d_in[2 + base];
    const float* wf_ih    = (const float*)d_in[3 + base];
    const float* wf_hh    = (const float*)d_in[4 + base];
    const float* wf_bi    = (const float*)d_in[5 + base];
    const float* wf_bh    = (const float*)d_in[6 + base];
    const float* wb_ih    = (const float*)d_in[7 + base];
    const float* wb_hh    = (const float*)d_in[8 + base];
    const float* wb_bi    = (const float*)d_in[9 + base];
    const float* wb_bh    = (const float*)d_in[10 + base];
    const float* sf_ih    = (const float*)d_in[11 + base];
    const float* sf_hh    = (const float*)d_in[12 + base];
    const float* sf_bi    = (const float*)d_in[13 + base];
    const float* sf_bh    = (const float*)d_in[14 + base];
    const float* sb_ih    = (const float*)d_in[15 + base];
    const float* sb_hh    = (const float*)d_in[16 + base];
    const float* sb_bi    = (const float*)d_in[17 + base];
    const float* sb_bh    = (const float*)d_in[18 + base];
    const float* doc_w    = (const float*)d_in[19 + base];
    const float* doc_b    = (const float*)d_in[20 + base];
    const float* sent_w   = (const float*)d_in[21 + base];
    const float* sent_b   = (const float*)d_in[22 + base];
    float* out = (float*)d_out;

    float *P, *gxs, *pool;
    cudaGetSymbolAddress((void**)&P, g_P);
    cudaGetSymbolAddress((void**)&gxs, g_gxs);
    cudaGetSymbolAddress((void**)&pool, g_pool);

    // dynamic smem: hsT + pool + gxb + sln
    const int SMW = HH * 20 * 8 + 40 * HH * 4 + TW * 40 * 4 + 40 * 4;   // 72160
    const int SMS = HH * 8 * 8 + 16 * HH * 4 + DT * 16 * 4 + 16 * 4;    // 26304
    cudaFuncSetAttribute(gru_seq<40, true>,
                         cudaFuncAttributeMaxDynamicSharedMemorySize, SMW);
    cudaFuncSetAttribute(gru_seq<16, false>,
                         cudaFuncAttributeMaxDynamicSharedMemorySize, SMS);

    k_prep<<<256, 256>>>(x, wf_hh, wb_hh, sf_hh, sb_hh);

    // P = emb @ [wf_ih; wb_ih]^T   (50000 x 1200)
    dim3 gP((600 + 63) / 64, (VOC + 127) / 128);
    gemm_bt<<<gP, 256>>>(emb, wf_ih, P, VOC, 600, DD, GXW);
    gemm_bt<<<gP, 256>>>(emb, wb_ih, P + 600, VOC, 600, DD, GXW);

    // word-level BiGRU: persistent, 64 x 2 blocks, 512 threads
    gru_seq<40, true><<<dim3(NS / 40, 2), 512, SMW>>>(
        x, doc_lens, wf_bi, wf_bh, wb_bi, wb_bh);

    // sentence-level gates: gxs = s @ [sf_ih; sb_ih]^T   (2560 x 1200, K=400)
    dim3 gS((600 + 63) / 64, (NS + 127) / 128);
    gemm_bt<<<gS, 256>>>(pool, sf_ih, gxs, NS, 600, 2 * HH, GXW);
    gemm_bt<<<gS, 256>>>(pool, sb_ih, gxs + 600, NS, 600, 2 * HH, GXW);

    // sentence-level BiGRU: persistent, 16 x 2 blocks, 512 threads
    gru_seq<16, false><<<dim3(ND / 16, 2), 512, SMS>>>(
        nullptr, doc_lens, sf_bi, sf_bh, sb_bi, sb_bh);

    k_scan<<<1, 32>>>(doc_lens);
    k_final<<<ND, 128>>>(doc_lens, doc_w, doc_b, sent_w, sent_b, out);
}

// round 8
// speedup vs baseline: 1.2686x; 1.0724x over previous
#include <cuda_runtime.h>
#include <math.h>

#define HH   200
#define DD   300
#define TW   50
#define NS   2560
#define ND   256
#define DT   10
#define GG   600
#define GXW  1200
#define VOC  50000

// ---------------- device scratch ----------------
__device__ float g_P[VOC * GXW];        // emb @ [wf_ih; wb_ih]^T
__device__ float g_gxs[NS * GXW];       // sentence-level input gates
// packed recurrent weights: [k*HH+j] -> float4(w_r, w_z, w_n, 0)
// index 0=word-fwd 1=word-bwd 2=sent-fwd 3=sent-bwd
__device__ __align__(16) float4 g_wP[4][HH * HH];
__device__ float g_pool[NS * 2 * HH];
__device__ float g_poold[ND * 2 * HH];
__device__ int   g_slen[NS];
__device__ int   g_offs[ND];

// ---------------- helpers ----------------
typedef unsigned long long ull;
__device__ __forceinline__ ull pack1(float a) {
    ull r; asm("mov.b64 %0, {%1, %1};" : "=l"(r) : "f"(a)); return r;
}
__device__ __forceinline__ void fma2(ull& d, ull a, ull b) {
    asm("fma.rn.f32x2 %0, %1, %2, %0;" : "+l"(d) : "l"(a), "l"(b));
}
__device__ __forceinline__ void unpack2(ull v, float& a, float& b) {
    asm("mov.b64 {%0, %1}, %2;" : "=f"(a), "=f"(b) : "l"(v));
}
__device__ __forceinline__ float sigmoidf_(float x) {
    return __fdividef(1.f, 1.f + __expf(-x));
}
__device__ __forceinline__ float tanhf_(float x) {
    return 2.f * __fdividef(1.f, 1.f + __expf(-2.f * x)) - 1.f;
}

// ---------------- C[M,N](ldc) = A[M,K] @ B[N,K]^T  (fp32, f32x2) ----------------
__global__ __launch_bounds__(256) void gemm_bt(const float* __restrict__ A,
                                               const float* __restrict__ B,
                                               float* __restrict__ C,
                                               int M, int N, int K, int ldc) {
    __shared__ __align__(16) float As[20][132];
    __shared__ __align__(16) float Bs[20][68];
    int tid = threadIdx.x;
    int mb = blockIdx.y * 128, nb = blockIdx.x * 64;
    int tn = tid & 15, tm = tid >> 4;

    ull acc[4][4];
#pragma unroll
    for (int i = 0; i < 4; i++)
#pragma unroll
        for (int j = 0; j < 4; j++) acc[i][j] = 0ull;

    for (int k0 = 0; k0 < K; k0 += 20) {
#pragma unroll
        for (int l = 0; l < 10; l++) {
            int idx = tid + l * 256;
            int m = idx / 20, k = idx % 20;
            int gm = mb + m;
            As[k][m] = (gm < M) ? A[(size_t)gm * K + k0 + k] : 0.f;
        }
#pragma unroll
        for (int l = 0; l < 5; l++) {
            int idx = tid + l * 256;
            int n = idx / 20, k = idx % 20;
            int gn = nb + n;
            Bs[k][n] = (gn < N) ? B[(size_t)gn * K + k0 + k] : 0.f;
        }
        __syncthreads();
#pragma unroll
        for (int k = 0; k < 20; k++) {
            ulonglong2 a01 = *(const ulonglong2*)&As[k][tm * 8];
            ulonglong2 a23 = *(const ulonglong2*)&As[k][tm * 8 + 4];
            float4 bv = *(const float4*)&Bs[k][tn * 4];
            ull b0 = pack1(bv.x), b1 = pack1(bv.y), b2 = pack1(bv.z), b3 = pack1(bv.w);
            ull av[4] = {a01.x, a01.y, a23.x, a23.y};
#pragma unroll
            for (int i = 0; i < 4; i++) {
                fma2(acc[i][0], av[i], b0);
                fma2(acc[i][1], av[i], b1);
                fma2(acc[i][2], av[i], b2);
                fma2(acc[i][3], av[i], b3);
            }
        }
        __syncthreads();
    }
    int n0 = nb + tn * 4;
    if (n0 < N) {
#pragma unroll
        for (int i = 0; i < 4; i++) {
            int r0 = mb + tm * 8 + 2 * i;
            float v[2][4];
            unpack2(acc[i][0], v[0][0], v[1][0]);
            unpack2(acc[i][1], v[0][1], v[1][1]);
            unpack2(acc[i][2], v[0][2], v[1][2]);
            unpack2(acc[i][3], v[0][3], v[1][3]);
#pragma unroll
            for (int l = 0; l < 2; l++)
                if (r0 + l < M)
                    *(float4*)&C[(size_t)(r0 + l) * ldc + n0] =
                        make_float4(v[l][0], v[l][1], v[l][2], v[l][3]);
        }
    }
}

// ---------------- persistent GRU, 512 threads = two independent 256-halves ----
// Halves share the weight stream (L1 dedup) but own disjoint rows.
// Each half cp.async-stages its 20 gx rows into smem during the matvec.
template <int BROWS, bool WORD>
__global__ __launch_bounds__(512, 1) void gru_seq(
    const int* __restrict__ toks, const int* __restrict__ dlens,
    const float* __restrict__ bi_f, const float* __restrict__ bh_f,
    const float* __restrict__ bi_b, const float* __restrict__ bh_b) {
    constexpr int PW = BROWS / 2;       // row-pairs total (hsT width)
    constexpr int BP = PW / 2;          // row-pairs per thread (per half)
    constexpr int HR = BROWS / 2;       // rows per half
    constexpr int CH = HR * 150;        // float4 gx chunks per half per step
    constexpr int TLEN = WORD ? TW : DT;
    const float* gxsrc = WORD ? g_P : g_gxs;
    float* poolg = WORD ? g_pool : g_poold;

    extern __shared__ __align__(16) char sm_[];
    float2* hsT   = (float2*)sm_;                                   // [HH*PW]
    float*  gxs_  = (float*)(sm_ + HH * PW * 8);                    // [BROWS*600]
    float* pool_s = (float*)(sm_ + HH * PW * 8 + BROWS * 600 * 4);  // [BROWS*HH]
    int* gxb = (int*)(sm_ + HH * PW * 8 + BROWS * 600 * 4 + BROWS * HH * 4);
    int* sln = gxb + TLEN * BROWS;

    int dir = blockIdx.y;
    int b0 = blockIdx.x * BROWS;
    const float4* wP = g_wP[(WORD ? 0 : 2) + dir];
    const float* bi = dir ? bi_b : bi_f;
    const float* bh = dir ? bh_b : bh_f;
    int tid = threadIdx.x;
    int half = tid >> 8;
    int j = tid & 255;
    int pbase = half * BP;

    for (int idx = tid; idx < HH * PW; idx += 512) hsT[idx] = make_float2(0.f, 0.f);
    for (int idx = tid; idx < BROWS * HH; idx += 512) pool_s[idx] = 0.f;
    for (int idx = tid; idx < TLEN * BROWS; idx += 512) {
        int t = idx / BROWS, b = idx % BROWS;
        int tt = dir ? (TLEN - 1 - t) : t;
        int bg = b0 + b;
        int row = WORD ? toks[bg * TLEN + tt] : (bg * TLEN + tt);
        gxb[idx] = row * GXW + dir * GG;
    }
    if (tid < BROWS) sln[tid] = WORD ? g_slen[b0 + tid] : dlens[b0 + tid];
    __syncthreads();

    float br = 0, bz = 0, bin = 0, bhn = 0;
    if (j < HH) {
        br = bi[j] + bh[j];
        bz = bi[HH + j] + bh[HH + j];
        bin = bi[2 * HH + j];
        bhn = bh[2 * HH + j];
    }

    for (int t = 0; t < TLEN; t++) {
        int tt = dir ? (TLEN - 1 - t) : t;
        // ---- stage this half's gx rows into smem (overlaps the matvec) ----
        {
            const int* gq = gxb + t * BROWS;
#pragma unroll 2
            for (int c = j; c < CH; c += 256) {
                int b = half * HR + c / 150;
                int off = (c % 150) * 4;
                const float* src = gxsrc + gq[b] + off;
                unsigned int dst =
                    (unsigned int)__cvta_generic_to_shared(gxs_ + b * 600 + off);
                asm volatile("cp.async.cg.shared.global [%0], [%1], 16;"
                             :: "r"(dst), "l"(src));
            }
            asm volatile("cp.async.commit_group;");
        }
        // ---- matvec: h @ W_hh ----
        ull aR[BP], aZ[BP], aN[BP];
        if (j < HH) {
#pragma unroll
            for (int p = 0; p < BP; p++) { aR[p] = 0; aZ[p] = 0; aN[p] = 0; }
            const float4* wp = wP + j;
            float4 ra[4];
#pragma unroll
            for (int i = 0; i < 4; i++) ra[i] = wp[i * HH];
#pragma unroll 4
            for (int k = 0; k < HH; k++) {
                float4 wc = ra[k & 3];
                int kp = k + 4;
                if (kp < HH) ra[k & 3] = wp[kp * HH];
                ull w0 = pack1(wc.x), w1 = pack1(wc.y), w2 = pack1(wc.z);
#pragma unroll
                for (int q = 0; q < BP / 2; q++) {
                    ulonglong2 hq =
                        *(const ulonglong2*)&hsT[k * PW + pbase + 2 * q];
                    fma2(aR[2 * q], hq.x, w0);
                    fma2(aZ[2 * q], hq.x, w1);
                    fma2(aN[2 * q], hq.x, w2);
                    fma2(aR[2 * q + 1], hq.y, w0);
                    fma2(aZ[2 * q + 1], hq.y, w1);
                    fma2(aN[2 * q + 1], hq.y, w2);
                }
            }
        }
        asm volatile("cp.async.wait_group 0;");
        asm volatile("bar.sync %0, 256;" :: "r"(1 + half) : "memory");
        if (j < HH) {
#pragma unroll
            for (int p = 0; p < BP; p++) {
                int gp = pbase + p;
                float hr[2], hz[2], hn[2], hnew[2];
                unpack2(aR[p], hr[0], hr[1]);
                unpack2(aZ[p], hz[0], hz[1]);
                unpack2(aN[p], hn[0], hn[1]);
                float2 hold = hsT[j * PW + gp];
#pragma unroll
                for (int l = 0; l < 2; l++) {
                    int b = 2 * gp + l;
                    const float* gx = gxs_ + b * 600;
                    float r = sigmoidf_(gx[j] + hr[l] + br);
                    float z = sigmoidf_(gx[HH + j] + hz[l] + bz);
                    float nn = tanhf_(gx[2 * HH + j] + bin + r * (hn[l] + bhn));
                    float ho = l ? hold.y : hold.x;
                    hnew[l] = (1.f - z) * nn + z * ho;
                    if (tt < sln[b]) pool_s[b * HH + j] += hnew[l];
                }
                hsT[j * PW + gp] = make_float2(hnew[0], hnew[1]);
            }
        }
        asm volatile("bar.sync %0, 256;" :: "r"(1 + half) : "memory");
    }

    if (j < HH) {
#pragma unroll
        for (int p = 0; p < BP; p++) {
#pragma unroll
            for (int l = 0; l < 2; l++) {
                int b = 2 * (pbase + p) + l;
                int ln = sln[b];
                float v = pool_s[b * HH + j];
                poolg[(size_t)(b0 + b) * (2 * HH) + (size_t)dir * HH + j] =
                    ln ? v / (float)ln : 0.f;
            }
        }
    }
}

// ---------------- prep: weight packing, sent lens ----------------
__global__ void k_prep(const int* __restrict__ x,
                       const float* __restrict__ wf_hh, const float* __restrict__ wb_hh,
                       const float* __restrict__ sf_hh, const float* __restrict__ sb_hh) {
    int i0 = blockIdx.x * blockDim.x + threadIdx.x;
    int gs = gridDim.x * blockDim.x;
    const float* ws[4] = {wf_hh, wb_hh, sf_hh, sb_hh};
    for (int idx = i0; idx < HH * HH; idx += gs) {
        int k = idx / HH, j = idx % HH;
#pragma unroll
        for (int a = 0; a < 4; a++) {
            g_wP[a][idx] = make_float4(ws[a][j * HH + k],
                                       ws[a][(HH + j) * HH + k],
                                       ws[a][(2 * HH + j) * HH + k], 0.f);
        }
    }
    for (int s = i0; s < NS; s += gs) {
        int c = 0;
        for (int t = 0; t < TW; t++) c += (x[s * TW + t] != 0);
        g_slen[s] = c;
    }
}

__global__ void k_scan(const int* __restrict__ dl) {
    if (threadIdx.x == 0) {
        int a = 0;
        for (int i = 0; i < ND; i++) { g_offs[i] = a; a += dl[i]; }
    }
}

__global__ __launch_bounds__(128) void k_final(const int* __restrict__ dl,
                                               const float* __restrict__ doc_w,
                                               const float* __restrict__ doc_b,
                                               const float* __restrict__ sent_w,
                                               const float* __restrict__ sent_b,
                                               float* __restrict__ out) {
    __shared__ float d[2 * HH];
    __shared__ float redw[4];
    int doc = blockIdx.x, tid = threadIdx.x;
    int l = dl[doc];
    for (int f = tid; f < 2 * HH; f += 128)
        d[f] = g_poold[doc * 2 * HH + f];   // already averaged
    __syncthreads();
    for (int r = 0; r < 11; r++) {
        const float* w = (r == 0) ? doc_w : sent_w + (r - 1) * 2 * HH;
        float p = 0.f;
        for (int f = tid; f < 2 * HH; f += 128) p += d[f] * w[f];
        for (int o = 16; o; o >>= 1) p += __shfl_down_sync(0xFFFFFFFFu, p, o);
        if ((tid & 31) == 0) redw[tid >> 5] = p;
        __syncthreads();
        if (tid == 0) {
            float s = redw[0] + redw[1] + redw[2] + redw[3];
            if (r == 0) out[doc] = sigmoidf_(s + doc_b[0]);
            else if (r - 1 < l) out[ND + g_offs[doc] + (r - 1)] = sigmoidf_(s + sent_b[r - 1]);
        }
        __syncthreads();
    }
}

// ---------------- host ----------------
extern "C" void kernel_launch(void* const* d_in, const int* in_sizes, int n_in,
                              void* d_out, int out_size) {
    int base = (n_in >= 24) ? 1 : 0;  // doc_nums scalar present or not
    const int*   x        = (const int*)d_in[0];
    const int*   doc_lens = (const int*)d_in[1 + base];
    const float* emb      = (const float*)d_in[2 + base];
    const float* wf_ih    = (const float*)d_in[3 + base];
    const float* wf_hh    = (const float*)d_in[4 + base];
    const float* wf_bi    = (const float*)d_in[5 + base];
    const float* wf_bh    = (const float*)d_in[6 + base];
    const float* wb_ih    = (const float*)d_in[7 + base];
    const float* wb_hh    = (const float*)d_in[8 + base];
    const float* wb_bi    = (const float*)d_in[9 + base];
    const float* wb_bh    = (const float*)d_in[10 + base];
    const float* sf_ih    = (const float*)d_in[11 + base];
    const float* sf_hh    = (const float*)d_in[12 + base];
    const float* sf_bi    = (const float*)d_in[13 + base];
    const float* sf_bh    = (const float*)d_in[14 + base];
    const float* sb_ih    = (const float*)d_in[15 + base];
    const float* sb_hh    = (const float*)d_in[16 + base];
    const float* sb_bi    = (const float*)d_in[17 + base];
    const float* sb_bh    = (const float*)d_in[18 + base];
    const float* doc_w    = (const float*)d_in[19 + base];
    const float* doc_b    = (const float*)d_in[20 + base];
    const float* sent_w   = (const float*)d_in[21 + base];
    const float* sent_b   = (const float*)d_in[22 + base];
    float* out = (float*)d_out;

    float *P, *gxs, *pool;
    cudaGetSymbolAddress((void**)&P, g_P);
    cudaGetSymbolAddress((void**)&gxs, g_gxs);
    cudaGetSymbolAddress((void**)&pool, g_pool);

    // dynamic smem: hsT + gx stage + pool + gxb + sln
    const int SMW = HH * 20 * 8 + 40 * 600 * 4 + 40 * HH * 4 + TW * 40 * 4 + 40 * 4;
    const int SMS = HH * 8 * 8 + 16 * 600 * 4 + 16 * HH * 4 + DT * 16 * 4 + 16 * 4;
    cudaFuncSetAttribute(gru_seq<40, true>,
                         cudaFuncAttributeMaxDynamicSharedMemorySize, SMW);
    cudaFuncSetAttribute(gru_seq<16, false>,
                         cudaFuncAttributeMaxDynamicSharedMemorySize, SMS);

    k_prep<<<256, 256>>>(x, wf_hh, wb_hh, sf_hh, sb_hh);

    // P = emb @ [wf_ih; wb_ih]^T   (50000 x 1200)
    dim3 gP((600 + 63) / 64, (VOC + 127) / 128);
    gemm_bt<<<gP, 256>>>(emb, wf_ih, P, VOC, 600, DD, GXW);
    gemm_bt<<<gP, 256>>>(emb, wb_ih, P + 600, VOC, 600, DD, GXW);

    // word-level BiGRU: persistent, 64 x 2 blocks, 512 threads
    gru_seq<40, true><<<dim3(NS / 40, 2), 512, SMW>>>(
        x, doc_lens, wf_bi, wf_bh, wb_bi, wb_bh);

    // sentence-level gates: gxs = s @ [sf_ih; sb_ih]^T   (2560 x 1200, K=400)
    dim3 gS((600 + 63) / 64, (NS + 127) / 128);
    gemm_bt<<<gS, 256>>>(pool, sf_ih, gxs, NS, 600, 2 * HH, GXW);
    gemm_bt<<<gS, 256>>>(pool, sb_ih, gxs + 600, NS, 600, 2 * HH, GXW);

    // sentence-level BiGRU: persistent, 16 x 2 blocks, 512 threads
    gru_seq<16, false><<<dim3(ND / 16, 2), 512, SMS>>>(
        nullptr, doc_lens, sf_bi, sf_bh, sb_bi, sb_bh);

    k_scan<<<1, 32>>>(doc_lens);
    k_final<<<ND, 128>>>(doc_lens, doc_w, doc_b, sent_w, sent_b, out);
}

// round 9
// speedup vs baseline: 1.5164x; 1.1953x over previous
#include <cuda_runtime.h>
#include <math.h>

#define HH   200
#define DD   300
#define TW   50
#define NS   2560
#define ND   256
#define DT   10
#define GG   600
#define GXW  1200
#define VOC  50000

// ---------------- device scratch ----------------
__device__ float g_P[VOC * GXW];        // emb @ [wf_ih; wb_ih]^T
__device__ float g_gxs[NS * GXW];       // sentence-level input gates
// packed recurrent weights: [k*HH+j] -> float4(w_r, w_z, w_n, 0)
__device__ __align__(16) float4 g_wP[4][HH * HH];
__device__ float g_pool[NS * 2 * HH];
__device__ float g_poold[ND * 2 * HH];
__device__ int   g_slen[NS];
__device__ int   g_offs[ND];

// ---------------- helpers ----------------
typedef unsigned long long ull;
__device__ __forceinline__ ull pack1(float a) {
    ull r; asm("mov.b64 %0, {%1, %1};" : "=l"(r) : "f"(a)); return r;
}
__device__ __forceinline__ void fma2(ull& d, ull a, ull b) {
    asm("fma.rn.f32x2 %0, %1, %2, %0;" : "+l"(d) : "l"(a), "l"(b));
}
__device__ __forceinline__ void unpack2(ull v, float& a, float& b) {
    asm("mov.b64 {%0, %1}, %2;" : "=f"(a), "=f"(b) : "l"(v));
}
__device__ __forceinline__ float sigmoidf_(float x) {
    return __fdividef(1.f, 1.f + __expf(-x));
}
__device__ __forceinline__ float tanhf_(float x) {
    return 2.f * __fdividef(1.f, 1.f + __expf(-2.f * x)) - 1.f;
}
__device__ __forceinline__ unsigned int to_tf32(float f) {
    unsigned int u;
    asm("cvt.rna.tf32.f32 %0, %1;" : "=r"(u) : "f"(f));
    return u;
}

// ---------------- tf32 tensor-core GEMM: C[M,N](ldc) = A[M,K] @ B[N,K]^T ------
// 128x64 tile, BK=32, 256 threads = 8 warps (4M x 2N), warp tile 32x32.
__global__ __launch_bounds__(256) void gemm_tf32(const float* __restrict__ A,
                                                 const float* __restrict__ B,
                                                 float* __restrict__ C,
                                                 int M, int N, int K, int ldc) {
    __shared__ __align__(16) unsigned int As[128][36];
    __shared__ __align__(16) unsigned int Bs[64][36];
    int tid = threadIdx.x;
    int mb = blockIdx.y * 128, nb = blockIdx.x * 64;
    int warp = tid >> 5, lane = tid & 31;
    int wm = warp & 3, wn = warp >> 2;
    int gid = lane >> 2, tig = lane & 3;

    float c[2][4][4];
#pragma unroll
    for (int mt = 0; mt < 2; mt++)
#pragma unroll
        for (int nt = 0; nt < 4; nt++)
#pragma unroll
            for (int i = 0; i < 4; i++) c[mt][nt][i] = 0.f;

    int r = tid >> 3, c4 = (tid & 7) * 4;
    for (int k0 = 0; k0 < K; k0 += 32) {
        int col = k0 + c4;
        bool okc = (col + 4 <= K);
#pragma unroll
        for (int l = 0; l < 4; l++) {
            int row = r + l * 32;
            int gm = mb + row;
            float4 v = make_float4(0.f, 0.f, 0.f, 0.f);
            if (okc && gm < M) v = *(const float4*)&A[(size_t)gm * K + col];
            As[row][c4]     = to_tf32(v.x);
            As[row][c4 + 1] = to_tf32(v.y);
            As[row][c4 + 2] = to_tf32(v.z);
            As[row][c4 + 3] = to_tf32(v.w);
        }
#pragma unroll
        for (int l = 0; l < 2; l++) {
            int row = r + l * 32;
            int gn = nb + row;
            float4 v = make_float4(0.f, 0.f, 0.f, 0.f);
            if (okc && gn < N) v = *(const float4*)&B[(size_t)gn * K + col];
            Bs[row][c4]     = to_tf32(v.x);
            Bs[row][c4 + 1] = to_tf32(v.y);
            Bs[row][c4 + 2] = to_tf32(v.z);
            Bs[row][c4 + 3] = to_tf32(v.w);
        }
        __syncthreads();
#pragma unroll
        for (int kc = 0; kc < 4; kc++) {
            int kk = kc * 8;
            unsigned int af[2][4];
#pragma unroll
            for (int mt = 0; mt < 2; mt++) {
                int mr = wm * 32 + mt * 16;
                af[mt][0] = As[mr + gid][kk + tig];
                af[mt][1] = As[mr + gid + 8][kk + tig];
                af[mt][2] = As[mr + gid][kk + tig + 4];
                af[mt][3] = As[mr + gid + 8][kk + tig + 4];
            }
            unsigned int bf[4][2];
#pragma unroll
            for (int nt = 0; nt < 4; nt++) {
                int nc = wn * 32 + nt * 8;
                bf[nt][0] = Bs[nc + gid][kk + tig];
                bf[nt][1] = Bs[nc + gid][kk + tig + 4];
            }
#pragma unroll
            for (int mt = 0; mt < 2; mt++)
#pragma unroll
                for (int nt = 0; nt < 4; nt++) {
                    asm volatile(
                        "mma.sync.aligned.m16n8k8.row.col.f32.tf32.tf32.f32 "
                        "{%0,%1,%2,%3}, {%4,%5,%6,%7}, {%8,%9}, {%0,%1,%2,%3};"
                        : "+f"(c[mt][nt][0]), "+f"(c[mt][nt][1]),
                          "+f"(c[mt][nt][2]), "+f"(c[mt][nt][3])
                        : "r"(af[mt][0]), "r"(af[mt][1]),
                          "r"(af[mt][2]), "r"(af[mt][3]),
                          "r"(bf[nt][0]), "r"(bf[nt][1]));
                }
        }
        __syncthreads();
    }
#pragma unroll
    for (int mt = 0; mt < 2; mt++)
#pragma unroll
        for (int nt = 0; nt < 4; nt++) {
            int row0 = mb + wm * 32 + mt * 16 + gid;
            int col0 = nb + wn * 32 + nt * 8 + tig * 2;
            if (col0 < N) {
                if (row0 < M)
                    *(float2*)&C[(size_t)row0 * ldc + col0] =
                        make_float2(c[mt][nt][0], c[mt][nt][1]);
                if (row0 + 8 < M)
                    *(float2*)&C[(size_t)(row0 + 8) * ldc + col0] =
                        make_float2(c[mt][nt][2], c[mt][nt][3]);
            }
        }
}

// ---------------- fp32 f32x2 GEMM (kept for the small sentence-gates GEMM) ----
__global__ __launch_bounds__(256) void gemm_bt(const float* __restrict__ A,
                                               const float* __restrict__ B,
                                               float* __restrict__ C,
                                               int M, int N, int K, int ldc) {
    __shared__ __align__(16) float As[20][132];
    __shared__ __align__(16) float Bs[20][68];
    int tid = threadIdx.x;
    int mb = blockIdx.y * 128, nb = blockIdx.x * 64;
    int tn = tid & 15, tm = tid >> 4;

    ull acc[4][4];
#pragma unroll
    for (int i = 0; i < 4; i++)
#pragma unroll
        for (int j = 0; j < 4; j++) acc[i][j] = 0ull;

    for (int k0 = 0; k0 < K; k0 += 20) {
#pragma unroll
        for (int l = 0; l < 10; l++) {
            int idx = tid + l * 256;
            int m = idx / 20, k = idx % 20;
            int gm = mb + m;
            As[k][m] = (gm < M) ? A[(size_t)gm * K + k0 + k] : 0.f;
        }
#pragma unroll
        for (int l = 0; l < 5; l++) {
            int idx = tid + l * 256;
            int n = idx / 20, k = idx % 20;
            int gn = nb + n;
            Bs[k][n] = (gn < N) ? B[(size_t)gn * K + k0 + k] : 0.f;
        }
        __syncthreads();
#pragma unroll
        for (int k = 0; k < 20; k++) {
            ulonglong2 a01 = *(const ulonglong2*)&As[k][tm * 8];
            ulonglong2 a23 = *(const ulonglong2*)&As[k][tm * 8 + 4];
            float4 bv = *(const float4*)&Bs[k][tn * 4];
            ull b0 = pack1(bv.x), b1 = pack1(bv.y), b2 = pack1(bv.z), b3 = pack1(bv.w);
            ull av[4] = {a01.x, a01.y, a23.x, a23.y};
#pragma unroll
            for (int i = 0; i < 4; i++) {
                fma2(acc[i][0], av[i], b0);
                fma2(acc[i][1], av[i], b1);
                fma2(acc[i][2], av[i], b2);
                fma2(acc[i][3], av[i], b3);
            }
        }
        __syncthreads();
    }
    int n0 = nb + tn * 4;
    if (n0 < N) {
#pragma unroll
        for (int i = 0; i < 4; i++) {
            int r0 = mb + tm * 8 + 2 * i;
            float v[2][4];
            unpack2(acc[i][0], v[0][0], v[1][0]);
            unpack2(acc[i][1], v[0][1], v[1][1]);
            unpack2(acc[i][2], v[0][2], v[1][2]);
            unpack2(acc[i][3], v[0][3], v[1][3]);
#pragma unroll
            for (int l = 0; l < 2; l++)
                if (r0 + l < M)
                    *(float4*)&C[(size_t)(r0 + l) * ldc + n0] =
                        make_float4(v[l][0], v[l][1], v[l][2], v[l][3]);
        }
    }
}

// ---------------- persistent GRU, 512 threads = two independent 256-halves ----
template <int BROWS, bool WORD>
__global__ __launch_bounds__(512, 1) void gru_seq(
    const int* __restrict__ toks, const int* __restrict__ dlens,
    const float* __restrict__ bi_f, const float* __restrict__ bh_f,
    const float* __restrict__ bi_b, const float* __restrict__ bh_b) {
    constexpr int PW = BROWS / 2;
    constexpr int BP = PW / 2;
    constexpr int HR = BROWS / 2;
    constexpr int CH = HR * 150;
    constexpr int TLEN = WORD ? TW : DT;
    const float* gxsrc = WORD ? g_P : g_gxs;
    float* poolg = WORD ? g_pool : g_poold;

    extern __shared__ __align__(16) char sm_[];
    float2* hsT   = (float2*)sm_;
    float*  gxs_  = (float*)(sm_ + HH * PW * 8);
    float* pool_s = (float*)(sm_ + HH * PW * 8 + BROWS * 600 * 4);
    int* gxb = (int*)(sm_ + HH * PW * 8 + BROWS * 600 * 4 + BROWS * HH * 4);
    int* sln = gxb + TLEN * BROWS;

    int dir = blockIdx.y;
    int b0 = blockIdx.x * BROWS;
    const float4* wP = g_wP[(WORD ? 0 : 2) + dir];
    const float* bi = dir ? bi_b : bi_f;
    const float* bh = dir ? bh_b : bh_f;
    int tid = threadIdx.x;
    int half = tid >> 8;
    int j = tid & 255;
    int pbase = half * BP;

    for (int idx = tid; idx < HH * PW; idx += 512) hsT[idx] = make_float2(0.f, 0.f);
    for (int idx = tid; idx < BROWS * HH; idx += 512) pool_s[idx] = 0.f;
    for (int idx = tid; idx < TLEN * BROWS; idx += 512) {
        int t = idx / BROWS, b = idx % BROWS;
        int tt = dir ? (TLEN - 1 - t) : t;
        int bg = b0 + b;
        int row = WORD ? toks[bg * TLEN + tt] : (bg * TLEN + tt);
        gxb[idx] = row * GXW + dir * GG;
    }
    if (tid < BROWS) sln[tid] = WORD ? g_slen[b0 + tid] : dlens[b0 + tid];
    __syncthreads();

    float br = 0, bz = 0, bin = 0, bhn = 0;
    if (j < HH) {
        br = bi[j] + bh[j];
        bz = bi[HH + j] + bh[HH + j];
        bin = bi[2 * HH + j];
        bhn = bh[2 * HH + j];
    }

    for (int t = 0; t < TLEN; t++) {
        int tt = dir ? (TLEN - 1 - t) : t;
        {
            const int* gq = gxb + t * BROWS;
#pragma unroll 2
            for (int c = j; c < CH; c += 256) {
                int b = half * HR + c / 150;
                int off = (c % 150) * 4;
                const float* src = gxsrc + gq[b] + off;
                unsigned int dst =
                    (unsigned int)__cvta_generic_to_shared(gxs_ + b * 600 + off);
                asm volatile("cp.async.cg.shared.global [%0], [%1], 16;"
                             :: "r"(dst), "l"(src));
            }
            asm volatile("cp.async.commit_group;");
        }
        ull aR[BP], aZ[BP], aN[BP];
        if (j < HH) {
#pragma unroll
            for (int p = 0; p < BP; p++) { aR[p] = 0; aZ[p] = 0; aN[p] = 0; }
            const float4* wp = wP + j;
            float4 ra[4];
#pragma unroll
            for (int i = 0; i < 4; i++) ra[i] = wp[i * HH];
#pragma unroll 4
            for (int k = 0; k < HH; k++) {
                float4 wc = ra[k & 3];
                int kp = k + 4;
                if (kp < HH) ra[k & 3] = wp[kp * HH];
                ull w0 = pack1(wc.x), w1 = pack1(wc.y), w2 = pack1(wc.z);
#pragma unroll
                for (int q = 0; q < BP / 2; q++) {
                    ulonglong2 hq =
                        *(const ulonglong2*)&hsT[k * PW + pbase + 2 * q];
                    fma2(aR[2 * q], hq.x, w0);
                    fma2(aZ[2 * q], hq.x, w1);
                    fma2(aN[2 * q], hq.x, w2);
                    fma2(aR[2 * q + 1], hq.y, w0);
                    fma2(aZ[2 * q + 1], hq.y, w1);
                    fma2(aN[2 * q + 1], hq.y, w2);
                }
            }
        }
        asm volatile("cp.async.wait_group 0;");
        asm volatile("bar.sync %0, 256;" :: "r"(1 + half) : "memory");
        if (j < HH) {
#pragma unroll
            for (int p = 0; p < BP; p++) {
                int gp = pbase + p;
                float hr[2], hz[2], hn[2], hnew[2];
                unpack2(aR[p], hr[0], hr[1]);
                unpack2(aZ[p], hz[0], hz[1]);
                unpack2(aN[p], hn[0], hn[1]);
                float2 hold = hsT[j * PW + gp];
#pragma unroll
                for (int l = 0; l < 2; l++) {
                    int b = 2 * gp + l;
                    const float* gx = gxs_ + b * 600;
                    float r = sigmoidf_(gx[j] + hr[l] + br);
                    float z = sigmoidf_(gx[HH + j] + hz[l] + bz);
                    float nn = tanhf_(gx[2 * HH + j] + bin + r * (hn[l] + bhn));
                    float ho = l ? hold.y : hold.x;
                    hnew[l] = (1.f - z) * nn + z * ho;
                    if (tt < sln[b]) pool_s[b * HH + j] += hnew[l];
                }
                hsT[j * PW + gp] = make_float2(hnew[0], hnew[1]);
            }
        }
        asm volatile("bar.sync %0, 256;" :: "r"(1 + half) : "memory");
    }

    if (j < HH) {
#pragma unroll
        for (int p = 0; p < BP; p++) {
#pragma unroll
            for (int l = 0; l < 2; l++) {
                int b = 2 * (pbase + p) + l;
                int ln = sln[b];
                float v = pool_s[b * HH + j];
                poolg[(size_t)(b0 + b) * (2 * HH) + (size_t)dir * HH + j] =
                    ln ? v / (float)ln : 0.f;
            }
        }
    }
}

// ---------------- prep: weight packing, sent lens ----------------
__global__ void k_prep(const int* __restrict__ x,
                       const float* __restrict__ wf_hh, const float* __restrict__ wb_hh,
                       const float* __restrict__ sf_hh, const float* __restrict__ sb_hh) {
    int i0 = blockIdx.x * blockDim.x + threadIdx.x;
    int gs = gridDim.x * blockDim.x;
    const float* ws[4] = {wf_hh, wb_hh, sf_hh, sb_hh};
    for (int idx = i0; idx < HH * HH; idx += gs) {
        int k = idx / HH, j = idx % HH;
#pragma unroll
        for (int a = 0; a < 4; a++) {
            g_wP[a][idx] = make_float4(ws[a][j * HH + k],
                                       ws[a][(HH + j) * HH + k],
                                       ws[a][(2 * HH + j) * HH + k], 0.f);
        }
    }
    for (int s = i0; s < NS; s += gs) {
        int c = 0;
        for (int t = 0; t < TW; t++) c += (x[s * TW + t] != 0);
        g_slen[s] = c;
    }
}

__global__ void k_scan(const int* __restrict__ dl) {
    if (threadIdx.x == 0) {
        int a = 0;
        for (int i = 0; i < ND; i++) { g_offs[i] = a; a += dl[i]; }
    }
}

__global__ __launch_bounds__(128) void k_final(const int* __restrict__ dl,
                                               const float* __restrict__ doc_w,
                                               const float* __restrict__ doc_b,
                                               const float* __restrict__ sent_w,
                                               const float* __restrict__ sent_b,
                                               float* __restrict__ out) {
    __shared__ float d[2 * HH];
    __shared__ float redw[4];
    int doc = blockIdx.x, tid = threadIdx.x;
    int l = dl[doc];
    for (int f = tid; f < 2 * HH; f += 128)
        d[f] = g_poold[doc * 2 * HH + f];
    __syncthreads();
    for (int r = 0; r < 11; r++) {
        const float* w = (r == 0) ? doc_w : sent_w + (r - 1) * 2 * HH;
        float p = 0.f;
        for (int f = tid; f < 2 * HH; f += 128) p += d[f] * w[f];
        for (int o = 16; o; o >>= 1) p += __shfl_down_sync(0xFFFFFFFFu, p, o);
        if ((tid & 31) == 0) redw[tid >> 5] = p;
        __syncthreads();
        if (tid == 0) {
            float s = redw[0] + redw[1] + redw[2] + redw[3];
            if (r == 0) out[doc] = sigmoidf_(s + doc_b[0]);
            else if (r - 1 < l) out[ND + g_offs[doc] + (r - 1)] = sigmoidf_(s + sent_b[r - 1]);
        }
        __syncthreads();
    }
}

// ---------------- host ----------------
extern "C" void kernel_launch(void* const* d_in, const int* in_sizes, int n_in,
                              void* d_out, int out_size) {
    int base = (n_in >= 24) ? 1 : 0;
    const int*   x        = (const int*)d_in[0];
    const int*   doc_lens = (const int*)d_in[1 + base];
    const float* emb      = (const float*)d_in[2 + base];
    const float* wf_ih    = (const float*)d_in[3 + base];
    const float* wf_hh    = (const float*)d_in[4 + base];
    const float* wf_bi    = (const float*)d_in[5 + base];
    const float* wf_bh    = (const float*)d_in[6 + base];
    const float* wb_ih    = (const float*)d_in[7 + base];
    const float* wb_hh    = (const float*)d_in[8 + base];
    const float* wb_bi    = (const float*)d_in[9 + base];
    const float* wb_bh    = (const float*)d_in[10 + base];
    const float* sf_ih    = (const float*)d_in[11 + base];
    const float* sf_hh    = (const float*)d_in[12 + base];
    const float* sf_bi    = (const float*)d_in[13 + base];
    const float* sf_bh    = (const float*)d_in[14 + base];
    const float* sb_ih    = (const float*)d_in[15 + base];
    const float* sb_hh    = (const float*)d_in[16 + base];
    const float* sb_bi    = (const float*)d_in[17 + base];
    const float* sb_bh    = (const float*)d_in[18 + base];
    const float* doc_w    = (const float*)d_in[19 + base];
    const float* doc_b    = (const float*)d_in[20 + base];
    const float* sent_w   = (const float*)d_in[21 + base];
    const float* sent_b   = (const float*)d_in[22 + base];
    float* out = (float*)d_out;

    float *P, *gxs, *pool;
    cudaGetSymbolAddress((void**)&P, g_P);
    cudaGetSymbolAddress((void**)&gxs, g_gxs);
    cudaGetSymbolAddress((void**)&pool, g_pool);

    const int SMW = HH * 20 * 8 + 40 * 600 * 4 + 40 * HH * 4 + TW * 40 * 4 + 40 * 4;
    const int SMS = HH * 8 * 8 + 16 * 600 * 4 + 16 * HH * 4 + DT * 16 * 4 + 16 * 4;
    cudaFuncSetAttribute(gru_seq<40, true>,
                         cudaFuncAttributeMaxDynamicSharedMemorySize, SMW);
    cudaFuncSetAttribute(gru_seq<16, false>,
                         cudaFuncAttributeMaxDynamicSharedMemorySize, SMS);

    k_prep<<<256, 256>>>(x, wf_hh, wb_hh, sf_hh, sb_hh);

    // P = emb @ [wf_ih; wb_ih]^T   (50000 x 1200) — tf32 tensor cores
    dim3 gP((600 + 63) / 64, (VOC + 127) / 128);
    gemm_tf32<<<gP, 256>>>(emb, wf_ih, P, VOC, 600, DD, GXW);
    gemm_tf32<<<gP, 256>>>(emb, wb_ih, P + 600, VOC, 600, DD, GXW);

    // word-level BiGRU: persistent, 64 x 2 blocks, 512 threads
    gru_seq<40, true><<<dim3(NS / 40, 2), 512, SMW>>>(
        x, doc_lens, wf_bi, wf_bh, wb_bi, wb_bh);

    // sentence-level gates: gxs = s @ [sf_ih; sb_ih]^T (fp32, small)
    dim3 gS((600 + 63) / 64, (NS + 127) / 128);
    gemm_bt<<<gS, 256>>>(pool, sf_ih, gxs, NS, 600, 2 * HH, GXW);
    gemm_bt<<<gS, 256>>>(pool, sb_ih, gxs + 600, NS, 600, 2 * HH, GXW);

    // sentence-level BiGRU: persistent, 16 x 2 blocks, 512 threads
    gru_seq<16, false><<<dim3(ND / 16, 2), 512, SMS>>>(
        nullptr, doc_lens, sf_bi, sf_bh, sb_bi, sb_bh);

    k_scan<<<1, 32>>>(doc_lens);
    k_final<<<ND, 128>>>(doc_lens, doc_w, doc_b, sent_w, sent_b, out);
}

// round 10
// speedup vs baseline: 2.1026x; 1.3866x over previous
#include <cuda_runtime.h>
#include <cuda_bf16.h>
#include <math.h>

#define HH   200
#define DD   300
#define TW   50
#define NS   2560
#define ND   256
#define DT   10
#define GG   600
#define GXW  1200
#define VOC  50000

// word-level tensor-core GRU geometry
#define MT_   38      // m-tiles of 16 (600 -> 608)
#define KT_   13      // k-tiles of 16 (200 -> 208)
#define NT_   5       // n-tiles of 8  (40)
#define BR_   40      // rows per block
#define KPAD  232     // padded K stride for Hb (conflict-free)
#define GPAD  616     // padded M stride for G

// ---------------- device scratch ----------------
__device__ float g_P[VOC * GXW];        // emb @ [wf_ih; wb_ih]^T
__device__ float g_gxs[NS * GXW];       // sentence-level input gates
// fp32 packed recurrent weights (sentence level): [k*HH+j] -> (r,z,n,0)
__device__ __align__(16) float4 g_wP[4][HH * HH];
// word-level mma fragments: [dir][(mt*KT_+kt)*32+lane][8] = {a_hi0..3, a_lo0..3}
__device__ __align__(16) unsigned int g_Wf[2][MT_ * KT_ * 32 * 8];
__device__ float g_pool[NS * 2 * HH];
__device__ float g_poold[ND * 2 * HH];
__device__ int   g_slen[NS];
__device__ int   g_offs[ND];

// ---------------- helpers ----------------
typedef unsigned long long ull;
__device__ __forceinline__ ull pack1(float a) {
    ull r; asm("mov.b64 %0, {%1, %1};" : "=l"(r) : "f"(a)); return r;
}
__device__ __forceinline__ void fma2(ull& d, ull a, ull b) {
    asm("fma.rn.f32x2 %0, %1, %2, %0;" : "+l"(d) : "l"(a), "l"(b));
}
__device__ __forceinline__ void unpack2(ull v, float& a, float& b) {
    asm("mov.b64 {%0, %1}, %2;" : "=f"(a), "=f"(b) : "l"(v));
}
__device__ __forceinline__ float sigmoidf_(float x) {
    return __fdividef(1.f, 1.f + __expf(-x));
}
__device__ __forceinline__ float tanhf_(float x) {
    return 2.f * __fdividef(1.f, 1.f + __expf(-2.f * x)) - 1.f;
}
__device__ __forceinline__ unsigned int to_tf32(float f) {
    unsigned int u;
    asm("cvt.rna.tf32.f32 %0, %1;" : "=r"(u) : "f"(f));
    return u;
}
__device__ __forceinline__ void mma_bf16(float* c, uint4 a,
                                         unsigned int b0, unsigned int b1) {
    asm volatile(
        "mma.sync.aligned.m16n8k16.row.col.f32.bf16.bf16.f32 "
        "{%0,%1,%2,%3}, {%4,%5,%6,%7}, {%8,%9}, {%0,%1,%2,%3};"
        : "+f"(c[0]), "+f"(c[1]), "+f"(c[2]), "+f"(c[3])
        : "r"(a.x), "r"(a.y), "r"(a.z), "r"(a.w), "r"(b0), "r"(b1));
}

// ---------------- tf32 tensor-core GEMM: C[M,N](ldc) = A[M,K] @ B[N,K]^T ------
__global__ __launch_bounds__(256) void gemm_tf32(const float* __restrict__ A,
                                                 const float* __restrict__ B,
                                                 float* __restrict__ C,
                                                 int M, int N, int K, int ldc) {
    __shared__ __align__(16) unsigned int As[128][36];
    __shared__ __align__(16) unsigned int Bs[64][36];
    int tid = threadIdx.x;
    int mb = blockIdx.y * 128, nb = blockIdx.x * 64;
    int warp = tid >> 5, lane = tid & 31;
    int wm = warp & 3, wn = warp >> 2;
    int gid = lane >> 2, tig = lane & 3;

    float c[2][4][4];
#pragma unroll
    for (int mt = 0; mt < 2; mt++)
#pragma unroll
        for (int nt = 0; nt < 4; nt++)
#pragma unroll
            for (int i = 0; i < 4; i++) c[mt][nt][i] = 0.f;

    int r = tid >> 3, c4 = (tid & 7) * 4;
    for (int k0 = 0; k0 < K; k0 += 32) {
        int col = k0 + c4;
        bool okc = (col + 4 <= K);
#pragma unroll
        for (int l = 0; l < 4; l++) {
            int row = r + l * 32;
            int gm = mb + row;
            float4 v = make_float4(0.f, 0.f, 0.f, 0.f);
            if (okc && gm < M) v = *(const float4*)&A[(size_t)gm * K + col];
            As[row][c4]     = to_tf32(v.x);
            As[row][c4 + 1] = to_tf32(v.y);
            As[row][c4 + 2] = to_tf32(v.z);
            As[row][c4 + 3] = to_tf32(v.w);
        }
#pragma unroll
        for (int l = 0; l < 2; l++) {
            int row = r + l * 32;
            int gn = nb + row;
            float4 v = make_float4(0.f, 0.f, 0.f, 0.f);
            if (okc && gn < N) v = *(const float4*)&B[(size_t)gn * K + col];
            Bs[row][c4]     = to_tf32(v.x);
            Bs[row][c4 + 1] = to_tf32(v.y);
            Bs[row][c4 + 2] = to_tf32(v.z);
            Bs[row][c4 + 3] = to_tf32(v.w);
        }
        __syncthreads();
#pragma unroll
        for (int kc = 0; kc < 4; kc++) {
            int kk = kc * 8;
            unsigned int af[2][4];
#pragma unroll
            for (int mt = 0; mt < 2; mt++) {
                int mr = wm * 32 + mt * 16;
                af[mt][0] = As[mr + gid][kk + tig];
                af[mt][1] = As[mr + gid + 8][kk + tig];
                af[mt][2] = As[mr + gid][kk + tig + 4];
                af[mt][3] = As[mr + gid + 8][kk + tig + 4];
            }
            unsigned int bf[4][2];
#pragma unroll
            for (int nt = 0; nt < 4; nt++) {
                int nc = wn * 32 + nt * 8;
                bf[nt][0] = Bs[nc + gid][kk + tig];
                bf[nt][1] = Bs[nc + gid][kk + tig + 4];
            }
#pragma unroll
            for (int mt = 0; mt < 2; mt++)
#pragma unroll
                for (int nt = 0; nt < 4; nt++) {
                    asm volatile(
                        "mma.sync.aligned.m16n8k8.row.col.f32.tf32.tf32.f32 "
                        "{%0,%1,%2,%3}, {%4,%5,%6,%7}, {%8,%9}, {%0,%1,%2,%3};"
                        : "+f"(c[mt][nt][0]), "+f"(c[mt][nt][1]),
                          "+f"(c[mt][nt][2]), "+f"(c[mt][nt][3])
                        : "r"(af[mt][0]), "r"(af[mt][1]),
                          "r"(af[mt][2]), "r"(af[mt][3]),
                          "r"(bf[nt][0]), "r"(bf[nt][1]));
                }
        }
        __syncthreads();
    }
#pragma unroll
    for (int mt = 0; mt < 2; mt++)
#pragma unroll
        for (int nt = 0; nt < 4; nt++) {
            int row0 = mb + wm * 32 + mt * 16 + gid;
            int col0 = nb + wn * 32 + nt * 8 + tig * 2;
            if (col0 < N) {
                if (row0 < M)
                    *(float2*)&C[(size_t)row0 * ldc + col0] =
                        make_float2(c[mt][nt][0], c[mt][nt][1]);
                if (row0 + 8 < M)
                    *(float2*)&C[(size_t)(row0 + 8) * ldc + col0] =
                        make_float2(c[mt][nt][2], c[mt][nt][3]);
            }
        }
}

// ---------------- fp32 f32x2 GEMM (sentence-gates GEMM) ----
__global__ __launch_bounds__(256) void gemm_bt(const float* __restrict__ A,
                                               const float* __restrict__ B,
                                               float* __restrict__ C,
                                               int M, int N, int K, int ldc) {
    __shared__ __align__(16) float As[20][132];
    __shared__ __align__(16) float Bs[20][68];
    int tid = threadIdx.x;
    int mb = blockIdx.y * 128, nb = blockIdx.x * 64;
    int tn = tid & 15, tm = tid >> 4;

    ull acc[4][4];
#pragma unroll
    for (int i = 0; i < 4; i++)
#pragma unroll
        for (int j = 0; j < 4; j++) acc[i][j] = 0ull;

    for (int k0 = 0; k0 < K; k0 += 20) {
#pragma unroll
        for (int l = 0; l < 10; l++) {
            int idx = tid + l * 256;
            int m = idx / 20, k = idx % 20;
            int gm = mb + m;
            As[k][m] = (gm < M) ? A[(size_t)gm * K + k0 + k] : 0.f;
        }
#pragma unroll
        for (int l = 0; l < 5; l++) {
            int idx = tid + l * 256;
            int n = idx / 20, k = idx % 20;
            int gn = nb + n;
            Bs[k][n] = (gn < N) ? B[(size_t)gn * K + k0 + k] : 0.f;
        }
        __syncthreads();
#pragma unroll
        for (int k = 0; k < 20; k++) {
            ulonglong2 a01 = *(const ulonglong2*)&As[k][tm * 8];
            ulonglong2 a23 = *(const ulonglong2*)&As[k][tm * 8 + 4];
            float4 bv = *(const float4*)&Bs[k][tn * 4];
            ull b0 = pack1(bv.x), b1 = pack1(bv.y), b2 = pack1(bv.z), b3 = pack1(bv.w);
            ull av[4] = {a01.x, a01.y, a23.x, a23.y};
#pragma unroll
            for (int i = 0; i < 4; i++) {
                fma2(acc[i][0], av[i], b0);
                fma2(acc[i][1], av[i], b1);
                fma2(acc[i][2], av[i], b2);
                fma2(acc[i][3], av[i], b3);
            }
        }
        __syncthreads();
    }
    int n0 = nb + tn * 4;
    if (n0 < N) {
#pragma unroll
        for (int i = 0; i < 4; i++) {
            int r0 = mb + tm * 8 + 2 * i;
            float v[2][4];
            unpack2(acc[i][0], v[0][0], v[1][0]);
            unpack2(acc[i][1], v[0][1], v[1][1]);
            unpack2(acc[i][2], v[0][2], v[1][2]);
            unpack2(acc[i][3], v[0][3], v[1][3]);
#pragma unroll
            for (int l = 0; l < 2; l++)
                if (r0 + l < M)
                    *(float4*)&C[(size_t)(r0 + l) * ldc + n0] =
                        make_float4(v[l][0], v[l][1], v[l][2], v[l][3]);
        }
    }
}

// ---------------- word-level persistent GRU on tensor cores ----------------
// 512 threads. Per step: 16 warps compute G[608,40]=W@H via bf16 hi/lo mma
// (3-term compensation); then 400 threads do gates+pool and re-split H.
__global__ __launch_bounds__(512, 1) void gru_tc(
    const int* __restrict__ toks,
    const float* __restrict__ bi_f, const float* __restrict__ bh_f,
    const float* __restrict__ bi_b, const float* __restrict__ bh_b) {
    extern __shared__ __align__(16) char sm_[];
    float* G = (float*)sm_;                                  // [40][GPAD]
    __nv_bfloat16* HbHi = (__nv_bfloat16*)(sm_ + 40 * GPAD * 4);   // [40][KPAD]
    __nv_bfloat16* HbLo = HbHi + 40 * KPAD;
    int* gxb = (int*)(sm_ + 40 * GPAD * 4 + 2 * 40 * KPAD * 2);    // [TW][40]
    int* sln = gxb + TW * BR_;                               // [40]
    float* Hf = (float*)(sln + BR_);                         // [40][HH]
    float* pool_s = Hf + BR_ * HH;                           // [40][HH]

    int dir = blockIdx.y;
    int b0 = blockIdx.x * BR_;
    const unsigned int* wdir = g_Wf[dir];
    const float* bi = dir ? bi_b : bi_f;
    const float* bh = dir ? bh_b : bh_f;
    int tid = threadIdx.x;
    int warp = tid >> 5, lane = tid & 31;
    int gid = lane >> 2, tig = lane & 3;

    // ---- init ----
    for (int idx = tid; idx < 40 * KPAD / 2; idx += 512)
        ((unsigned int*)HbHi)[idx] = 0u;
    for (int idx = tid; idx < 40 * KPAD / 2; idx += 512)
        ((unsigned int*)HbLo)[idx] = 0u;
    for (int idx = tid; idx < BR_ * HH; idx += 512) { Hf[idx] = 0.f; pool_s[idx] = 0.f; }
    for (int idx = tid; idx < TW * BR_; idx += 512) {
        int t = idx / BR_, b = idx % BR_;
        int tt = dir ? (TW - 1 - t) : t;
        int row = toks[(b0 + b) * TW + tt];
        gxb[idx] = row * GXW + dir * GG;
    }
    if (tid < BR_) sln[tid] = g_slen[b0 + tid];
    __syncthreads();

    int ej = tid < 400 ? (tid % 200) : 0;
    int ehalf = tid < 400 ? (tid / 200) : 0;
    float br = 0, bz = 0, bin = 0, bhn = 0;
    if (tid < 400) {
        br = bi[ej] + bh[ej];
        bz = bi[HH + ej] + bh[HH + ej];
        bin = bi[2 * HH + ej];
        bhn = bh[2 * HH + ej];
    }

    for (int t = 0; t < TW; t++) {
        int tt = dir ? (TW - 1 - t) : t;
        // ---- mma phase: G = W @ H (3-term bf16 compensation) ----
        for (int mt = warp; mt < MT_; mt += 16) {
            float c[NT_][4];
#pragma unroll
            for (int nt = 0; nt < NT_; nt++)
#pragma unroll
                for (int i = 0; i < 4; i++) c[nt][i] = 0.f;
            const unsigned int* wfb = wdir + (size_t)mt * KT_ * 32 * 8;
#pragma unroll 2
            for (int kt = 0; kt < KT_; kt++) {
                const uint4* p = (const uint4*)(wfb + ((size_t)kt * 32 + lane) * 8);
                uint4 ahi = p[0];
                uint4 alo = p[1];
                int koff = kt * 16 + tig * 2;
#pragma unroll
                for (int nt = 0; nt < NT_; nt++) {
                    int n = nt * 8 + gid;
                    unsigned int bhi0 = *(const unsigned int*)&HbHi[n * KPAD + koff];
                    unsigned int bhi1 = *(const unsigned int*)&HbHi[n * KPAD + koff + 8];
                    unsigned int blo0 = *(const unsigned int*)&HbLo[n * KPAD + koff];
                    unsigned int blo1 = *(const unsigned int*)&HbLo[n * KPAD + koff + 8];
                    mma_bf16(c[nt], ahi, bhi0, bhi1);
                    mma_bf16(c[nt], ahi, blo0, blo1);
                    mma_bf16(c[nt], alo, bhi0, bhi1);
                }
            }
#pragma unroll
            for (int nt = 0; nt < NT_; nt++) {
                int bcol = nt * 8 + tig * 2;
                int m = mt * 16 + gid;
                G[bcol * GPAD + m] = c[nt][0];
                G[(bcol + 1) * GPAD + m] = c[nt][1];
                G[bcol * GPAD + m + 8] = c[nt][2];
                G[(bcol + 1) * GPAD + m + 8] = c[nt][3];
            }
        }
        __syncthreads();
        // ---- epilogue: gates, pool, H re-split ----
        if (tid < 400) {
#pragma unroll 4
            for (int i = 0; i < 20; i++) {
                int b = ehalf * 20 + i;
                const float* gx = g_P + gxb[t * BR_ + b];
                float gr = G[b * GPAD + ej];
                float gz = G[b * GPAD + ej + 200];
                float gn = G[b * GPAD + ej + 400];
                float r = sigmoidf_(gx[ej] + gr + br);
                float z = sigmoidf_(gx[HH + ej] + gz + bz);
                float nn = tanhf_(gx[2 * HH + ej] + bin + r * (gn + bhn));
                float ho = Hf[b * HH + ej];
                float hnew = (1.f - z) * nn + z * ho;
                Hf[b * HH + ej] = hnew;
                if (tt < sln[b]) pool_s[b * HH + ej] += hnew;
                __nv_bfloat16 hi = __float2bfloat16(hnew);
                __nv_bfloat16 lo = __float2bfloat16(hnew - __bfloat162float(hi));
                HbHi[b * KPAD + ej] = hi;
                HbLo[b * KPAD + ej] = lo;
            }
        }
        __syncthreads();
    }

    // ---- pooled average writeback ----
    if (tid < 400) {
#pragma unroll
        for (int i = 0; i < 20; i++) {
            int b = ehalf * 20 + i;
            int l = sln[b];
            float v = pool_s[b * HH + ej];
            g_pool[(size_t)(b0 + b) * (2 * HH) + (size_t)dir * HH + ej] =
                l ? v / (float)l : 0.f;
        }
    }
}

// ---------------- sentence-level persistent GRU (fp32, as round 8) ----------
template <int BROWS>
__global__ __launch_bounds__(512, 1) void gru_seq_s(
    const int* __restrict__ dlens,
    const float* __restrict__ bi_f, const float* __restrict__ bh_f,
    const float* __restrict__ bi_b, const float* __restrict__ bh_b) {
    constexpr int PW = BROWS / 2;
    constexpr int BP = PW / 2;
    constexpr int HR = BROWS / 2;
    constexpr int CH = HR * 150;
    constexpr int TLEN = DT;

    extern __shared__ __align__(16) char sm_[];
    float2* hsT   = (float2*)sm_;
    float*  gxs_  = (float*)(sm_ + HH * PW * 8);
    float* pool_s = (float*)(sm_ + HH * PW * 8 + BROWS * 600 * 4);
    int* gxb = (int*)(sm_ + HH * PW * 8 + BROWS * 600 * 4 + BROWS * HH * 4);
    int* sln = gxb + TLEN * BROWS;

    int dir = blockIdx.y;
    int b0 = blockIdx.x * BROWS;
    const float4* wP = g_wP[2 + dir];
    const float* bi = dir ? bi_b : bi_f;
    const float* bh = dir ? bh_b : bh_f;
    int tid = threadIdx.x;
    int half = tid >> 8;
    int j = tid & 255;
    int pbase = half * BP;

    for (int idx = tid; idx < HH * PW; idx += 512) hsT[idx] = make_float2(0.f, 0.f);
    for (int idx = tid; idx < BROWS * HH; idx += 512) pool_s[idx] = 0.f;
    for (int idx = tid; idx < TLEN * BROWS; idx += 512) {
        int t = idx / BROWS, b = idx % BROWS;
        int tt = dir ? (TLEN - 1 - t) : t;
        int row = (b0 + b) * TLEN + tt;
        gxb[idx] = row * GXW + dir * GG;
    }
    if (tid < BROWS) sln[tid] = dlens[b0 + tid];
    __syncthreads();

    float br = 0, bz = 0, bin = 0, bhn = 0;
    if (j < HH) {
        br = bi[j] + bh[j];
        bz = bi[HH + j] + bh[HH + j];
        bin = bi[2 * HH + j];
        bhn = bh[2 * HH + j];
    }

    for (int t = 0; t < TLEN; t++) {
        int tt = dir ? (TLEN - 1 - t) : t;
        {
            const int* gq = gxb + t * BROWS;
#pragma unroll 2
            for (int c = j; c < CH; c += 256) {
                int b = half * HR + c / 150;
                int off = (c % 150) * 4;
                const float* src = g_gxs + gq[b] + off;
                unsigned int dst =
                    (unsigned int)__cvta_generic_to_shared(gxs_ + b * 600 + off);
                asm volatile("cp.async.cg.shared.global [%0], [%1], 16;"
                             :: "r"(dst), "l"(src));
            }
            asm volatile("cp.async.commit_group;");
        }
        ull aR[BP], aZ[BP], aN[BP];
        if (j < HH) {
#pragma unroll
            for (int p = 0; p < BP; p++) { aR[p] = 0; aZ[p] = 0; aN[p] = 0; }
            const float4* wp = wP + j;
            float4 ra[4];
#pragma unroll
            for (int i = 0; i < 4; i++) ra[i] = wp[i * HH];
#pragma unroll 4
            for (int k = 0; k < HH; k++) {
                float4 wc = ra[k & 3];
                int kp = k + 4;
                if (kp < HH) ra[k & 3] = wp[kp * HH];
                ull w0 = pack1(wc.x), w1 = pack1(wc.y), w2 = pack1(wc.z);
#pragma unroll
                for (int q = 0; q < BP / 2; q++) {
                    ulonglong2 hq =
                        *(const ulonglong2*)&hsT[k * PW + pbase + 2 * q];
                    fma2(aR[2 * q], hq.x, w0);
                    fma2(aZ[2 * q], hq.x, w1);
                    fma2(aN[2 * q], hq.x, w2);
                    fma2(aR[2 * q + 1], hq.y, w0);
                    fma2(aZ[2 * q + 1], hq.y, w1);
                    fma2(aN[2 * q + 1], hq.y, w2);
                }
            }
        }
        asm volatile("cp.async.wait_group 0;");
        asm volatile("bar.sync %0, 256;" :: "r"(1 + half) : "memory");
        if (j < HH) {
#pragma unroll
            for (int p = 0; p < BP; p++) {
                int gp = pbase + p;
                float hr[2], hz[2], hn[2], hnew[2];
                unpack2(aR[p], hr[0], hr[1]);
                unpack2(aZ[p], hz[0], hz[1]);
                unpack2(aN[p], hn[0], hn[1]);
                float2 hold = hsT[j * PW + gp];
#pragma unroll
                for (int l = 0; l < 2; l++) {
                    int b = 2 * gp + l;
                    const float* gx = gxs_ + b * 600;
                    float r = sigmoidf_(gx[j] + hr[l] + br);
                    float z = sigmoidf_(gx[HH + j] + hz[l] + bz);
                    float nn = tanhf_(gx[2 * HH + j] + bin + r * (hn[l] + bhn));
                    float ho = l ? hold.y : hold.x;
                    hnew[l] = (1.f - z) * nn + z * ho;
                    if (tt < sln[b]) pool_s[b * HH + j] += hnew[l];
                }
                hsT[j * PW + gp] = make_float2(hnew[0], hnew[1]);
            }
        }
        asm volatile("bar.sync %0, 256;" :: "r"(1 + half) : "memory");
    }

    if (j < HH) {
#pragma unroll
        for (int p = 0; p < BP; p++) {
#pragma unroll
            for (int l = 0; l < 2; l++) {
                int b = 2 * (pbase + p) + l;
                int ln = sln[b];
                float v = pool_s[b * HH + j];
                g_poold[(size_t)(b0 + b) * (2 * HH) + (size_t)dir * HH + j] =
                    ln ? v / (float)ln : 0.f;
            }
        }
    }
}

// ---------------- prep: weight packing, mma fragments, sent lens -------------
__global__ void k_prep(const int* __restrict__ x,
                       const float* __restrict__ wf_hh, const float* __restrict__ wb_hh,
                       const float* __restrict__ sf_hh, const float* __restrict__ sb_hh) {
    int i0 = blockIdx.x * blockDim.x + threadIdx.x;
    int gs = gridDim.x * blockDim.x;
    const float* ws[4] = {wf_hh, wb_hh, sf_hh, sb_hh};
    // fp32 packed (sentence level uses 2,3)
    for (int idx = i0; idx < HH * HH; idx += gs) {
        int k = idx / HH, j = idx % HH;
#pragma unroll
        for (int a = 0; a < 4; a++) {
            g_wP[a][idx] = make_float4(ws[a][j * HH + k],
                                       ws[a][(HH + j) * HH + k],
                                       ws[a][(2 * HH + j) * HH + k], 0.f);
        }
    }
    // word-level mma fragments (bf16 hi/lo), per-lane layout
    const int TOT = 2 * MT_ * KT_ * 32 * 4;
    for (int idx = i0; idx < TOT; idx += gs) {
        int rr = idx & 3;
        int lane = (idx >> 2) & 31;
        int kt = (idx >> 7) % KT_;
        int mt = (idx / (KT_ * 32 * 4)) % MT_;
        int a = idx / (MT_ * KT_ * 32 * 4);
        int gid = lane >> 2, tig = lane & 3;
        int row = mt * 16 + gid + (rr & 1) * 8;
        int k0 = kt * 16 + tig * 2 + ((rr >> 1) & 1) * 8;
        float w0 = (row < GG && k0 < HH) ? ws[a][row * HH + k0] : 0.f;
        float w1 = (row < GG && k0 + 1 < HH) ? ws[a][row * HH + k0 + 1] : 0.f;
        __nv_bfloat16 h0 = __float2bfloat16(w0);
        __nv_bfloat16 h1 = __float2bfloat16(w1);
        __nv_bfloat16 l0 = __float2bfloat16(w0 - __bfloat162float(h0));
        __nv_bfloat16 l1 = __float2bfloat16(w1 - __bfloat162float(h1));
        unsigned int hiw = ((unsigned int)__bfloat16_as_ushort(h1) << 16) |
                           (unsigned int)__bfloat16_as_ushort(h0);
        unsigned int low = ((unsigned int)__bfloat16_as_ushort(l1) << 16) |
                           (unsigned int)__bfloat16_as_ushort(l0);
        size_t base = (((size_t)mt * KT_ + kt) * 32 + lane) * 8;
        g_Wf[a][base + rr] = hiw;
        g_Wf[a][base + rr + 4] = low;
    }
    for (int s = i0; s < NS; s += gs) {
        int c = 0;
        for (int t = 0; t < TW; t++) c += (x[s * TW + t] != 0);
        g_slen[s] = c;
    }
}

__global__ void k_scan(const int* __restrict__ dl) {
    if (threadIdx.x == 0) {
        int a = 0;
        for (int i = 0; i < ND; i++) { g_offs[i] = a; a += dl[i]; }
    }
}

__global__ __launch_bounds__(128) void k_final(const int* __restrict__ dl,
                                               const float* __restrict__ doc_w,
                                               const float* __restrict__ doc_b,
                                               const float* __restrict__ sent_w,
                                               const float* __restrict__ sent_b,
                                               float* __restrict__ out) {
    __shared__ float d[2 * HH];
    __shared__ float redw[4];
    int doc = blockIdx.x, tid = threadIdx.x;
    int l = dl[doc];
    for (int f = tid; f < 2 * HH; f += 128)
        d[f] = g_poold[doc * 2 * HH + f];
    __syncthreads();
    for (int r = 0; r < 11; r++) {
        const float* w = (r == 0) ? doc_w : sent_w + (r - 1) * 2 * HH;
        float p = 0.f;
        for (int f = tid; f < 2 * HH; f += 128) p += d[f] * w[f];
        for (int o = 16; o; o >>= 1) p += __shfl_down_sync(0xFFFFFFFFu, p, o);
        if ((tid & 31) == 0) redw[tid >> 5] = p;
        __syncthreads();
        if (tid == 0) {
            float s = redw[0] + redw[1] + redw[2] + redw[3];
            if (r == 0) out[doc] = sigmoidf_(s + doc_b[0]);
            else if (r - 1 < l) out[ND + g_offs[doc] + (r - 1)] = sigmoidf_(s + sent_b[r - 1]);
        }
        __syncthreads();
    }
}

// ---------------- host ----------------
extern "C" void kernel_launch(void* const* d_in, const int* in_sizes, int n_in,
                              void* d_out, int out_size) {
    int base = (n_in >= 24) ? 1 : 0;
    const int*   x        = (const int*)d_in[0];
    const int*   doc_lens = (const int*)d_in[1 + base];
    const float* emb      = (const float*)d_in[2 + base];
    const float* wf_ih    = (const float*)d_in[3 + base];
    const float* wf_hh    = (const float*)d_in[4 + base];
    const float* wf_bi    = (const float*)d_in[5 + base];
    const float* wf_bh    = (const float*)d_in[6 + base];
    const float* wb_ih    = (const float*)d_in[7 + base];
    const float* wb_hh    = (const float*)d_in[8 + base];
    const float* wb_bi    = (const float*)d_in[9 + base];
    const float* wb_bh    = (const float*)d_in[10 + base];
    const float* sf_ih    = (const float*)d_in[11 + base];
    const float* sf_hh    = (const float*)d_in[12 + base];
    const float* sf_bi    = (const float*)d_in[13 + base];
    const float* sf_bh    = (const float*)d_in[14 + base];
    const float* sb_ih    = (const float*)d_in[15 + base];
    const float* sb_hh    = (const float*)d_in[16 + base];
    const float* sb_bi    = (const float*)d_in[17 + base];
    const float* sb_bh    = (const float*)d_in[18 + base];
    const float* doc_w    = (const float*)d_in[19 + base];
    const float* doc_b    = (const float*)d_in[20 + base];
    const float* sent_w   = (const float*)d_in[21 + base];
    const float* sent_b   = (const float*)d_in[22 + base];
    float* out = (float*)d_out;

    float *P, *gxs, *pool;
    cudaGetSymbolAddress((void**)&P, g_P);
    cudaGetSymbolAddress((void**)&gxs, g_gxs);
    cudaGetSymbolAddress((void**)&pool, g_pool);

    // word tc kernel smem: G + HbHi/Lo + gxb + sln + Hf + pool
    const int SMW = 40 * GPAD * 4 + 2 * 40 * KPAD * 2 + TW * BR_ * 4 + BR_ * 4
                    + BR_ * HH * 4 + BR_ * HH * 4;   // 207,840
    const int SMS = HH * 8 * 8 + 16 * 600 * 4 + 16 * HH * 4 + DT * 16 * 4 + 16 * 4;
    cudaFuncSetAttribute(gru_tc,
                         cudaFuncAttributeMaxDynamicSharedMemorySize, SMW);
    cudaFuncSetAttribute(gru_seq_s<16>,
                         cudaFuncAttributeMaxDynamicSharedMemorySize, SMS);

    k_prep<<<256, 256>>>(x, wf_hh, wb_hh, sf_hh, sb_hh);

    // P = emb @ [wf_ih; wb_ih]^T   (50000 x 1200) — tf32 tensor cores
    dim3 gP((600 + 63) / 64, (VOC + 127) / 128);
    gemm_tf32<<<gP, 256>>>(emb, wf_ih, P, VOC, 600, DD, GXW);
    gemm_tf32<<<gP, 256>>>(emb, wb_ih, P + 600, VOC, 600, DD, GXW);

    // word-level BiGRU: persistent tensor-core kernel, 64 x 2 blocks
    gru_tc<<<dim3(NS / BR_, 2), 512, SMW>>>(x, wf_bi, wf_bh, wb_bi, wb_bh);

    // sentence-level gates: gxs = s @ [sf_ih; sb_ih]^T (fp32)
    dim3 gS((600 + 63) / 64, (NS + 127) / 128);
    gemm_bt<<<gS, 256>>>(pool, sf_ih, gxs, NS, 600, 2 * HH, GXW);
    gemm_bt<<<gS, 256>>>(pool, sb_ih, gxs + 600, NS, 600, 2 * HH, GXW);

    // sentence-level BiGRU: fp32 persistent, 16 x 2 blocks
    gru_seq_s<16><<<dim3(ND / 16, 2), 512, SMS>>>(
        doc_lens, sf_bi, sf_bh, sb_bi, sb_bh);

    k_scan<<<1, 32>>>(doc_lens);
    k_final<<<ND, 128>>>(doc_lens, doc_w, doc_b, sent_w, sent_b, out);
}

// round 11
// speedup vs baseline: 2.8537x; 1.3572x over previous
#include <cuda_runtime.h>
#include <cuda_bf16.h>
#include <math.h>

#define HH   200
#define DD   300
#define TW   50
#define NS   2560
#define ND   256
#define DT   10
#define GG   600
#define GXW  1200
#define VOC  50000

// word-level tensor-core GRU geometry
#define MT_   38      // m-tiles of 16 (600 -> 608)
#define KT_   13      // k-tiles of 16 (200 -> 208)
#define NT_   5       // n-tiles of 8  (40)
#define BR_   40      // rows per block
#define KPAD  232     // padded K stride for Hb (conflict-free)
#define GPAD  616     // padded M stride for G

// ---------------- device scratch ----------------
__device__ __nv_bfloat16 g_P[VOC * GXW];   // emb @ [wf_ih; wb_ih]^T  (bf16)
__device__ float g_gxs[NS * GXW];          // sentence-level input gates (fp32)
// fp32 packed recurrent weights (sentence level): [k*HH+j] -> (r,z,n,0)
__device__ __align__(16) float4 g_wP[4][HH * HH];
// word-level mma fragments: [dir][(mt*KT_+kt)*32+lane][8] = {a_hi0..3, a_lo0..3}
__device__ __align__(16) unsigned int g_Wf[2][MT_ * KT_ * 32 * 8];
__device__ float g_pool[NS * 2 * HH];
__device__ float g_poold[ND * 2 * HH];
__device__ int   g_slen[NS];
__device__ int   g_offs[ND];

// ---------------- helpers ----------------
typedef unsigned long long ull;
__device__ __forceinline__ ull pack1(float a) {
    ull r; asm("mov.b64 %0, {%1, %1};" : "=l"(r) : "f"(a)); return r;
}
__device__ __forceinline__ void fma2(ull& d, ull a, ull b) {
    asm("fma.rn.f32x2 %0, %1, %2, %0;" : "+l"(d) : "l"(a), "l"(b));
}
__device__ __forceinline__ void unpack2(ull v, float& a, float& b) {
    asm("mov.b64 {%0, %1}, %2;" : "=f"(a), "=f"(b) : "l"(v));
}
__device__ __forceinline__ float sigmoidf_(float x) {
    return __fdividef(1.f, 1.f + __expf(-x));
}
__device__ __forceinline__ float tanhf_(float x) {
    return 2.f * __fdividef(1.f, 1.f + __expf(-2.f * x)) - 1.f;
}
__device__ __forceinline__ void mma_bf16(float* c, uint4 a,
                                         unsigned int b0, unsigned int b1) {
    asm volatile(
        "mma.sync.aligned.m16n8k16.row.col.f32.bf16.bf16.f32 "
        "{%0,%1,%2,%3}, {%4,%5,%6,%7}, {%8,%9}, {%0,%1,%2,%3};"
        : "+f"(c[0]), "+f"(c[1]), "+f"(c[2]), "+f"(c[3])
        : "r"(a.x), "r"(a.y), "r"(a.z), "r"(a.w), "r"(b0), "r"(b1));
}
__device__ __forceinline__ void cpa16(void* dst, const void* src, int sz) {
    unsigned int d = (unsigned int)__cvta_generic_to_shared(dst);
    asm volatile("cp.async.cg.shared.global [%0], [%1], 16, %2;"
                 :: "r"(d), "l"(src), "r"(sz));
}

// -------- tf32 tensor-core GEMM (double-buffered cp.async, raw fp32->tf32) ---
// C[M,N](ldc) = A[M,K] @ B[N,K]^T.  BF16OUT: C is bf16, else fp32.
template <bool BF16OUT>
__global__ __launch_bounds__(256) void gemm_tc(const float* __restrict__ A,
                                               const float* __restrict__ B,
                                               void* __restrict__ Cv,
                                               int M, int N, int K, int ldc) {
    extern __shared__ __align__(16) float smg[];
    float* As = smg;                 // [2][128][36]
    float* Bs = smg + 2 * 128 * 36;  // [2][64][36]
    int tid = threadIdx.x;
    int mb = blockIdx.y * 128, nb = blockIdx.x * 64;
    int warp = tid >> 5, lane = tid & 31;
    int wm = warp & 3, wn = warp >> 2;
    int gid = lane >> 2, tig = lane & 3;

    float c[2][4][4];
#pragma unroll
    for (int mt = 0; mt < 2; mt++)
#pragma unroll
        for (int nt = 0; nt < 4; nt++)
#pragma unroll
            for (int i = 0; i < 4; i++) c[mt][nt][i] = 0.f;

    int r = tid >> 3, c4 = (tid & 7) * 4;
    int nk = (K + 31) / 32;

    auto load_chunk = [&](int i, int buf) {
        int col = i * 32 + c4;
        int nb_ = (col < K) ? (K - col < 4 ? (K - col) * 4 : 16) : 0;
        int cc = (col < K) ? col : 0;
#pragma unroll
        for (int l = 0; l < 4; l++) {
            int row = r + l * 32;
            int gm = mb + row;
            int sz = (gm < M) ? nb_ : 0;
            if (gm >= M) gm = M - 1;
            cpa16(&As[buf * 128 * 36 + row * 36 + c4],
                  &A[(size_t)gm * K + cc], sz);
        }
#pragma unroll
        for (int l = 0; l < 2; l++) {
            int row = r + l * 32;
            int gn = nb + row;
            int sz = (gn < N) ? nb_ : 0;
            if (gn >= N) gn = N - 1;
            cpa16(&Bs[buf * 64 * 36 + row * 36 + c4],
                  &B[(size_t)gn * K + cc], sz);
        }
        asm volatile("cp.async.commit_group;");
    };

    load_chunk(0, 0);
    for (int i = 0; i < nk; i++) {
        if (i + 1 < nk) {
            load_chunk(i + 1, (i + 1) & 1);
            asm volatile("cp.async.wait_group 1;");
        } else {
            asm volatile("cp.async.wait_group 0;");
        }
        __syncthreads();
        const unsigned int* Ab =
            (const unsigned int*)(As + (i & 1) * 128 * 36);
        const unsigned int* Bb =
            (const unsigned int*)(Bs + (i & 1) * 64 * 36);
#pragma unroll
        for (int kc = 0; kc < 4; kc++) {
            int kk = kc * 8;
            unsigned int af[2][4];
#pragma unroll
            for (int mt = 0; mt < 2; mt++) {
                int mr = wm * 32 + mt * 16;
                af[mt][0] = Ab[(mr + gid) * 36 + kk + tig];
                af[mt][1] = Ab[(mr + gid + 8) * 36 + kk + tig];
                af[mt][2] = Ab[(mr + gid) * 36 + kk + tig + 4];
                af[mt][3] = Ab[(mr + gid + 8) * 36 + kk + tig + 4];
            }
            unsigned int bf[4][2];
#pragma unroll
            for (int nt = 0; nt < 4; nt++) {
                int nc = wn * 32 + nt * 8;
                bf[nt][0] = Bb[(nc + gid) * 36 + kk + tig];
                bf[nt][1] = Bb[(nc + gid) * 36 + kk + tig + 4];
            }
#pragma unroll
            for (int mt = 0; mt < 2; mt++)
#pragma unroll
                for (int nt = 0; nt < 4; nt++) {
                    asm volatile(
                        "mma.sync.aligned.m16n8k8.row.col.f32.tf32.tf32.f32 "
                        "{%0,%1,%2,%3}, {%4,%5,%6,%7}, {%8,%9}, {%0,%1,%2,%3};"
                        : "+f"(c[mt][nt][0]), "+f"(c[mt][nt][1]),
                          "+f"(c[mt][nt][2]), "+f"(c[mt][nt][3])
                        : "r"(af[mt][0]), "r"(af[mt][1]),
                          "r"(af[mt][2]), "r"(af[mt][3]),
                          "r"(bf[nt][0]), "r"(bf[nt][1]));
                }
        }
        __syncthreads();
    }
#pragma unroll
    for (int mt = 0; mt < 2; mt++)
#pragma unroll
        for (int nt = 0; nt < 4; nt++) {
            int row0 = mb + wm * 32 + mt * 16 + gid;
            int col0 = nb + wn * 32 + nt * 8 + tig * 2;
            if (col0 < N) {
                if (BF16OUT) {
                    __nv_bfloat16* C = (__nv_bfloat16*)Cv;
                    if (row0 < M)
                        *(__nv_bfloat162*)&C[(size_t)row0 * ldc + col0] =
                            __float22bfloat162_rn(
                                make_float2(c[mt][nt][0], c[mt][nt][1]));
                    if (row0 + 8 < M)
                        *(__nv_bfloat162*)&C[(size_t)(row0 + 8) * ldc + col0] =
                            __float22bfloat162_rn(
                                make_float2(c[mt][nt][2], c[mt][nt][3]));
                } else {
                    float* C = (float*)Cv;
                    if (row0 < M)
                        *(float2*)&C[(size_t)row0 * ldc + col0] =
                            make_float2(c[mt][nt][0], c[mt][nt][1]);
                    if (row0 + 8 < M)
                        *(float2*)&C[(size_t)(row0 + 8) * ldc + col0] =
                            make_float2(c[mt][nt][2], c[mt][nt][3]);
                }
            }
        }
}

// ---------------- word-level persistent GRU on tensor cores ----------------
// 512 threads. Per step: cp.async stages gx (bf16) while 16 warps compute
// G[608,40]=W@H via bf16 hi/lo mma; 400 threads do gates+pool (regs).
__global__ __launch_bounds__(512, 1) void gru_tc(
    const int* __restrict__ toks,
    const float* __restrict__ bi_f, const float* __restrict__ bh_f,
    const float* __restrict__ bi_b, const float* __restrict__ bh_b) {
    extern __shared__ __align__(16) char sm_[];
    float* G = (float*)sm_;                                       // 40*GPAD
    __nv_bfloat16* HbHi = (__nv_bfloat16*)(sm_ + 40 * GPAD * 4);  // 40*KPAD
    __nv_bfloat16* HbLo = HbHi + 40 * KPAD;
    __nv_bfloat16* gxS = (__nv_bfloat16*)(sm_ + 135680);          // 40*608
    int* gxb = (int*)(sm_ + 184320);                              // TW*40
    int* sln = gxb + TW * BR_;                                    // 40
    float* Hf = (float*)(sm_ + 192480);                           // 40*200

    int dir = blockIdx.y;
    int b0 = blockIdx.x * BR_;
    const unsigned int* wdir = g_Wf[dir];
    const float* bi = dir ? bi_b : bi_f;
    const float* bh = dir ? bh_b : bh_f;
    int tid = threadIdx.x;
    int warp = tid >> 5, lane = tid & 31;
    int gid = lane >> 2, tig = lane & 3;

    // ---- init ----
    for (int idx = tid; idx < 40 * KPAD / 2; idx += 512)
        ((unsigned int*)HbHi)[idx] = 0u;
    for (int idx = tid; idx < 40 * KPAD / 2; idx += 512)
        ((unsigned int*)HbLo)[idx] = 0u;
    for (int idx = tid; idx < BR_ * HH; idx += 512) Hf[idx] = 0.f;
    for (int idx = tid; idx < TW * BR_; idx += 512) {
        int t = idx / BR_, b = idx % BR_;
        int tt = dir ? (TW - 1 - t) : t;
        int row = toks[(b0 + b) * TW + tt];
        gxb[idx] = row * GXW + dir * GG;
    }
    if (tid < BR_) sln[tid] = g_slen[b0 + tid];
    __syncthreads();

    int ej = tid < 400 ? (tid % 200) : 0;
    int ehalf = tid < 400 ? (tid / 200) : 0;
    float br = 0, bz = 0, bin = 0, bhn = 0;
    if (tid < 400) {
        br = bi[ej] + bh[ej];
        bz = bi[HH + ej] + bh[HH + ej];
        bin = bi[2 * HH + ej];
        bhn = bh[2 * HH + ej];
    }
    float pool_r[20];
#pragma unroll
    for (int i = 0; i < 20; i++) pool_r[i] = 0.f;

    for (int t = 0; t < TW; t++) {
        int tt = dir ? (TW - 1 - t) : t;
        // ---- stage gx rows (bf16) into smem; overlaps the mma phase ----
        {
            const int* gq = gxb + t * BR_;
            for (int ci = tid; ci < BR_ * 75; ci += 512) {
                int b = ci / 75, off = (ci % 75) * 8;
                cpa16(gxS + b * 608 + off, g_P + gq[b] + off, 16);
            }
            asm volatile("cp.async.commit_group;");
        }
        // ---- mma phase: G = W @ H (3-term bf16 compensation) ----
        for (int mt = warp; mt < MT_; mt += 16) {
            float c[NT_][4];
#pragma unroll
            for (int nt = 0; nt < NT_; nt++)
#pragma unroll
                for (int i = 0; i < 4; i++) c[nt][i] = 0.f;
            const unsigned int* wfb = wdir + (size_t)mt * KT_ * 32 * 8;
#pragma unroll 2
            for (int kt = 0; kt < KT_; kt++) {
                const uint4* p = (const uint4*)(wfb + ((size_t)kt * 32 + lane) * 8);
                uint4 ahi = p[0];
                uint4 alo = p[1];
                int koff = kt * 16 + tig * 2;
#pragma unroll
                for (int nt = 0; nt < NT_; nt++) {
                    int n = nt * 8 + gid;
                    unsigned int bhi0 = *(const unsigned int*)&HbHi[n * KPAD + koff];
                    unsigned int bhi1 = *(const unsigned int*)&HbHi[n * KPAD + koff + 8];
                    unsigned int blo0 = *(const unsigned int*)&HbLo[n * KPAD + koff];
                    unsigned int blo1 = *(const unsigned int*)&HbLo[n * KPAD + koff + 8];
                    mma_bf16(c[nt], ahi, bhi0, bhi1);
                    mma_bf16(c[nt], ahi, blo0, blo1);
                    mma_bf16(c[nt], alo, bhi0, bhi1);
                }
            }
#pragma unroll
            for (int nt = 0; nt < NT_; nt++) {
                int bcol = nt * 8 + tig * 2;
                int m = mt * 16 + gid;
                G[bcol * GPAD + m] = c[nt][0];
                G[(bcol + 1) * GPAD + m] = c[nt][1];
                G[bcol * GPAD + m + 8] = c[nt][2];
                G[(bcol + 1) * GPAD + m + 8] = c[nt][3];
            }
        }
        asm volatile("cp.async.wait_group 0;");
        __syncthreads();
        // ---- epilogue: gates, pool, H re-split ----
        if (tid < 400) {
#pragma unroll 4
            for (int i = 0; i < 20; i++) {
                int b = ehalf * 20 + i;
                float gxr = __bfloat162float(gxS[b * 608 + ej]);
                float gxz = __bfloat162float(gxS[b * 608 + 200 + ej]);
                float gxn = __bfloat162float(gxS[b * 608 + 400 + ej]);
                float gr = G[b * GPAD + ej];
                float gz = G[b * GPAD + ej + 200];
                float gn = G[b * GPAD + ej + 400];
                float r = sigmoidf_(gxr + gr + br);
                float z = sigmoidf_(gxz + gz + bz);
                float nn = tanhf_(gxn + bin + r * (gn + bhn));
                float ho = Hf[b * HH + ej];
                float hnew = (1.f - z) * nn + z * ho;
                Hf[b * HH + ej] = hnew;
                if (tt < sln[b]) pool_r[i] += hnew;
                __nv_bfloat16 hi = __float2bfloat16(hnew);
                __nv_bfloat16 lo = __float2bfloat16(hnew - __bfloat162float(hi));
                HbHi[b * KPAD + ej] = hi;
                HbLo[b * KPAD + ej] = lo;
            }
        }
        __syncthreads();
    }

    // ---- pooled average writeback ----
    if (tid < 400) {
#pragma unroll
        for (int i = 0; i < 20; i++) {
            int b = ehalf * 20 + i;
            int l = sln[b];
            g_pool[(size_t)(b0 + b) * (2 * HH) + (size_t)dir * HH + ej] =
                l ? pool_r[i] / (float)l : 0.f;
        }
    }
}

// ---------------- sentence-level persistent GRU (fp32) ----------
template <int BROWS>
__global__ __launch_bounds__(512, 1) void gru_seq_s(
    const int* __restrict__ dlens,
    const float* __restrict__ bi_f, const float* __restrict__ bh_f,
    const float* __restrict__ bi_b, const float* __restrict__ bh_b) {
    constexpr int PW = BROWS / 2;
    constexpr int BP = PW / 2;
    constexpr int HR = BROWS / 2;
    constexpr int CH = HR * 150;
    constexpr int TLEN = DT;

    extern __shared__ __align__(16) char sm_[];
    float2* hsT   = (float2*)sm_;
    float*  gxs_  = (float*)(sm_ + HH * PW * 8);
    float* pool_s = (float*)(sm_ + HH * PW * 8 + BROWS * 600 * 4);
    int* gxb = (int*)(sm_ + HH * PW * 8 + BROWS * 600 * 4 + BROWS * HH * 4);
    int* sln = gxb + TLEN * BROWS;

    int dir = blockIdx.y;
    int b0 = blockIdx.x * BROWS;
    const float4* wP = g_wP[2 + dir];
    const float* bi = dir ? bi_b : bi_f;
    const float* bh = dir ? bh_b : bh_f;
    int tid = threadIdx.x;
    int half = tid >> 8;
    int j = tid & 255;
    int pbase = half * BP;

    for (int idx = tid; idx < HH * PW; idx += 512) hsT[idx] = make_float2(0.f, 0.f);
    for (int idx = tid; idx < BROWS * HH; idx += 512) pool_s[idx] = 0.f;
    for (int idx = tid; idx < TLEN * BROWS; idx += 512) {
        int t = idx / BROWS, b = idx % BROWS;
        int tt = dir ? (TLEN - 1 - t) : t;
        int row = (b0 + b) * TLEN + tt;
        gxb[idx] = row * GXW + dir * GG;
    }
    if (tid < BROWS) sln[tid] = dlens[b0 + tid];
    __syncthreads();

    float br = 0, bz = 0, bin = 0, bhn = 0;
    if (j < HH) {
        br = bi[j] + bh[j];
        bz = bi[HH + j] + bh[HH + j];
        bin = bi[2 * HH + j];
        bhn = bh[2 * HH + j];
    }

    for (int t = 0; t < TLEN; t++) {
        int tt = dir ? (TLEN - 1 - t) : t;
        {
            const int* gq = gxb + t * BROWS;
#pragma unroll 2
            for (int c = j; c < CH; c += 256) {
                int b = half * HR + c / 150;
                int off = (c % 150) * 4;
                cpa16(gxs_ + b * 600 + off, g_gxs + gq[b] + off, 16);
            }
            asm volatile("cp.async.commit_group;");
        }
        ull aR[BP], aZ[BP], aN[BP];
        if (j < HH) {
#pragma unroll
            for (int p = 0; p < BP; p++) { aR[p] = 0; aZ[p] = 0; aN[p] = 0; }
            const float4* wp = wP + j;
            float4 ra[4];
#pragma unroll
            for (int i = 0; i < 4; i++) ra[i] = wp[i * HH];
#pragma unroll 4
            for (int k = 0; k < HH; k++) {
                float4 wc = ra[k & 3];
                int kp = k + 4;
                if (kp < HH) ra[k & 3] = wp[kp * HH];
                ull w0 = pack1(wc.x), w1 = pack1(wc.y), w2 = pack1(wc.z);
#pragma unroll
                for (int q = 0; q < BP / 2; q++) {
                    ulonglong2 hq =
                        *(const ulonglong2*)&hsT[k * PW + pbase + 2 * q];
                    fma2(aR[2 * q], hq.x, w0);
                    fma2(aZ[2 * q], hq.x, w1);
                    fma2(aN[2 * q], hq.x, w2);
                    fma2(aR[2 * q + 1], hq.y, w0);
                    fma2(aZ[2 * q + 1], hq.y, w1);
                    fma2(aN[2 * q + 1], hq.y, w2);
                }
            }
        }
        asm volatile("cp.async.wait_group 0;");
        asm volatile("bar.sync %0, 256;" :: "r"(1 + half) : "memory");
        if (j < HH) {
#pragma unroll
            for (int p = 0; p < BP; p++) {
                int gp = pbase + p;
                float hr[2], hz[2], hn[2], hnew[2];
                unpack2(aR[p], hr[0], hr[1]);
                unpack2(aZ[p], hz[0], hz[1]);
                unpack2(aN[p], hn[0], hn[1]);
                float2 hold = hsT[j * PW + gp];
#pragma unroll
                for (int l = 0; l < 2; l++) {
                    int b = 2 * gp + l;
                    const float* gx = gxs_ + b * 600;
                    float r = sigmoidf_(gx[j] + hr[l] + br);
                    float z = sigmoidf_(gx[HH + j] + hz[l] + bz);
                    float nn = tanhf_(gx[2 * HH + j] + bin + r * (hn[l] + bhn));
                    float ho = l ? hold.y : hold.x;
                    hnew[l] = (1.f - z) * nn + z * ho;
                    if (tt < sln[b]) pool_s[b * HH + j] += hnew[l];
                }
                hsT[j * PW + gp] = make_float2(hnew[0], hnew[1]);
            }
        }
        asm volatile("bar.sync %0, 256;" :: "r"(1 + half) : "memory");
    }

    if (j < HH) {
#pragma unroll
        for (int p = 0; p < BP; p++) {
#pragma unroll
            for (int l = 0; l < 2; l++) {
                int b = 2 * (pbase + p) + l;
                int ln = sln[b];
                float v = pool_s[b * HH + j];
                g_poold[(size_t)(b0 + b) * (2 * HH) + (size_t)dir * HH + j] =
                    ln ? v / (float)ln : 0.f;
            }
        }
    }
}

// ---------------- prep: weight packing, mma fragments, sent lens -------------
__global__ void k_prep(const int* __restrict__ x,
                       const float* __restrict__ wf_hh, const float* __restrict__ wb_hh,
                       const float* __restrict__ sf_hh, const float* __restrict__ sb_hh) {
    int i0 = blockIdx.x * blockDim.x + threadIdx.x;
    int gs = gridDim.x * blockDim.x;
    const float* ws[4] = {wf_hh, wb_hh, sf_hh, sb_hh};
    for (int idx = i0; idx < HH * HH; idx += gs) {
        int k = idx / HH, j = idx % HH;
#pragma unroll
        for (int a = 0; a < 4; a++) {
            g_wP[a][idx] = make_float4(ws[a][j * HH + k],
                                       ws[a][(HH + j) * HH + k],
                                       ws[a][(2 * HH + j) * HH + k], 0.f);
        }
    }
    const int TOT = 2 * MT_ * KT_ * 32 * 4;
    for (int idx = i0; idx < TOT; idx += gs) {
        int rr = idx & 3;
        int lane = (idx >> 2) & 31;
        int kt = (idx >> 7) % KT_;
        int mt = (idx / (KT_ * 32 * 4)) % MT_;
        int a = idx / (MT_ * KT_ * 32 * 4);
        int gid = lane >> 2, tig = lane & 3;
        int row = mt * 16 + gid + (rr & 1) * 8;
        int k0 = kt * 16 + tig * 2 + ((rr >> 1) & 1) * 8;
        float w0 = (row < GG && k0 < HH) ? ws[a][row * HH + k0] : 0.f;
        float w1 = (row < GG && k0 + 1 < HH) ? ws[a][row * HH + k0 + 1] : 0.f;
        __nv_bfloat16 h0 = __float2bfloat16(w0);
        __nv_bfloat16 h1 = __float2bfloat16(w1);
        __nv_bfloat16 l0 = __float2bfloat16(w0 - __bfloat162float(h0));
        __nv_bfloat16 l1 = __float2bfloat16(w1 - __bfloat162float(h1));
        unsigned int hiw = ((unsigned int)__bfloat16_as_ushort(h1) << 16) |
                           (unsigned int)__bfloat16_as_ushort(h0);
        unsigned int low = ((unsigned int)__bfloat16_as_ushort(l1) << 16) |
                           (unsigned int)__bfloat16_as_ushort(l0);
        size_t base = (((size_t)mt * KT_ + kt) * 32 + lane) * 8;
        g_Wf[a][base + rr] = hiw;
        g_Wf[a][base + rr + 4] = low;
    }
    for (int s = i0; s < NS; s += gs) {
        int c = 0;
        for (int t = 0; t < TW; t++) c += (x[s * TW + t] != 0);
        g_slen[s] = c;
    }
}

__global__ void k_scan(const int* __restrict__ dl) {
    if (threadIdx.x == 0) {
        int a = 0;
        for (int i = 0; i < ND; i++) { g_offs[i] = a; a += dl[i]; }
    }
}

__global__ __launch_bounds__(128) void k_final(const int* __restrict__ dl,
                                               const float* __restrict__ doc_w,
                                               const float* __restrict__ doc_b,
                                               const float* __restrict__ sent_w,
                                               const float* __restrict__ sent_b,
                                               float* __restrict__ out) {
    __shared__ float d[2 * HH];
    __shared__ float redw[4];
    int doc = blockIdx.x, tid = threadIdx.x;
    int l = dl[doc];
    for (int f = tid; f < 2 * HH; f += 128)
        d[f] = g_poold[doc * 2 * HH + f];
    __syncthreads();
    for (int r = 0; r < 11; r++) {
        const float* w = (r == 0) ? doc_w : sent_w + (r - 1) * 2 * HH;
        float p = 0.f;
        for (int f = tid; f < 2 * HH; f += 128) p += d[f] * w[f];
        for (int o = 16; o; o >>= 1) p += __shfl_down_sync(0xFFFFFFFFu, p, o);
        if ((tid & 31) == 0) redw[tid >> 5] = p;
        __syncthreads();
        if (tid == 0) {
            float s = redw[0] + redw[1] + redw[2] + redw[3];
            if (r == 0) out[doc] = sigmoidf_(s + doc_b[0]);
            else if (r - 1 < l) out[ND + g_offs[doc] + (r - 1)] = sigmoidf_(s + sent_b[r - 1]);
        }
        __syncthreads();
    }
}

// ---------------- host ----------------
extern "C" void kernel_launch(void* const* d_in, const int* in_sizes, int n_in,
                              void* d_out, int out_size) {
    int base = (n_in >= 24) ? 1 : 0;
    const int*   x        = (const int*)d_in[0];
    const int*   doc_lens = (const int*)d_in[1 + base];
    const float* emb      = (const float*)d_in[2 + base];
    const float* wf_ih    = (const float*)d_in[3 + base];
    const float* wf_hh    = (const float*)d_in[4 + base];
    const float* wf_bi    = (const float*)d_in[5 + base];
    const float* wf_bh    = (const float*)d_in[6 + base];
    const float* wb_ih    = (const float*)d_in[7 + base];
    const float* wb_hh    = (const float*)d_in[8 + base];
    const float* wb_bi    = (const float*)d_in[9 + base];
    const float* wb_bh    = (const float*)d_in[10 + base];
    const float* sf_ih    = (const float*)d_in[11 + base];
    const float* sf_hh    = (const float*)d_in[12 + base];
    const float* sf_bi    = (const float*)d_in[13 + base];
    const float* sf_bh    = (const float*)d_in[14 + base];
    const float* sb_ih    = (const float*)d_in[15 + base];
    const float* sb_hh    = (const float*)d_in[16 + base];
    const float* sb_bi    = (const float*)d_in[17 + base];
    const float* sb_bh    = (const float*)d_in[18 + base];
    const float* doc_w    = (const float*)d_in[19 + base];
    const float* doc_b    = (const float*)d_in[20 + base];
    const float* sent_w   = (const float*)d_in[21 + base];
    const float* sent_b   = (const float*)d_in[22 + base];
    float* out = (float*)d_out;

    void *P, *gxs, *pool;
    cudaGetSymbolAddress(&P, g_P);
    cudaGetSymbolAddress(&gxs, g_gxs);
    cudaGetSymbolAddress(&pool, g_pool);

    const int SMG = (2 * 128 * 36 + 2 * 64 * 36) * 4;              // 55,296
    const int SMW = 40 * GPAD * 4 + 2 * 40 * KPAD * 2 + 40 * 608 * 2
                    + TW * BR_ * 4 + BR_ * 4 + BR_ * HH * 4;       // 224,480
    const int SMS = HH * 8 * 8 + 16 * 600 * 4 + 16 * HH * 4 + DT * 16 * 4 + 16 * 4;
    cudaFuncSetAttribute(gemm_tc<true>,
                         cudaFuncAttributeMaxDynamicSharedMemorySize, SMG);
    cudaFuncSetAttribute(gemm_tc<false>,
                         cudaFuncAttributeMaxDynamicSharedMemorySize, SMG);
    cudaFuncSetAttribute(gru_tc,
                         cudaFuncAttributeMaxDynamicSharedMemorySize, SMW);
    cudaFuncSetAttribute(gru_seq_s<16>,
                         cudaFuncAttributeMaxDynamicSharedMemorySize, SMS);

    k_prep<<<256, 256>>>(x, wf_hh, wb_hh, sf_hh, sb_hh);

    // P = emb @ [wf_ih; wb_ih]^T   (50000 x 1200) — tf32, bf16 output
    dim3 gP((600 + 63) / 64, (VOC + 127) / 128);
    gemm_tc<true><<<gP, 256, SMG>>>(emb, wf_ih, P, VOC, 600, DD, GXW);
    gemm_tc<true><<<gP, 256, SMG>>>(emb, wb_ih,
                                    (void*)((__nv_bfloat16*)P + 600),
                                    VOC, 600, DD, GXW);

    // word-level BiGRU: persistent tensor-core kernel, 64 x 2 blocks
    gru_tc<<<dim3(NS / BR_, 2), 512, SMW>>>(x, wf_bi, wf_bh, wb_bi, wb_bh);

    // sentence-level gates: gxs = s @ [sf_ih; sb_ih]^T (tf32, fp32 out)
    dim3 gS((600 + 63) / 64, (NS + 127) / 128);
    gemm_tc<false><<<gS, 256, SMG>>>((const float*)pool, sf_ih, gxs,
                                     NS, 600, 2 * HH, GXW);
    gemm_tc<false><<<gS, 256, SMG>>>((const float*)pool, sb_ih,
                                     (void*)((float*)gxs + 600),
                                     NS, 600, 2 * HH, GXW);

    // sentence-level BiGRU: fp32 persistent, 16 x 2 blocks
    gru_seq_s<16><<<dim3(ND / 16, 2), 512, SMS>>>(
        doc_lens, sf_bi, sf_bh, sb_bi, sb_bh);

    k_scan<<<1, 32>>>(doc_lens);
    k_final<<<ND, 128>>>(doc_lens, doc_w, doc_b, sent_w, sent_b, out);
}

// round 12
// speedup vs baseline: 3.7306x; 1.3073x over previous
#include <cuda_runtime.h>
#include <cuda_bf16.h>
#include <math.h>

#define HH   200
#define DD   300
#define TW   50
#define NS   2560
#define ND   256
#define DT   10
#define GG   600
#define GXW  1200
#define VOC  50000

// word-level tensor-core GRU geometry
#define MT_   38      // m-tiles of 16 (600 -> 608)
#define KT_   13      // k-tiles of 16 (200 -> 208)
#define NT_   5       // n-tiles of 8  (40)
#define BR_   40      // rows per block
#define KPAD  232     // padded K stride for Hb (conflict-free)
#define GPAD  616     // padded M stride for G

// ---------------- device scratch ----------------
__device__ __nv_bfloat16 g_P[VOC * GXW];   // emb @ [wf_ih; wb_ih]^T  (bf16)
__device__ float g_gxs[NS * GXW];          // sentence-level input gates (fp32)
// fp32 packed recurrent weights (sentence level): [k*HH+j] -> (r,z,n,0)
__device__ __align__(16) float4 g_wP[4][HH * HH];
// word-level mma fragments (bf16, hi only): [dir][(mt*KT_+kt)*32+lane][4]
__device__ __align__(16) unsigned int g_Wf[2][MT_ * KT_ * 32 * 4];
__device__ float g_pool[NS * 2 * HH];
__device__ float g_poold[ND * 2 * HH];
__device__ int   g_slen[NS];
__device__ int   g_offs[ND];

// ---------------- helpers ----------------
typedef unsigned long long ull;
__device__ __forceinline__ ull pack1(float a) {
    ull r; asm("mov.b64 %0, {%1, %1};" : "=l"(r) : "f"(a)); return r;
}
__device__ __forceinline__ void fma2(ull& d, ull a, ull b) {
    asm("fma.rn.f32x2 %0, %1, %2, %0;" : "+l"(d) : "l"(a), "l"(b));
}
__device__ __forceinline__ void unpack2(ull v, float& a, float& b) {
    asm("mov.b64 {%0, %1}, %2;" : "=f"(a), "=f"(b) : "l"(v));
}
__device__ __forceinline__ float sigmoidf_(float x) {
    return __fdividef(1.f, 1.f + __expf(-x));
}
__device__ __forceinline__ float tanhf_(float x) {
    return 2.f * __fdividef(1.f, 1.f + __expf(-2.f * x)) - 1.f;
}
__device__ __forceinline__ void mma_bf16(float* c, uint4 a,
                                         unsigned int b0, unsigned int b1) {
    asm volatile(
        "mma.sync.aligned.m16n8k16.row.col.f32.bf16.bf16.f32 "
        "{%0,%1,%2,%3}, {%4,%5,%6,%7}, {%8,%9}, {%0,%1,%2,%3};"
        : "+f"(c[0]), "+f"(c[1]), "+f"(c[2]), "+f"(c[3])
        : "r"(a.x), "r"(a.y), "r"(a.z), "r"(a.w), "r"(b0), "r"(b1));
}
__device__ __forceinline__ void cpa16(void* dst, const void* src, int sz) {
    unsigned int d = (unsigned int)__cvta_generic_to_shared(dst);
    asm volatile("cp.async.cg.shared.global [%0], [%1], 16, %2;"
                 :: "r"(d), "l"(src), "r"(sz));
}

// -------- tf32 tensor-core GEMM (double-buffered cp.async, raw fp32->tf32) ---
// C[M,N](ldc) = A[M,K] @ B[N,K]^T.  BF16OUT: C is bf16, else fp32.
template <bool BF16OUT>
__global__ __launch_bounds__(256) void gemm_tc(const float* __restrict__ A,
                                               const float* __restrict__ B,
                                               void* __restrict__ Cv,
                                               int M, int N, int K, int ldc) {
    extern __shared__ __align__(16) float smg[];
    float* As = smg;                 // [2][128][36]
    float* Bs = smg + 2 * 128 * 36;  // [2][64][36]
    int tid = threadIdx.x;
    int mb = blockIdx.y * 128, nb = blockIdx.x * 64;
    int warp = tid >> 5, lane = tid & 31;
    int wm = warp & 3, wn = warp >> 2;
    int gid = lane >> 2, tig = lane & 3;

    float c[2][4][4];
#pragma unroll
    for (int mt = 0; mt < 2; mt++)
#pragma unroll
        for (int nt = 0; nt < 4; nt++)
#pragma unroll
            for (int i = 0; i < 4; i++) c[mt][nt][i] = 0.f;

    int r = tid >> 3, c4 = (tid & 7) * 4;
    int nk = (K + 31) / 32;

    auto load_chunk = [&](int i, int buf) {
        int col = i * 32 + c4;
        int nb_ = (col < K) ? (K - col < 4 ? (K - col) * 4 : 16) : 0;
        int cc = (col < K) ? col : 0;
#pragma unroll
        for (int l = 0; l < 4; l++) {
            int row = r + l * 32;
            int gm = mb + row;
            int sz = (gm < M) ? nb_ : 0;
            if (gm >= M) gm = M - 1;
            cpa16(&As[buf * 128 * 36 + row * 36 + c4],
                  &A[(size_t)gm * K + cc], sz);
        }
#pragma unroll
        for (int l = 0; l < 2; l++) {
            int row = r + l * 32;
            int gn = nb + row;
            int sz = (gn < N) ? nb_ : 0;
            if (gn >= N) gn = N - 1;
            cpa16(&Bs[buf * 64 * 36 + row * 36 + c4],
                  &B[(size_t)gn * K + cc], sz);
        }
        asm volatile("cp.async.commit_group;");
    };

    load_chunk(0, 0);
    for (int i = 0; i < nk; i++) {
        if (i + 1 < nk) {
            load_chunk(i + 1, (i + 1) & 1);
            asm volatile("cp.async.wait_group 1;");
        } else {
            asm volatile("cp.async.wait_group 0;");
        }
        __syncthreads();
        const unsigned int* Ab =
            (const unsigned int*)(As + (i & 1) * 128 * 36);
        const unsigned int* Bb =
            (const unsigned int*)(Bs + (i & 1) * 64 * 36);
#pragma unroll
        for (int kc = 0; kc < 4; kc++) {
            int kk = kc * 8;
            unsigned int af[2][4];
#pragma unroll
            for (int mt = 0; mt < 2; mt++) {
                int mr = wm * 32 + mt * 16;
                af[mt][0] = Ab[(mr + gid) * 36 + kk + tig];
                af[mt][1] = Ab[(mr + gid + 8) * 36 + kk + tig];
                af[mt][2] = Ab[(mr + gid) * 36 + kk + tig + 4];
                af[mt][3] = Ab[(mr + gid + 8) * 36 + kk + tig + 4];
            }
            unsigned int bf[4][2];
#pragma unroll
            for (int nt = 0; nt < 4; nt++) {
                int nc = wn * 32 + nt * 8;
                bf[nt][0] = Bb[(nc + gid) * 36 + kk + tig];
                bf[nt][1] = Bb[(nc + gid) * 36 + kk + tig + 4];
            }
#pragma unroll
            for (int mt = 0; mt < 2; mt++)
#pragma unroll
                for (int nt = 0; nt < 4; nt++) {
                    asm volatile(
                        "mma.sync.aligned.m16n8k8.row.col.f32.tf32.tf32.f32 "
                        "{%0,%1,%2,%3}, {%4,%5,%6,%7}, {%8,%9}, {%0,%1,%2,%3};"
                        : "+f"(c[mt][nt][0]), "+f"(c[mt][nt][1]),
                          "+f"(c[mt][nt][2]), "+f"(c[mt][nt][3])
                        : "r"(af[mt][0]), "r"(af[mt][1]),
                          "r"(af[mt][2]), "r"(af[mt][3]),
                          "r"(bf[nt][0]), "r"(bf[nt][1]));
                }
        }
        __syncthreads();
    }
#pragma unroll
    for (int mt = 0; mt < 2; mt++)
#pragma unroll
        for (int nt = 0; nt < 4; nt++) {
            int row0 = mb + wm * 32 + mt * 16 + gid;
            int col0 = nb + wn * 32 + nt * 8 + tig * 2;
            if (col0 < N) {
                if (BF16OUT) {
                    __nv_bfloat16* C = (__nv_bfloat16*)Cv;
                    if (row0 < M)
                        *(__nv_bfloat162*)&C[(size_t)row0 * ldc + col0] =
                            __float22bfloat162_rn(
                                make_float2(c[mt][nt][0], c[mt][nt][1]));
                    if (row0 + 8 < M)
                        *(__nv_bfloat162*)&C[(size_t)(row0 + 8) * ldc + col0] =
                            __float22bfloat162_rn(
                                make_float2(c[mt][nt][2], c[mt][nt][3]));
                } else {
                    float* C = (float*)Cv;
                    if (row0 < M)
                        *(float2*)&C[(size_t)row0 * ldc + col0] =
                            make_float2(c[mt][nt][0], c[mt][nt][1]);
                    if (row0 + 8 < M)
                        *(float2*)&C[(size_t)(row0 + 8) * ldc + col0] =
                            make_float2(c[mt][nt][2], c[mt][nt][3]);
                }
            }
        }
}

// ---------------- word-level persistent GRU on tensor cores ----------------
// 512 threads. Per step: cp.async stages gx (bf16) while 16 warps compute
// G[608,40]=W@H via single bf16 mma per tile; 400 threads do gates+pool.
// smem layout (bytes):
//   G     @ 0        : 40*GPAD*4  = 98,560
//   HbHi  @ 98,560   : 40*KPAD*2  = 18,560
//   gxS   @ 117,120  : 40*608*2   = 48,640
//   gxb   @ 165,760  : TW*40*4    =  8,000
//   sln   @ 173,760  : 40*4       =    160
//   Hf    @ 173,920  : 40*200*4   = 32,000   -> total 205,920
__global__ __launch_bounds__(512, 1) void gru_tc(
    const int* __restrict__ toks,
    const float* __restrict__ bi_f, const float* __restrict__ bh_f,
    const float* __restrict__ bi_b, const float* __restrict__ bh_b) {
    extern __shared__ __align__(16) char sm_[];
    float* G = (float*)sm_;
    __nv_bfloat16* HbHi = (__nv_bfloat16*)(sm_ + 98560);
    __nv_bfloat16* gxS = (__nv_bfloat16*)(sm_ + 117120);
    int* gxb = (int*)(sm_ + 165760);
    int* sln = (int*)(sm_ + 173760);
    float* Hf = (float*)(sm_ + 173920);

    int dir = blockIdx.y;
    int b0 = blockIdx.x * BR_;
    const unsigned int* wdir = g_Wf[dir];
    const float* bi = dir ? bi_b : bi_f;
    const float* bh = dir ? bh_b : bh_f;
    int tid = threadIdx.x;
    int warp = tid >> 5, lane = tid & 31;
    int gid = lane >> 2, tig = lane & 3;

    // ---- init ----
    for (int idx = tid; idx < 40 * KPAD / 2; idx += 512)
        ((unsigned int*)HbHi)[idx] = 0u;
    for (int idx = tid; idx < BR_ * HH; idx += 512) Hf[idx] = 0.f;
    for (int idx = tid; idx < TW * BR_; idx += 512) {
        int t = idx / BR_, b = idx % BR_;
        int tt = dir ? (TW - 1 - t) : t;
        int row = toks[(b0 + b) * TW + tt];
        gxb[idx] = row * GXW + dir * GG;
    }
    if (tid < BR_) sln[tid] = g_slen[b0 + tid];
    __syncthreads();

    int ej = tid < 400 ? (tid % 200) : 0;
    int ehalf = tid < 400 ? (tid / 200) : 0;
    float br = 0, bz = 0, bin = 0, bhn = 0;
    if (tid < 400) {
        br = bi[ej] + bh[ej];
        bz = bi[HH + ej] + bh[HH + ej];
        bin = bi[2 * HH + ej];
        bhn = bh[2 * HH + ej];
    }
    float pool_r[20];
#pragma unroll
    for (int i = 0; i < 20; i++) pool_r[i] = 0.f;

    for (int t = 0; t < TW; t++) {
        int tt = dir ? (TW - 1 - t) : t;
        // ---- stage gx rows (bf16) into smem; overlaps the mma phase ----
        {
            const int* gq = gxb + t * BR_;
            for (int ci = tid; ci < BR_ * 75; ci += 512) {
                int b = ci / 75, off = (ci % 75) * 8;
                cpa16(gxS + b * 608 + off, g_P + gq[b] + off, 16);
            }
            asm volatile("cp.async.commit_group;");
        }
        // ---- mma phase: G = W @ H (single bf16 mma per tile) ----
        for (int mt = warp; mt < MT_; mt += 16) {
            float c[NT_][4];
#pragma unroll
            for (int nt = 0; nt < NT_; nt++)
#pragma unroll
                for (int i = 0; i < 4; i++) c[nt][i] = 0.f;
            const unsigned int* wfb = wdir + (size_t)mt * KT_ * 32 * 4;
#pragma unroll 4
            for (int kt = 0; kt < KT_; kt++) {
                uint4 ahi = *(const uint4*)(wfb + ((size_t)kt * 32 + lane) * 4);
                int koff = kt * 16 + tig * 2;
#pragma unroll
                for (int nt = 0; nt < NT_; nt++) {
                    int n = nt * 8 + gid;
                    unsigned int bhi0 = *(const unsigned int*)&HbHi[n * KPAD + koff];
                    unsigned int bhi1 = *(const unsigned int*)&HbHi[n * KPAD + koff + 8];
                    mma_bf16(c[nt], ahi, bhi0, bhi1);
                }
            }
#pragma unroll
            for (int nt = 0; nt < NT_; nt++) {
                int bcol = nt * 8 + tig * 2;
                int m = mt * 16 + gid;
                G[bcol * GPAD + m] = c[nt][0];
                G[(bcol + 1) * GPAD + m] = c[nt][1];
                G[bcol * GPAD + m + 8] = c[nt][2];
                G[(bcol + 1) * GPAD + m + 8] = c[nt][3];
            }
        }
        asm volatile("cp.async.wait_group 0;");
        __syncthreads();
        // ---- epilogue: gates, pool, H update ----
        if (tid < 400) {
#pragma unroll 4
            for (int i = 0; i < 20; i++) {
                int b = ehalf * 20 + i;
                float gxr = __bfloat162float(gxS[b * 608 + ej]);
                float gxz = __bfloat162float(gxS[b * 608 + 200 + ej]);
                float gxn = __bfloat162float(gxS[b * 608 + 400 + ej]);
                float gr = G[b * GPAD + ej];
                float gz = G[b * GPAD + ej + 200];
                float gn = G[b * GPAD + ej + 400];
                float r = sigmoidf_(gxr + gr + br);
                float z = sigmoidf_(gxz + gz + bz);
                float nn = tanhf_(gxn + bin + r * (gn + bhn));
                float ho = Hf[b * HH + ej];
                float hnew = (1.f - z) * nn + z * ho;
                Hf[b * HH + ej] = hnew;
                if (tt < sln[b]) pool_r[i] += hnew;
                HbHi[b * KPAD + ej] = __float2bfloat16(hnew);
            }
        }
        __syncthreads();
    }

    // ---- pooled average writeback ----
    if (tid < 400) {
#pragma unroll
        for (int i = 0; i < 20; i++) {
            int b = ehalf * 20 + i;
            int l = sln[b];
            g_pool[(size_t)(b0 + b) * (2 * HH) + (size_t)dir * HH + ej] =
                l ? pool_r[i] / (float)l : 0.f;
        }
    }
}

// ---------------- sentence-level persistent GRU (fp32) ----------
template <int BROWS>
__global__ __launch_bounds__(512, 1) void gru_seq_s(
    const int* __restrict__ dlens,
    const float* __restrict__ bi_f, const float* __restrict__ bh_f,
    const float* __restrict__ bi_b, const float* __restrict__ bh_b) {
    constexpr int PW = BROWS / 2;
    constexpr int BP = PW / 2;
    constexpr int HR = BROWS / 2;
    constexpr int CH = HR * 150;
    constexpr int TLEN = DT;

    extern __shared__ __align__(16) char sm_[];
    float2* hsT   = (float2*)sm_;
    float*  gxs_  = (float*)(sm_ + HH * PW * 8);
    float* pool_s = (float*)(sm_ + HH * PW * 8 + BROWS * 600 * 4);
    int* gxb = (int*)(sm_ + HH * PW * 8 + BROWS * 600 * 4 + BROWS * HH * 4);
    int* sln = gxb + TLEN * BROWS;

    int dir = blockIdx.y;
    int b0 = blockIdx.x * BROWS;
    const float4* wP = g_wP[2 + dir];
    const float* bi = dir ? bi_b : bi_f;
    const float* bh = dir ? bh_b : bh_f;
    int tid = threadIdx.x;
    int half = tid >> 8;
    int j = tid & 255;
    int pbase = half * BP;

    for (int idx = tid; idx < HH * PW; idx += 512) hsT[idx] = make_float2(0.f, 0.f);
    for (int idx = tid; idx < BROWS * HH; idx += 512) pool_s[idx] = 0.f;
    for (int idx = tid; idx < TLEN * BROWS; idx += 512) {
        int t = idx / BROWS, b = idx % BROWS;
        int tt = dir ? (TLEN - 1 - t) : t;
        int row = (b0 + b) * TLEN + tt;
        gxb[idx] = row * GXW + dir * GG;
    }
    if (tid < BROWS) sln[tid] = dlens[b0 + tid];
    __syncthreads();

    float br = 0, bz = 0, bin = 0, bhn = 0;
    if (j < HH) {
        br = bi[j] + bh[j];
        bz = bi[HH + j] + bh[HH + j];
        bin = bi[2 * HH + j];
        bhn = bh[2 * HH + j];
    }

    for (int t = 0; t < TLEN; t++) {
        int tt = dir ? (TLEN - 1 - t) : t;
        {
            const int* gq = gxb + t * BROWS;
#pragma unroll 2
            for (int c = j; c < CH; c += 256) {
                int b = half * HR + c / 150;
                int off = (c % 150) * 4;
                cpa16(gxs_ + b * 600 + off, g_gxs + gq[b] + off, 16);
            }
            asm volatile("cp.async.commit_group;");
        }
        ull aR[BP], aZ[BP], aN[BP];
        if (j < HH) {
#pragma unroll
            for (int p = 0; p < BP; p++) { aR[p] = 0; aZ[p] = 0; aN[p] = 0; }
            const float4* wp = wP + j;
            float4 ra[4];
#pragma unroll
            for (int i = 0; i < 4; i++) ra[i] = wp[i * HH];
#pragma unroll 4
            for (int k = 0; k < HH; k++) {
                float4 wc = ra[k & 3];
                int kp = k + 4;
                if (kp < HH) ra[k & 3] = wp[kp * HH];
                ull w0 = pack1(wc.x), w1 = pack1(wc.y), w2 = pack1(wc.z);
#pragma unroll
                for (int q = 0; q < BP / 2; q++) {
                    ulonglong2 hq =
                        *(const ulonglong2*)&hsT[k * PW + pbase + 2 * q];
                    fma2(aR[2 * q], hq.x, w0);
                    fma2(aZ[2 * q], hq.x, w1);
                    fma2(aN[2 * q], hq.x, w2);
                    fma2(aR[2 * q + 1], hq.y, w0);
                    fma2(aZ[2 * q + 1], hq.y, w1);
                    fma2(aN[2 * q + 1], hq.y, w2);
                }
            }
        }
        asm volatile("cp.async.wait_group 0;");
        asm volatile("bar.sync %0, 256;" :: "r"(1 + half) : "memory");
        if (j < HH) {
#pragma unroll
            for (int p = 0; p < BP; p++) {
                int gp = pbase + p;
                float hr[2], hz[2], hn[2], hnew[2];
                unpack2(aR[p], hr[0], hr[1]);
                unpack2(aZ[p], hz[0], hz[1]);
                unpack2(aN[p], hn[0], hn[1]);
                float2 hold = hsT[j * PW + gp];
#pragma unroll
                for (int l = 0; l < 2; l++) {
                    int b = 2 * gp + l;
                    const float* gx = gxs_ + b * 600;
                    float r = sigmoidf_(gx[j] + hr[l] + br);
                    float z = sigmoidf_(gx[HH + j] + hz[l] + bz);
                    float nn = tanhf_(gx[2 * HH + j] + bin + r * (hn[l] + bhn));
                    float ho = l ? hold.y : hold.x;
                    hnew[l] = (1.f - z) * nn + z * ho;
                    if (tt < sln[b]) pool_s[b * HH + j] += hnew[l];
                }
                hsT[j * PW + gp] = make_float2(hnew[0], hnew[1]);
            }
        }
        asm volatile("bar.sync %0, 256;" :: "r"(1 + half) : "memory");
    }

    if (j < HH) {
#pragma unroll
        for (int p = 0; p < BP; p++) {
#pragma unroll
            for (int l = 0; l < 2; l++) {
                int b = 2 * (pbase + p) + l;
                int ln = sln[b];
                float v = pool_s[b * HH + j];
                g_poold[(size_t)(b0 + b) * (2 * HH) + (size_t)dir * HH + j] =
                    ln ? v / (float)ln : 0.f;
            }
        }
    }
}

// ---------------- prep: weight packing, mma fragments, sent lens -------------
__global__ void k_prep(const int* __restrict__ x,
                       const float* __restrict__ wf_hh, const float* __restrict__ wb_hh,
                       const float* __restrict__ sf_hh, const float* __restrict__ sb_hh) {
    int i0 = blockIdx.x * blockDim.x + threadIdx.x;
    int gs = gridDim.x * blockDim.x;
    const float* ws[4] = {wf_hh, wb_hh, sf_hh, sb_hh};
    for (int idx = i0; idx < HH * HH; idx += gs) {
        int k = idx / HH, j = idx % HH;
#pragma unroll
        for (int a = 0; a < 4; a++) {
            g_wP[a][idx] = make_float4(ws[a][j * HH + k],
                                       ws[a][(HH + j) * HH + k],
                                       ws[a][(2 * HH + j) * HH + k], 0.f);
        }
    }
    const int TOT = 2 * MT_ * KT_ * 32 * 4;
    for (int idx = i0; idx < TOT; idx += gs) {
        int rr = idx & 3;
        int lane = (idx >> 2) & 31;
        int kt = (idx >> 7) % KT_;
        int mt = (idx / (KT_ * 32 * 4)) % MT_;
        int a = idx / (MT_ * KT_ * 32 * 4);
        int gid = lane >> 2, tig = lane & 3;
        int row = mt * 16 + gid + (rr & 1) * 8;
        int k0 = kt * 16 + tig * 2 + ((rr >> 1) & 1) * 8;
        float w0 = (row < GG && k0 < HH) ? ws[a][row * HH + k0] : 0.f;
        float w1 = (row < GG && k0 + 1 < HH) ? ws[a][row * HH + k0 + 1] : 0.f;
        __nv_bfloat16 h0 = __float2bfloat16(w0);
        __nv_bfloat16 h1 = __float2bfloat16(w1);
        unsigned int hiw = ((unsigned int)__bfloat16_as_ushort(h1) << 16) |
                           (unsigned int)__bfloat16_as_ushort(h0);
        size_t base = (((size_t)mt * KT_ + kt) * 32 + lane) * 4;
        g_Wf[a][base + rr] = hiw;
    }
    for (int s = i0; s < NS; s += gs) {
        int c = 0;
        for (int t = 0; t < TW; t++) c += (x[s * TW + t] != 0);
        g_slen[s] = c;
    }
}

__global__ void k_scan(const int* __restrict__ dl) {
    if (threadIdx.x == 0) {
        int a = 0;
        for (int i = 0; i < ND; i++) { g_offs[i] = a; a += dl[i]; }
    }
}

__global__ __launch_bounds__(128) void k_final(const int* __restrict__ dl,
                                               const float* __restrict__ doc_w,
                                               const float* __restrict__ doc_b,
                                               const float* __restrict__ sent_w,
                                               const float* __restrict__ sent_b,
                                               float* __restrict__ out) {
    __shared__ float d[2 * HH];
    __shared__ float redw[4];
    int doc = blockIdx.x, tid = threadIdx.x;
    int l = dl[doc];
    for (int f = tid; f < 2 * HH; f += 128)
        d[f] = g_poold[doc * 2 * HH + f];
    __syncthreads();
    for (int r = 0; r < 11; r++) {
        const float* w = (r == 0) ? doc_w : sent_w + (r - 1) * 2 * HH;
        float p = 0.f;
        for (int f = tid; f < 2 * HH; f += 128) p += d[f] * w[f];
        for (int o = 16; o; o >>= 1) p += __shfl_down_sync(0xFFFFFFFFu, p, o);
        if ((tid & 31) == 0) redw[tid >> 5] = p;
        __syncthreads();
        if (tid == 0) {
            float s = redw[0] + redw[1] + redw[2] + redw[3];
            if (r == 0) out[doc] = sigmoidf_(s + doc_b[0]);
            else if (r - 1 < l) out[ND + g_offs[doc] + (r - 1)] = sigmoidf_(s + sent_b[r - 1]);
        }
        __syncthreads();
    }
}

// ---------------- host ----------------
extern "C" void kernel_launch(void* const* d_in, const int* in_sizes, int n_in,
                              void* d_out, int out_size) {
    int base = (n_in >= 24) ? 1 : 0;
    const int*   x        = (const int*)d_in[0];
    const int*   doc_lens = (const int*)d_in[1 + base];
    const float* emb      = (const float*)d_in[2 + base];
    const float* wf_ih    = (const float*)d_in[3 + base];
    const float* wf_hh    = (const float*)d_in[4 + base];
    const float* wf_bi    = (const float*)d_in[5 + base];
    const float* wf_bh    = (const float*)d_in[6 + base];
    const float* wb_ih    = (const float*)d_in[7 + base];
    const float* wb_hh    = (const float*)d_in[8 + base];
    const float* wb_bi    = (const float*)d_in[9 + base];
    const float* wb_bh    = (const float*)d_in[10 + base];
    const float* sf_ih    = (const float*)d_in[11 + base];
    const float* sf_hh    = (const float*)d_in[12 + base];
    const float* sf_bi    = (const float*)d_in[13 + base];
    const float* sf_bh    = (const float*)d_in[14 + base];
    const float* sb_ih    = (const float*)d_in[15 + base];
    const float* sb_hh    = (const float*)d_in[16 + base];
    const float* sb_bi    = (const float*)d_in[17 + base];
    const float* sb_bh    = (const float*)d_in[18 + base];
    const float* doc_w    = (const float*)d_in[19 + base];
    const float* doc_b    = (const float*)d_in[20 + base];
    const float* sent_w   = (const float*)d_in[21 + base];
    const float* sent_b   = (const float*)d_in[22 + base];
    float* out = (float*)d_out;

    void *P, *gxs, *pool;
    cudaGetSymbolAddress(&P, g_P);
    cudaGetSymbolAddress(&gxs, g_gxs);
    cudaGetSymbolAddress(&pool, g_pool);

    const int SMG = (2 * 128 * 36 + 2 * 64 * 36) * 4;   // 55,296
    const int SMW = 205920;
    const int SMS = HH * 8 * 8 + 16 * 600 * 4 + 16 * HH * 4 + DT * 16 * 4 + 16 * 4;
    cudaFuncSetAttribute(gemm_tc<true>,
                         cudaFuncAttributeMaxDynamicSharedMemorySize, SMG);
    cudaFuncSetAttribute(gemm_tc<false>,
                         cudaFuncAttributeMaxDynamicSharedMemorySize, SMG);
    cudaFuncSetAttribute(gru_tc,
                         cudaFuncAttributeMaxDynamicSharedMemorySize, SMW);
    cudaFuncSetAttribute(gru_seq_s<16>,
                         cudaFuncAttributeMaxDynamicSharedMemorySize, SMS);

    k_prep<<<256, 256>>>(x, wf_hh, wb_hh, sf_hh, sb_hh);

    // P = emb @ [wf_ih; wb_ih]^T   (50000 x 1200) — tf32, bf16 output
    dim3 gP((600 + 63) / 64, (VOC + 127) / 128);
    gemm_tc<true><<<gP, 256, SMG>>>(emb, wf_ih, P, VOC, 600, DD, GXW);
    gemm_tc<true><<<gP, 256, SMG>>>(emb, wb_ih,
                                    (void*)((__nv_bfloat16*)P + 600),
                                    VOC, 600, DD, GXW);

    // word-level BiGRU: persistent tensor-core kernel, 64 x 2 blocks
    gru_tc<<<dim3(NS / BR_, 2), 512, SMW>>>(x, wf_bi, wf_bh, wb_bi, wb_bh);

    // sentence-level gates: gxs = s @ [sf_ih; sb_ih]^T (tf32, fp32 out)
    dim3 gS((600 + 63) / 64, (NS + 127) / 128);
    gemm_tc<false><<<gS, 256, SMG>>>((const float*)pool, sf_ih, gxs,
                                     NS, 600, 2 * HH, GXW);
    gemm_tc<false><<<gS, 256, SMG>>>((const float*)pool, sb_ih,
                                     (void*)((float*)gxs + 600),
                                     NS, 600, 2 * HH, GXW);

    // sentence-level BiGRU: fp32 persistent, 16 x 2 blocks
    gru_seq_s<16><<<dim3(ND / 16, 2), 512, SMS>>>(
        doc_lens, sf_bi, sf_bh, sb_bi, sb_bh);

    k_scan<<<1, 32>>>(doc_lens);
    k_final<<<ND, 128>>>(doc_lens, doc_w, doc_b, sent_w, sent_b, out);
}

// round 13
// speedup vs baseline: 3.9897x; 1.0695x over previous
#include <cuda_runtime.h>
#include <cuda_bf16.h>
#include <math.h>

#define HH   200
#define DD   300
#define TW   50
#define NS   2560
#define ND   256
#define DT   10
#define GG   600
#define GXW  1200
#define VOC  50000
#define KPE  304     // padded K for emb/wih (16B-aligned bf16 rows)

// word-level tensor-core GRU geometry
#define MT_   38
#define KT_   13
#define NT_   5
#define BR_   40
#define KPAD  232
#define GPAD  616

// ---------------- device scratch ----------------
__device__ __nv_bfloat16 g_P[VOC * GXW];      // emb @ [wf_ih; wb_ih]^T (bf16)
__device__ __nv_bfloat16 g_embB[VOC * KPE];   // emb in bf16, padded
__device__ __nv_bfloat16 g_WihB[GXW * KPE];   // [wf_ih; wb_ih] bf16, padded
__device__ __nv_bfloat16 g_SihB[GXW * 400];   // [sf_ih; sb_ih] bf16
__device__ __nv_bfloat16 g_pool[NS * 2 * HH]; // word pooled (bf16)
__device__ float g_gxs[NS * GXW];             // sentence input gates (fp32)
__device__ __align__(16) float4 g_wP[2][HH * HH];  // sentence recurrent fp32
__device__ __align__(16) unsigned int g_Wf[2][MT_ * KT_ * 32 * 4];
__device__ float g_poold[ND * 2 * HH];
__device__ int   g_slen[NS];
__device__ int   g_offs[ND];

// ---------------- helpers ----------------
typedef unsigned long long ull;
__device__ __forceinline__ ull pack1(float a) {
    ull r; asm("mov.b64 %0, {%1, %1};" : "=l"(r) : "f"(a)); return r;
}
__device__ __forceinline__ void fma2(ull& d, ull a, ull b) {
    asm("fma.rn.f32x2 %0, %1, %2, %0;" : "+l"(d) : "l"(a), "l"(b));
}
__device__ __forceinline__ void unpack2(ull v, float& a, float& b) {
    asm("mov.b64 {%0, %1}, %2;" : "=f"(a), "=f"(b) : "l"(v));
}
__device__ __forceinline__ float sigmoidf_(float x) {
    return __fdividef(1.f, 1.f + __expf(-x));
}
__device__ __forceinline__ float tanhf_(float x) {
    return 2.f * __fdividef(1.f, 1.f + __expf(-2.f * x)) - 1.f;
}
__device__ __forceinline__ void mma_bf16(float* c, uint4 a,
                                         unsigned int b0, unsigned int b1) {
    asm volatile(
        "mma.sync.aligned.m16n8k16.row.col.f32.bf16.bf16.f32 "
        "{%0,%1,%2,%3}, {%4,%5,%6,%7}, {%8,%9}, {%0,%1,%2,%3};"
        : "+f"(c[0]), "+f"(c[1]), "+f"(c[2]), "+f"(c[3])
        : "r"(a.x), "r"(a.y), "r"(a.z), "r"(a.w), "r"(b0), "r"(b1));
}
__device__ __forceinline__ void cpa16(void* dst, const void* src, int sz) {
    unsigned int d = (unsigned int)__cvta_generic_to_shared(dst);
    asm volatile("cp.async.cg.shared.global [%0], [%1], 16, %2;"
                 :: "r"(d), "l"(src), "r"(sz));
}

// -------- bf16 tensor-core GEMM (double-buffered cp.async) --------
// C[M,N](ldc) = A[M,KP] @ B[N,KP]^T, A/B bf16 (rows KP-strided, KP mult of 8,
// zero-padded). BF16OUT: C bf16, else fp32.  128x64 tile, BK=32, 8 warps.
template <bool BF16OUT>
__global__ __launch_bounds__(256) void gemm_bf16(
    const __nv_bfloat16* __restrict__ A, const __nv_bfloat16* __restrict__ B,
    void* __restrict__ Cv, int M, int N, int KP, int ldc) {
    extern __shared__ __align__(16) __nv_bfloat16 smh[];
    __nv_bfloat16* As = smh;                 // [2][128][40]
    __nv_bfloat16* Bs = smh + 2 * 128 * 40;  // [2][64][40]
    int tid = threadIdx.x;
    int mb = blockIdx.y * 128, nb = blockIdx.x * 64;
    int warp = tid >> 5, lane = tid & 31;
    int wm = warp & 3, wn = warp >> 2;
    int gid = lane >> 2, tig = lane & 3;

    float c[2][4][4];
#pragma unroll
    for (int mt = 0; mt < 2; mt++)
#pragma unroll
        for (int nt = 0; nt < 4; nt++)
#pragma unroll
            for (int i = 0; i < 4; i++) c[mt][nt][i] = 0.f;

    int nk = (KP + 31) / 32;

    auto load_chunk = [&](int i, int buf) {
#pragma unroll
        for (int l = 0; l < 2; l++) {
            int cch = tid + l * 256;
            int row = cch >> 2, seg = cch & 3;
            int col = i * 32 + seg * 8;
            int gm = mb + row;
            int sz = (gm < M && col < KP) ? 16 : 0;
            if (gm >= M) gm = M - 1;
            int cc = (col < KP) ? col : 0;
            cpa16(&As[buf * 128 * 40 + row * 40 + seg * 8],
                  &A[(size_t)gm * KP + cc], sz);
        }
        {
            int row = tid >> 2, seg = tid & 3;
            int col = i * 32 + seg * 8;
            int gn = nb + row;
            int sz = (gn < N && col < KP) ? 16 : 0;
            if (gn >= N) gn = N - 1;
            int cc = (col < KP) ? col : 0;
            cpa16(&Bs[buf * 64 * 40 + row * 40 + seg * 8],
                  &B[(size_t)gn * KP + cc], sz);
        }
        asm volatile("cp.async.commit_group;");
    };

    load_chunk(0, 0);
    for (int i = 0; i < nk; i++) {
        if (i + 1 < nk) {
            load_chunk(i + 1, (i + 1) & 1);
            asm volatile("cp.async.wait_group 1;");
        } else {
            asm volatile("cp.async.wait_group 0;");
        }
        __syncthreads();
        const __nv_bfloat16* Ab = As + (i & 1) * 128 * 40;
        const __nv_bfloat16* Bb = Bs + (i & 1) * 64 * 40;
#pragma unroll
        for (int kc = 0; kc < 2; kc++) {
            int kk = kc * 16 + 2 * tig;
            uint4 af[2];
#pragma unroll
            for (int mt = 0; mt < 2; mt++) {
                int mr = wm * 32 + mt * 16;
                af[mt].x = *(const unsigned int*)&Ab[(mr + gid) * 40 + kk];
                af[mt].y = *(const unsigned int*)&Ab[(mr + gid + 8) * 40 + kk];
                af[mt].z = *(const unsigned int*)&Ab[(mr + gid) * 40 + kk + 8];
                af[mt].w = *(const unsigned int*)&Ab[(mr + gid + 8) * 40 + kk + 8];
            }
            unsigned int bf[4][2];
#pragma unroll
            for (int nt = 0; nt < 4; nt++) {
                int nc = wn * 32 + nt * 8;
                bf[nt][0] = *(const unsigned int*)&Bb[(nc + gid) * 40 + kk];
                bf[nt][1] = *(const unsigned int*)&Bb[(nc + gid) * 40 + kk + 8];
            }
#pragma unroll
            for (int mt = 0; mt < 2; mt++)
#pragma unroll
                for (int nt = 0; nt < 4; nt++)
                    mma_bf16(c[mt][nt], af[mt], bf[nt][0], bf[nt][1]);
        }
        __syncthreads();
    }
#pragma unroll
    for (int mt = 0; mt < 2; mt++)
#pragma unroll
        for (int nt = 0; nt < 4; nt++) {
            int row0 = mb + wm * 32 + mt * 16 + gid;
            int col0 = nb + wn * 32 + nt * 8 + tig * 2;
            if (col0 < N) {
                if (BF16OUT) {
                    __nv_bfloat16* C = (__nv_bfloat16*)Cv;
                    if (row0 < M)
                        *(__nv_bfloat162*)&C[(size_t)row0 * ldc + col0] =
                            __float22bfloat162_rn(
                                make_float2(c[mt][nt][0], c[mt][nt][1]));
                    if (row0 + 8 < M)
                        *(__nv_bfloat162*)&C[(size_t)(row0 + 8) * ldc + col0] =
                            __float22bfloat162_rn(
                                make_float2(c[mt][nt][2], c[mt][nt][3]));
                } else {
                    float* C = (float*)Cv;
                    if (row0 < M)
                        *(float2*)&C[(size_t)row0 * ldc + col0] =
                            make_float2(c[mt][nt][0], c[mt][nt][1]);
                    if (row0 + 8 < M)
                        *(float2*)&C[(size_t)(row0 + 8) * ldc + col0] =
                            make_float2(c[mt][nt][2], c[mt][nt][3]);
                }
            }
        }
}

// ---------------- word-level persistent GRU on tensor cores ----------------
__global__ __launch_bounds__(512, 1) void gru_tc(
    const int* __restrict__ toks,
    const float* __restrict__ bi_f, const float* __restrict__ bh_f,
    const float* __restrict__ bi_b, const float* __restrict__ bh_b) {
    extern __shared__ __align__(16) char sm_[];
    float* G = (float*)sm_;
    __nv_bfloat16* HbHi = (__nv_bfloat16*)(sm_ + 98560);
    __nv_bfloat16* gxS = (__nv_bfloat16*)(sm_ + 117120);
    int* gxb = (int*)(sm_ + 165760);
    int* sln = (int*)(sm_ + 173760);
    float* Hf = (float*)(sm_ + 173920);

    int dir = blockIdx.y;
    int b0 = blockIdx.x * BR_;
    const unsigned int* wdir = g_Wf[dir];
    const float* bi = dir ? bi_b : bi_f;
    const float* bh = dir ? bh_b : bh_f;
    int tid = threadIdx.x;
    int warp = tid >> 5, lane = tid & 31;
    int gid = lane >> 2, tig = lane & 3;

    for (int idx = tid; idx < 40 * KPAD / 2; idx += 512)
        ((unsigned int*)HbHi)[idx] = 0u;
    for (int idx = tid; idx < BR_ * HH; idx += 512) Hf[idx] = 0.f;
    for (int idx = tid; idx < TW * BR_; idx += 512) {
        int t = idx / BR_, b = idx % BR_;
        int tt = dir ? (TW - 1 - t) : t;
        int row = toks[(b0 + b) * TW + tt];
        gxb[idx] = row * GXW + dir * GG;
    }
    if (tid < BR_) sln[tid] = g_slen[b0 + tid];
    __syncthreads();

    int ej = tid < 400 ? (tid % 200) : 0;
    int ehalf = tid < 400 ? (tid / 200) : 0;
    float br = 0, bz = 0, bin = 0, bhn = 0;
    if (tid < 400) {
        br = bi[ej] + bh[ej];
        bz = bi[HH + ej] + bh[HH + ej];
        bin = bi[2 * HH + ej];
        bhn = bh[2 * HH + ej];
    }
    float pool_r[20];
#pragma unroll
    for (int i = 0; i < 20; i++) pool_r[i] = 0.f;

    for (int t = 0; t < TW; t++) {
        int tt = dir ? (TW - 1 - t) : t;
        {
            const int* gq = gxb + t * BR_;
            for (int ci = tid; ci < BR_ * 75; ci += 512) {
                int b = ci / 75, off = (ci % 75) * 8;
                cpa16(gxS + b * 608 + off, g_P + gq[b] + off, 16);
            }
            asm volatile("cp.async.commit_group;");
        }
        for (int mt = warp; mt < MT_; mt += 16) {
            float c[NT_][4];
#pragma unroll
            for (int nt = 0; nt < NT_; nt++)
#pragma unroll
                for (int i = 0; i < 4; i++) c[nt][i] = 0.f;
            const unsigned int* wfb = wdir + (size_t)mt * KT_ * 32 * 4;
#pragma unroll 4
            for (int kt = 0; kt < KT_; kt++) {
                uint4 ahi = *(const uint4*)(wfb + ((size_t)kt * 32 + lane) * 4);
                int koff = kt * 16 + tig * 2;
#pragma unroll
                for (int nt = 0; nt < NT_; nt++) {
                    int n = nt * 8 + gid;
                    unsigned int bhi0 = *(const unsigned int*)&HbHi[n * KPAD + koff];
                    unsigned int bhi1 = *(const unsigned int*)&HbHi[n * KPAD + koff + 8];
                    mma_bf16(c[nt], ahi, bhi0, bhi1);
                }
            }
#pragma unroll
            for (int nt = 0; nt < NT_; nt++) {
                int bcol = nt * 8 + tig * 2;
                int m = mt * 16 + gid;
                G[bcol * GPAD + m] = c[nt][0];
                G[(bcol + 1) * GPAD + m] = c[nt][1];
                G[bcol * GPAD + m + 8] = c[nt][2];
                G[(bcol + 1) * GPAD + m + 8] = c[nt][3];
            }
        }
        asm volatile("cp.async.wait_group 0;");
        __syncthreads();
        if (tid < 400) {
#pragma unroll 4
            for (int i = 0; i < 20; i++) {
                int b = ehalf * 20 + i;
                float gxr = __bfloat162float(gxS[b * 608 + ej]);
                float gxz = __bfloat162float(gxS[b * 608 + 200 + ej]);
                float gxn = __bfloat162float(gxS[b * 608 + 400 + ej]);
                float gr = G[b * GPAD + ej];
                float gz = G[b * GPAD + ej + 200];
                float gn = G[b * GPAD + ej + 400];
                float r = sigmoidf_(gxr + gr + br);
                float z = sigmoidf_(gxz + gz + bz);
                float nn = tanhf_(gxn + bin + r * (gn + bhn));
                float ho = Hf[b * HH + ej];
                float hnew = (1.f - z) * nn + z * ho;
                Hf[b * HH + ej] = hnew;
                if (tt < sln[b]) pool_r[i] += hnew;
                HbHi[b * KPAD + ej] = __float2bfloat16(hnew);
            }
        }
        __syncthreads();
    }

    if (tid < 400) {
#pragma unroll
        for (int i = 0; i < 20; i++) {
            int b = ehalf * 20 + i;
            int l = sln[b];
            float v = l ? pool_r[i] / (float)l : 0.f;
            g_pool[(size_t)(b0 + b) * (2 * HH) + (size_t)dir * HH + ej] =
                __float2bfloat16(v);
        }
    }
}

// ---------------- sentence-level persistent GRU (fp32) ----------
template <int BROWS>
__global__ __launch_bounds__(512, 1) void gru_seq_s(
    const int* __restrict__ dlens,
    const float* __restrict__ bi_f, const float* __restrict__ bh_f,
    const float* __restrict__ bi_b, const float* __restrict__ bh_b) {
    constexpr int PW = BROWS / 2;
    constexpr int BP = PW / 2;
    constexpr int HR = BROWS / 2;
    constexpr int CH = HR * 150;
    constexpr int TLEN = DT;

    extern __shared__ __align__(16) char sm_[];
    float2* hsT   = (float2*)sm_;
    float*  gxs_  = (float*)(sm_ + HH * PW * 8);
    float* pool_s = (float*)(sm_ + HH * PW * 8 + BROWS * 600 * 4);
    int* gxb = (int*)(sm_ + HH * PW * 8 + BROWS * 600 * 4 + BROWS * HH * 4);
    int* sln = gxb + TLEN * BROWS;

    int dir = blockIdx.y;
    int b0 = blockIdx.x * BROWS;
    const float4* wP = g_wP[dir];
    const float* bi = dir ? bi_b : bi_f;
    const float* bh = dir ? bh_b : bh_f;
    int tid = threadIdx.x;
    int half = tid >> 8;
    int j = tid & 255;
    int pbase = half * BP;

    for (int idx = tid; idx < HH * PW; idx += 512) hsT[idx] = make_float2(0.f, 0.f);
    for (int idx = tid; idx < BROWS * HH; idx += 512) pool_s[idx] = 0.f;
    for (int idx = tid; idx < TLEN * BROWS; idx += 512) {
        int t = idx / BROWS, b = idx % BROWS;
        int tt = dir ? (TLEN - 1 - t) : t;
        int row = (b0 + b) * TLEN + tt;
        gxb[idx] = row * GXW + dir * GG;
    }
    if (tid < BROWS) sln[tid] = dlens[b0 + tid];
    __syncthreads();

    float br = 0, bz = 0, bin = 0, bhn = 0;
    if (j < HH) {
        br = bi[j] + bh[j];
        bz = bi[HH + j] + bh[HH + j];
        bin = bi[2 * HH + j];
        bhn = bh[2 * HH + j];
    }

    for (int t = 0; t < TLEN; t++) {
        int tt = dir ? (TLEN - 1 - t) : t;
        {
            const int* gq = gxb + t * BROWS;
#pragma unroll 2
            for (int c = j; c < CH; c += 256) {
                int b = half * HR + c / 150;
                int off = (c % 150) * 4;
                cpa16(gxs_ + b * 600 + off, g_gxs + gq[b] + off, 16);
            }
            asm volatile("cp.async.commit_group;");
        }
        ull aR[BP], aZ[BP], aN[BP];
        if (j < HH) {
#pragma unroll
            for (int p = 0; p < BP; p++) { aR[p] = 0; aZ[p] = 0; aN[p] = 0; }
            const float4* wp = wP + j;
            float4 ra[4];
#pragma unroll
            for (int i = 0; i < 4; i++) ra[i] = wp[i * HH];
#pragma unroll 4
            for (int k = 0; k < HH; k++) {
                float4 wc = ra[k & 3];
                int kp = k + 4;
                if (kp < HH) ra[k & 3] = wp[kp * HH];
                ull w0 = pack1(wc.x), w1 = pack1(wc.y), w2 = pack1(wc.z);
#pragma unroll
                for (int q = 0; q < BP / 2; q++) {
                    ulonglong2 hq =
                        *(const ulonglong2*)&hsT[k * PW + pbase + 2 * q];
                    fma2(aR[2 * q], hq.x, w0);
                    fma2(aZ[2 * q], hq.x, w1);
                    fma2(aN[2 * q], hq.x, w2);
                    fma2(aR[2 * q + 1], hq.y, w0);
                    fma2(aZ[2 * q + 1], hq.y, w1);
                    fma2(aN[2 * q + 1], hq.y, w2);
                }
            }
        }
        asm volatile("cp.async.wait_group 0;");
        asm volatile("bar.sync %0, 256;" :: "r"(1 + half) : "memory");
        if (j < HH) {
#pragma unroll
            for (int p = 0; p < BP; p++) {
                int gp = pbase + p;
                float hr[2], hz[2], hn[2], hnew[2];
                unpack2(aR[p], hr[0], hr[1]);
                unpack2(aZ[p], hz[0], hz[1]);
                unpack2(aN[p], hn[0], hn[1]);
                float2 hold = hsT[j * PW + gp];
#pragma unroll
                for (int l = 0; l < 2; l++) {
                    int b = 2 * gp + l;
                    const float* gx = gxs_ + b * 600;
                    float r = sigmoidf_(gx[j] + hr[l] + br);
                    float z = sigmoidf_(gx[HH + j] + hz[l] + bz);
                    float nn = tanhf_(gx[2 * HH + j] + bin + r * (hn[l] + bhn));
                    float ho = l ? hold.y : hold.x;
                    hnew[l] = (1.f - z) * nn + z * ho;
                    if (tt < sln[b]) pool_s[b * HH + j] += hnew[l];
                }
                hsT[j * PW + gp] = make_float2(hnew[0], hnew[1]);
            }
        }
        asm volatile("bar.sync %0, 256;" :: "r"(1 + half) : "memory");
    }

    if (j < HH) {
#pragma unroll
        for (int p = 0; p < BP; p++) {
#pragma unroll
            for (int l = 0; l < 2; l++) {
                int b = 2 * (pbase + p) + l;
                int ln = sln[b];
                float v = pool_s[b * HH + j];
                g_poold[(size_t)(b0 + b) * (2 * HH) + (size_t)dir * HH + j] =
                    ln ? v / (float)ln : 0.f;
            }
        }
    }
}

// ---------------- prep ----------------
__global__ void k_prep(const int* __restrict__ x, const float* __restrict__ emb,
                       const float* __restrict__ wf_ih, const float* __restrict__ wb_ih,
                       const float* __restrict__ sf_ih, const float* __restrict__ sb_ih,
                       const float* __restrict__ wf_hh, const float* __restrict__ wb_hh,
                       const float* __restrict__ sf_hh, const float* __restrict__ sb_hh) {
    int i0 = blockIdx.x * blockDim.x + threadIdx.x;
    int gs = gridDim.x * blockDim.x;
    // sentence recurrent fp32 packed
    const float* wss[2] = {sf_hh, sb_hh};
    for (int idx = i0; idx < HH * HH; idx += gs) {
        int k = idx / HH, j = idx % HH;
#pragma unroll
        for (int a = 0; a < 2; a++) {
            g_wP[a][idx] = make_float4(wss[a][j * HH + k],
                                       wss[a][(HH + j) * HH + k],
                                       wss[a][(2 * HH + j) * HH + k], 0.f);
        }
    }
    // word recurrent bf16 mma fragments
    const float* wsw[2] = {wf_hh, wb_hh};
    const int TOT = 2 * MT_ * KT_ * 32 * 4;
    for (int idx = i0; idx < TOT; idx += gs) {
        int rr = idx & 3;
        int lane = (idx >> 2) & 31;
        int kt = (idx >> 7) % KT_;
        int mt = (idx / (KT_ * 32 * 4)) % MT_;
        int a = idx / (MT_ * KT_ * 32 * 4);
        int gid = lane >> 2, tig = lane & 3;
        int row = mt * 16 + gid + (rr & 1) * 8;
        int k0 = kt * 16 + tig * 2 + ((rr >> 1) & 1) * 8;
        float w0 = (row < GG && k0 < HH) ? wsw[a][row * HH + k0] : 0.f;
        float w1 = (row < GG && k0 + 1 < HH) ? wsw[a][row * HH + k0 + 1] : 0.f;
        __nv_bfloat16 h0 = __float2bfloat16(w0);
        __nv_bfloat16 h1 = __float2bfloat16(w1);
        unsigned int hiw = ((unsigned int)__bfloat16_as_ushort(h1) << 16) |
                           (unsigned int)__bfloat16_as_ushort(h0);
        g_Wf[a][(((size_t)mt * KT_ + kt) * 32 + lane) * 4 + rr] = hiw;
    }
    // emb -> bf16 padded
    for (int idx = i0; idx < VOC * KPE; idx += gs) {
        int r = idx / KPE, k = idx - r * KPE;
        g_embB[idx] = __float2bfloat16(k < DD ? emb[r * DD + k] : 0.f);
    }
    // [wf_ih; wb_ih] -> bf16 padded
    for (int idx = i0; idx < GXW * KPE; idx += gs) {
        int r = idx / KPE, k = idx - r * KPE;
        float v = 0.f;
        if (k < DD) v = (r < GG) ? wf_ih[r * DD + k] : wb_ih[(r - GG) * DD + k];
        g_WihB[idx] = __float2bfloat16(v);
    }
    // [sf_ih; sb_ih] -> bf16
    for (int idx = i0; idx < GXW * 400; idx += gs) {
        int r = idx / 400, k = idx - r * 400;
        float v = (r < GG) ? sf_ih[r * 400 + k] : sb_ih[(r - GG) * 400 + k];
        g_SihB[idx] = __float2bfloat16(v);
    }
    // sentence lengths
    for (int s = i0; s < NS; s += gs) {
        int c = 0;
        for (int t = 0; t < TW; t++) c += (x[s * TW + t] != 0);
        g_slen[s] = c;
    }
}

__global__ void k_scan(const int* __restrict__ dl) {
    if (threadIdx.x == 0) {
        int a = 0;
        for (int i = 0; i < ND; i++) { g_offs[i] = a; a += dl[i]; }
    }
}

__global__ __launch_bounds__(128) void k_final(const int* __restrict__ dl,
                                               const float* __restrict__ doc_w,
                                               const float* __restrict__ doc_b,
                                               const float* __restrict__ sent_w,
                                               const float* __restrict__ sent_b,
                                               float* __restrict__ out) {
    __shared__ float d[2 * HH];
    __shared__ float redw[4];
    int doc = blockIdx.x, tid = threadIdx.x;
    int l = dl[doc];
    for (int f = tid; f < 2 * HH; f += 128)
        d[f] = g_poold[doc * 2 * HH + f];
    __syncthreads();
    for (int r = 0; r < 11; r++) {
        const float* w = (r == 0) ? doc_w : sent_w + (r - 1) * 2 * HH;
        float p = 0.f;
        for (int f = tid; f < 2 * HH; f += 128) p += d[f] * w[f];
        for (int o = 16; o; o >>= 1) p += __shfl_down_sync(0xFFFFFFFFu, p, o);
        if ((tid & 31) == 0) redw[tid >> 5] = p;
        __syncthreads();
        if (tid == 0) {
            float s = redw[0] + redw[1] + redw[2] + redw[3];
            if (r == 0) out[doc] = sigmoidf_(s + doc_b[0]);
            else if (r - 1 < l) out[ND + g_offs[doc] + (r - 1)] = sigmoidf_(s + sent_b[r - 1]);
        }
        __syncthreads();
    }
}

// ---------------- host ----------------
extern "C" void kernel_launch(void* const* d_in, const int* in_sizes, int n_in,
                              void* d_out, int out_size) {
    int base = (n_in >= 24) ? 1 : 0;
    const int*   x        = (const int*)d_in[0];
    const int*   doc_lens = (const int*)d_in[1 + base];
    const float* emb      = (const float*)d_in[2 + base];
    const float* wf_ih    = (const float*)d_in[3 + base];
    const float* wf_hh    = (const float*)d_in[4 + base];
    const float* wf_bi    = (const float*)d_in[5 + base];
    const float* wf_bh    = (const float*)d_in[6 + base];
    const float* wb_ih    = (const float*)d_in[7 + base];
    const float* wb_hh    = (const float*)d_in[8 + base];
    const float* wb_bi    = (const float*)d_in[9 + base];
    const float* wb_bh    = (const float*)d_in[10 + base];
    const float* sf_ih    = (const float*)d_in[11 + base];
    const float* sf_hh    = (const float*)d_in[12 + base];
    const float* sf_bi    = (const float*)d_in[13 + base];
    const float* sf_bh    = (const float*)d_in[14 + base];
    const float* sb_ih    = (const float*)d_in[15 + base];
    const float* sb_hh    = (const float*)d_in[16 + base];
    const float* sb_bi    = (const float*)d_in[17 + base];
    const float* sb_bh    = (const float*)d_in[18 + base];
    const float* doc_w    = (const float*)d_in[19 + base];
    const float* doc_b    = (const float*)d_in[20 + base];
    const float* sent_w   = (const float*)d_in[21 + base];
    const float* sent_b   = (const float*)d_in[22 + base];
    float* out = (float*)d_out;

    void *P, *gxs, *pool, *embB, *wihB, *sihB;
    cudaGetSymbolAddress(&P, g_P);
    cudaGetSymbolAddress(&gxs, g_gxs);
    cudaGetSymbolAddress(&pool, g_pool);
    cudaGetSymbolAddress(&embB, g_embB);
    cudaGetSymbolAddress(&wihB, g_WihB);
    cudaGetSymbolAddress(&sihB, g_SihB);

    const int SMB = (2 * 128 * 40 + 2 * 64 * 40) * 2;   // 30,720
    const int SMW = 205920;
    const int SMS = HH * 8 * 8 + 16 * 600 * 4 + 16 * HH * 4 + DT * 16 * 4 + 16 * 4;
    cudaFuncSetAttribute(gemm_bf16<true>,
                         cudaFuncAttributeMaxDynamicSharedMemorySize, SMB);
    cudaFuncSetAttribute(gemm_bf16<false>,
                         cudaFuncAttributeMaxDynamicSharedMemorySize, SMB);
    cudaFuncSetAttribute(gru_tc,
                         cudaFuncAttributeMaxDynamicSharedMemorySize, SMW);
    cudaFuncSetAttribute(gru_seq_s<16>,
                         cudaFuncAttributeMaxDynamicSharedMemorySize, SMS);

    k_prep<<<512, 256>>>(x, emb, wf_ih, wb_ih, sf_ih, sb_ih,
                         wf_hh, wb_hh, sf_hh, sb_hh);

    // P = embB @ WihB^T   (50000 x 1200, K=304 padded) — bf16 mma, bf16 out
    gemm_bf16<true><<<dim3((GXW + 63) / 64, (VOC + 127) / 128), 256, SMB>>>(
        (const __nv_bfloat16*)embB, (const __nv_bfloat16*)wihB, P,
        VOC, GXW, KPE, GXW);

    // word-level BiGRU: persistent tensor-core kernel, 64 x 2 blocks
    gru_tc<<<dim3(NS / BR_, 2), 512, SMW>>>(x, wf_bi, wf_bh, wb_bi, wb_bh);

    // sentence gates: gxs = pool @ SihB^T (2560 x 1200, K=400) — bf16, fp32 out
    gemm_bf16<false><<<dim3((GXW + 63) / 64, (NS + 127) / 128), 256, SMB>>>(
        (const __nv_bfloat16*)pool, (const __nv_bfloat16*)sihB, gxs,
        NS, GXW, 400, GXW);

    // sentence-level BiGRU: fp32 persistent, 16 x 2 blocks
    gru_seq_s<16><<<dim3(ND / 16, 2), 512, SMS>>>(
        doc_lens, sf_bi, sf_bh, sb_bi, sb_bh);

    k_scan<<<1, 32>>>(doc_lens);
    k_final<<<ND, 128>>>(doc_lens, doc_w, doc_b, sent_w, sent_b, out);
}

// round 14
// speedup vs baseline: 4.2956x; 1.0767x over previous
#include <cuda_runtime.h>
#include <cuda_bf16.h>
#include <math.h>

#define HH   200
#define DD   300
#define TW   50
#define NS   2560
#define ND   256
#define DT   10
#define GG   600
#define GXW  1200
#define VOC  50000
#define KPE  304

// word-level tensor-core GRU geometry
#define MT_   38
#define KT_   13
#define NT_   5
#define BR_   40
#define KPAD  232
#define GPAD  616

// ---------------- device scratch ----------------
__device__ __nv_bfloat16 g_P[VOC * GXW];
__device__ __nv_bfloat16 g_embB[VOC * KPE];
__device__ __nv_bfloat16 g_WihB[GXW * KPE];
__device__ __nv_bfloat16 g_SihB[GXW * 400];
__device__ __nv_bfloat16 g_pool[NS * 2 * HH];
__device__ float g_gxs[NS * GXW];
__device__ __align__(16) float4 g_wP[2][HH * HH];
__device__ __align__(16) unsigned int g_Wf[2][MT_ * KT_ * 32 * 4];
__device__ float g_poold[ND * 2 * HH];
__device__ int   g_slen[NS];
__device__ int   g_offs[ND];

// ---------------- helpers ----------------
typedef unsigned long long ull;
__device__ __forceinline__ ull pack1(float a) {
    ull r; asm("mov.b64 %0, {%1, %1};" : "=l"(r) : "f"(a)); return r;
}
__device__ __forceinline__ void fma2(ull& d, ull a, ull b) {
    asm("fma.rn.f32x2 %0, %1, %2, %0;" : "+l"(d) : "l"(a), "l"(b));
}
__device__ __forceinline__ void unpack2(ull v, float& a, float& b) {
    asm("mov.b64 {%0, %1}, %2;" : "=f"(a), "=f"(b) : "l"(v));
}
__device__ __forceinline__ float tanha_(float x) {
    float y; asm("tanh.approx.f32 %0, %1;" : "=f"(y) : "f"(x)); return y;
}
__device__ __forceinline__ float sigmoidf_(float x) {
    return fmaf(0.5f, tanha_(0.5f * x), 0.5f);
}
__device__ __forceinline__ void mma_bf16(float* c, uint4 a,
                                         unsigned int b0, unsigned int b1) {
    asm volatile(
        "mma.sync.aligned.m16n8k16.row.col.f32.bf16.bf16.f32 "
        "{%0,%1,%2,%3}, {%4,%5,%6,%7}, {%8,%9}, {%0,%1,%2,%3};"
        : "+f"(c[0]), "+f"(c[1]), "+f"(c[2]), "+f"(c[3])
        : "r"(a.x), "r"(a.y), "r"(a.z), "r"(a.w), "r"(b0), "r"(b1));
}
__device__ __forceinline__ void cpa16(void* dst, const void* src, int sz) {
    unsigned int d = (unsigned int)__cvta_generic_to_shared(dst);
    asm volatile("cp.async.cg.shared.global [%0], [%1], 16, %2;"
                 :: "r"(d), "l"(src), "r"(sz));
}

// -------- bf16 tensor-core GEMM (double-buffered cp.async) --------
template <bool BF16OUT>
__global__ __launch_bounds__(256) void gemm_bf16(
    const __nv_bfloat16* __restrict__ A, const __nv_bfloat16* __restrict__ B,
    void* __restrict__ Cv, int M, int N, int KP, int ldc) {
    extern __shared__ __align__(16) __nv_bfloat16 smh[];
    __nv_bfloat16* As = smh;
    __nv_bfloat16* Bs = smh + 2 * 128 * 40;
    int tid = threadIdx.x;
    int mb = blockIdx.y * 128, nb = blockIdx.x * 64;
    int warp = tid >> 5, lane = tid & 31;
    int wm = warp & 3, wn = warp >> 2;
    int gid = lane >> 2, tig = lane & 3;

    float c[2][4][4];
#pragma unroll
    for (int mt = 0; mt < 2; mt++)
#pragma unroll
        for (int nt = 0; nt < 4; nt++)
#pragma unroll
            for (int i = 0; i < 4; i++) c[mt][nt][i] = 0.f;

    int nk = (KP + 31) / 32;

    auto load_chunk = [&](int i, int buf) {
#pragma unroll
        for (int l = 0; l < 2; l++) {
            int cch = tid + l * 256;
            int row = cch >> 2, seg = cch & 3;
            int col = i * 32 + seg * 8;
            int gm = mb + row;
            int sz = (gm < M && col < KP) ? 16 : 0;
            if (gm >= M) gm = M - 1;
            int cc = (col < KP) ? col : 0;
            cpa16(&As[buf * 128 * 40 + row * 40 + seg * 8],
                  &A[(size_t)gm * KP + cc], sz);
        }
        {
            int row = tid >> 2, seg = tid & 3;
            int col = i * 32 + seg * 8;
            int gn = nb + row;
            int sz = (gn < N && col < KP) ? 16 : 0;
            if (gn >= N) gn = N - 1;
            int cc = (col < KP) ? col : 0;
            cpa16(&Bs[buf * 64 * 40 + row * 40 + seg * 8],
                  &B[(size_t)gn * KP + cc], sz);
        }
        asm volatile("cp.async.commit_group;");
    };

    load_chunk(0, 0);
    for (int i = 0; i < nk; i++) {
        if (i + 1 < nk) {
            load_chunk(i + 1, (i + 1) & 1);
            asm volatile("cp.async.wait_group 1;");
        } else {
            asm volatile("cp.async.wait_group 0;");
        }
        __syncthreads();
        const __nv_bfloat16* Ab = As + (i & 1) * 128 * 40;
        const __nv_bfloat16* Bb = Bs + (i & 1) * 64 * 40;
#pragma unroll
        for (int kc = 0; kc < 2; kc++) {
            int kk = kc * 16 + 2 * tig;
            uint4 af[2];
#pragma unroll
            for (int mt = 0; mt < 2; mt++) {
                int mr = wm * 32 + mt * 16;
                af[mt].x = *(const unsigned int*)&Ab[(mr + gid) * 40 + kk];
                af[mt].y = *(const unsigned int*)&Ab[(mr + gid + 8) * 40 + kk];
                af[mt].z = *(const unsigned int*)&Ab[(mr + gid) * 40 + kk + 8];
                af[mt].w = *(const unsigned int*)&Ab[(mr + gid + 8) * 40 + kk + 8];
            }
            unsigned int bf[4][2];
#pragma unroll
            for (int nt = 0; nt < 4; nt++) {
                int nc = wn * 32 + nt * 8;
                bf[nt][0] = *(const unsigned int*)&Bb[(nc + gid) * 40 + kk];
                bf[nt][1] = *(const unsigned int*)&Bb[(nc + gid) * 40 + kk + 8];
            }
#pragma unroll
            for (int mt = 0; mt < 2; mt++)
#pragma unroll
                for (int nt = 0; nt < 4; nt++)
                    mma_bf16(c[mt][nt], af[mt], bf[nt][0], bf[nt][1]);
        }
        __syncthreads();
    }
#pragma unroll
    for (int mt = 0; mt < 2; mt++)
#pragma unroll
        for (int nt = 0; nt < 4; nt++) {
            int row0 = mb + wm * 32 + mt * 16 + gid;
            int col0 = nb + wn * 32 + nt * 8 + tig * 2;
            if (col0 < N) {
                if (BF16OUT) {
                    __nv_bfloat16* C = (__nv_bfloat16*)Cv;
                    if (row0 < M)
                        *(__nv_bfloat162*)&C[(size_t)row0 * ldc + col0] =
                            __float22bfloat162_rn(
                                make_float2(c[mt][nt][0], c[mt][nt][1]));
                    if (row0 + 8 < M)
                        *(__nv_bfloat162*)&C[(size_t)(row0 + 8) * ldc + col0] =
                            __float22bfloat162_rn(
                                make_float2(c[mt][nt][2], c[mt][nt][3]));
                } else {
                    float* C = (float*)Cv;
                    if (row0 < M)
                        *(float2*)&C[(size_t)row0 * ldc + col0] =
                            make_float2(c[mt][nt][0], c[mt][nt][1]);
                    if (row0 + 8 < M)
                        *(float2*)&C[(size_t)(row0 + 8) * ldc + col0] =
                            make_float2(c[mt][nt][2], c[mt][nt][3]);
                }
            }
        }
}

// ---------------- word-level persistent GRU on tensor cores ----------------
__global__ __launch_bounds__(512, 1) void gru_tc(
    const int* __restrict__ toks,
    const float* __restrict__ bi_f, const float* __restrict__ bh_f,
    const float* __restrict__ bi_b, const float* __restrict__ bh_b) {
    extern __shared__ __align__(16) char sm_[];
    float* G = (float*)sm_;
    __nv_bfloat16* HbHi = (__nv_bfloat16*)(sm_ + 98560);
    __nv_bfloat16* gxS = (__nv_bfloat16*)(sm_ + 117120);
    int* gxb = (int*)(sm_ + 165760);
    int* sln = (int*)(sm_ + 173760);
    float* Hf = (float*)(sm_ + 173920);

    int dir = blockIdx.y;
    int b0 = blockIdx.x * BR_;
    const unsigned int* wdir = g_Wf[dir];
    const float* bi = dir ? bi_b : bi_f;
    const float* bh = dir ? bh_b : bh_f;
    int tid = threadIdx.x;
    int warp = tid >> 5, lane = tid & 31;
    int gid = lane >> 2, tig = lane & 3;

    for (int idx = tid; idx < 40 * KPAD / 2; idx += 512)
        ((unsigned int*)HbHi)[idx] = 0u;
    for (int idx = tid; idx < BR_ * HH; idx += 512) Hf[idx] = 0.f;
    for (int idx = tid; idx < TW * BR_; idx += 512) {
        int t = idx / BR_, b = idx % BR_;
        int tt = dir ? (TW - 1 - t) : t;
        int row = toks[(b0 + b) * TW + tt];
        gxb[idx] = row * GXW + dir * GG;
    }
    if (tid < BR_) sln[tid] = g_slen[b0 + tid];
    __syncthreads();

    int ej = tid < 400 ? (tid % 200) : 0;
    int ehalf = tid < 400 ? (tid / 200) : 0;
    float br = 0, bz = 0, bin = 0, bhn = 0;
    if (tid < 400) {
        br = bi[ej] + bh[ej];
        bz = bi[HH + ej] + bh[HH + ej];
        bin = bi[2 * HH + ej];
        bhn = bh[2 * HH + ej];
    }
    float pool_r[20];
#pragma unroll
    for (int i = 0; i < 20; i++) pool_r[i] = 0.f;

    for (int t = 0; t < TW; t++) {
        int tt = dir ? (TW - 1 - t) : t;
        {
            const int* gq = gxb + t * BR_;
            for (int ci = tid; ci < BR_ * 75; ci += 512) {
                int b = ci / 75, off = (ci % 75) * 8;
                cpa16(gxS + b * 608 + off, g_P + gq[b] + off, 16);
            }
            asm volatile("cp.async.commit_group;");
        }
        for (int mt = warp; mt < MT_; mt += 16) {
            float c[NT_][4];
#pragma unroll
            for (int nt = 0; nt < NT_; nt++)
#pragma unroll
                for (int i = 0; i < 4; i++) c[nt][i] = 0.f;
            const unsigned int* wfb = wdir + (size_t)mt * KT_ * 32 * 4;
            // depth-4 weight prefetch ring
            uint4 ring[4];
#pragma unroll
            for (int i = 0; i < 4; i++)
                ring[i] = *(const uint4*)(wfb + ((size_t)i * 32 + lane) * 4);
#pragma unroll
            for (int kt = 0; kt < KT_; kt++) {
                uint4 ahi = ring[kt & 3];
                int kp = kt + 4;
                if (kp < KT_)
                    ring[kt & 3] =
                        *(const uint4*)(wfb + ((size_t)kp * 32 + lane) * 4);
                int koff = kt * 16 + tig * 2;
#pragma unroll
                for (int nt = 0; nt < NT_; nt++) {
                    int n = nt * 8 + gid;
                    unsigned int bhi0 = *(const unsigned int*)&HbHi[n * KPAD + koff];
                    unsigned int bhi1 = *(const unsigned int*)&HbHi[n * KPAD + koff + 8];
                    mma_bf16(c[nt], ahi, bhi0, bhi1);
                }
            }
#pragma unroll
            for (int nt = 0; nt < NT_; nt++) {
                int bcol = nt * 8 + tig * 2;
                int m = mt * 16 + gid;
                G[bcol * GPAD + m] = c[nt][0];
                G[(bcol + 1) * GPAD + m] = c[nt][1];
                G[bcol * GPAD + m + 8] = c[nt][2];
                G[(bcol + 1) * GPAD + m + 8] = c[nt][3];
            }
        }
        asm volatile("cp.async.wait_group 0;");
        __syncthreads();
        if (tid < 400) {
#pragma unroll 4
            for (int i = 0; i < 20; i++) {
                int b = ehalf * 20 + i;
                float gxr = __bfloat162float(gxS[b * 608 + ej]);
                float gxz = __bfloat162float(gxS[b * 608 + 200 + ej]);
                float gxn = __bfloat162float(gxS[b * 608 + 400 + ej]);
                float gr = G[b * GPAD + ej];
                float gz = G[b * GPAD + ej + 200];
                float gn = G[b * GPAD + ej + 400];
                float r = sigmoidf_(gxr + gr + br);
                float z = sigmoidf_(gxz + gz + bz);
                float nn = tanha_(gxn + bin + r * (gn + bhn));
                float ho = Hf[b * HH + ej];
                float hnew = (1.f - z) * nn + z * ho;
                Hf[b * HH + ej] = hnew;
                if (tt < sln[b]) pool_r[i] += hnew;
                HbHi[b * KPAD + ej] = __float2bfloat16(hnew);
            }
        }
        __syncthreads();
    }

    if (tid < 400) {
#pragma unroll
        for (int i = 0; i < 20; i++) {
            int b = ehalf * 20 + i;
            int l = sln[b];
            float v = l ? pool_r[i] / (float)l : 0.f;
            g_pool[(size_t)(b0 + b) * (2 * HH) + (size_t)dir * HH + ej] =
                __float2bfloat16(v);
        }
    }
}

// ---------------- sentence-level persistent GRU (fp32) ----------
template <int BROWS>
__global__ __launch_bounds__(512, 1) void gru_seq_s(
    const int* __restrict__ dlens,
    const float* __restrict__ bi_f, const float* __restrict__ bh_f,
    const float* __restrict__ bi_b, const float* __restrict__ bh_b) {
    constexpr int PW = BROWS / 2;
    constexpr int BP = PW / 2;
    constexpr int HR = BROWS / 2;
    constexpr int CH = HR * 150;
    constexpr int TLEN = DT;

    extern __shared__ __align__(16) char sm_[];
    float2* hsT   = (float2*)sm_;
    float*  gxs_  = (float*)(sm_ + HH * PW * 8);
    float* pool_s = (float*)(sm_ + HH * PW * 8 + BROWS * 600 * 4);
    int* gxb = (int*)(sm_ + HH * PW * 8 + BROWS * 600 * 4 + BROWS * HH * 4);
    int* sln = gxb + TLEN * BROWS;

    int dir = blockIdx.y;
    int b0 = blockIdx.x * BROWS;
    const float4* wP = g_wP[dir];
    const float* bi = dir ? bi_b : bi_f;
    const float* bh = dir ? bh_b : bh_f;
    int tid = threadIdx.x;
    int half = tid >> 8;
    int j = tid & 255;
    int pbase = half * BP;

    for (int idx = tid; idx < HH * PW; idx += 512) hsT[idx] = make_float2(0.f, 0.f);
    for (int idx = tid; idx < BROWS * HH; idx += 512) pool_s[idx] = 0.f;
    for (int idx = tid; idx < TLEN * BROWS; idx += 512) {
        int t = idx / BROWS, b = idx % BROWS;
        int tt = dir ? (TLEN - 1 - t) : t;
        int row = (b0 + b) * TLEN + tt;
        gxb[idx] = row * GXW + dir * GG;
    }
    if (tid < BROWS) sln[tid] = dlens[b0 + tid];
    __syncthreads();

    float br = 0, bz = 0, bin = 0, bhn = 0;
    if (j < HH) {
        br = bi[j] + bh[j];
        bz = bi[HH + j] + bh[HH + j];
        bin = bi[2 * HH + j];
        bhn = bh[2 * HH + j];
    }

    for (int t = 0; t < TLEN; t++) {
        int tt = dir ? (TLEN - 1 - t) : t;
        {
            const int* gq = gxb + t * BROWS;
#pragma unroll 2
            for (int c = j; c < CH; c += 256) {
                int b = half * HR + c / 150;
                int off = (c % 150) * 4;
                cpa16(gxs_ + b * 600 + off, g_gxs + gq[b] + off, 16);
            }
            asm volatile("cp.async.commit_group;");
        }
        ull aR[BP], aZ[BP], aN[BP];
        if (j < HH) {
#pragma unroll
            for (int p = 0; p < BP; p++) { aR[p] = 0; aZ[p] = 0; aN[p] = 0; }
            const float4* wp = wP + j;
            float4 ra[4];
#pragma unroll
            for (int i = 0; i < 4; i++) ra[i] = wp[i * HH];
#pragma unroll 4
            for (int k = 0; k < HH; k++) {
                float4 wc = ra[k & 3];
                int kp = k + 4;
                if (kp < HH) ra[k & 3] = wp[kp * HH];
                ull w0 = pack1(wc.x), w1 = pack1(wc.y), w2 = pack1(wc.z);
#pragma unroll
                for (int q = 0; q < BP / 2; q++) {
                    ulonglong2 hq =
                        *(const ulonglong2*)&hsT[k * PW + pbase + 2 * q];
                    fma2(aR[2 * q], hq.x, w0);
                    fma2(aZ[2 * q], hq.x, w1);
                    fma2(aN[2 * q], hq.x, w2);
                    fma2(aR[2 * q + 1], hq.y, w0);
                    fma2(aZ[2 * q + 1], hq.y, w1);
                    fma2(aN[2 * q + 1], hq.y, w2);
                }
            }
        }
        asm volatile("cp.async.wait_group 0;");
        asm volatile("bar.sync %0, 256;" :: "r"(1 + half) : "memory");
        if (j < HH) {
#pragma unroll
            for (int p = 0; p < BP; p++) {
                int gp = pbase + p;
                float hr[2], hz[2], hn[2], hnew[2];
                unpack2(aR[p], hr[0], hr[1]);
                unpack2(aZ[p], hz[0], hz[1]);
                unpack2(aN[p], hn[0], hn[1]);
                float2 hold = hsT[j * PW + gp];
#pragma unroll
                for (int l = 0; l < 2; l++) {
                    int b = 2 * gp + l;
                    const float* gx = gxs_ + b * 600;
                    float r = sigmoidf_(gx[j] + hr[l] + br);
                    float z = sigmoidf_(gx[HH + j] + hz[l] + bz);
                    float nn = tanha_(gx[2 * HH + j] + bin + r * (hn[l] + bhn));
                    float ho = l ? hold.y : hold.x;
                    hnew[l] = (1.f - z) * nn + z * ho;
                    if (tt < sln[b]) pool_s[b * HH + j] += hnew[l];
                }
                hsT[j * PW + gp] = make_float2(hnew[0], hnew[1]);
            }
        }
        asm volatile("bar.sync %0, 256;" :: "r"(1 + half) : "memory");
    }

    if (j < HH) {
#pragma unroll
        for (int p = 0; p < BP; p++) {
#pragma unroll
            for (int l = 0; l < 2; l++) {
                int b = 2 * (pbase + p) + l;
                int ln = sln[b];
                float v = pool_s[b * HH + j];
                g_poold[(size_t)(b0 + b) * (2 * HH) + (size_t)dir * HH + j] =
                    ln ? v / (float)ln : 0.f;
            }
        }
    }
}

// ---------------- prep ----------------
__global__ void k_prep(const int* __restrict__ x, const float* __restrict__ emb,
                       const float* __restrict__ wf_ih, const float* __restrict__ wb_ih,
                       const float* __restrict__ sf_ih, const float* __restrict__ sb_ih,
                       const float* __restrict__ wf_hh, const float* __restrict__ wb_hh,
                       const float* __restrict__ sf_hh, const float* __restrict__ sb_hh) {
    int i0 = blockIdx.x * blockDim.x + threadIdx.x;
    int gs = gridDim.x * blockDim.x;
    const float* wss[2] = {sf_hh, sb_hh};
    for (int idx = i0; idx < HH * HH; idx += gs) {
        int k = idx / HH, j = idx % HH;
#pragma unroll
        for (int a = 0; a < 2; a++) {
            g_wP[a][idx] = make_float4(wss[a][j * HH + k],
                                       wss[a][(HH + j) * HH + k],
                                       wss[a][(2 * HH + j) * HH + k], 0.f);
        }
    }
    const float* wsw[2] = {wf_hh, wb_hh};
    const int TOT = 2 * MT_ * KT_ * 32 * 4;
    for (int idx = i0; idx < TOT; idx += gs) {
        int rr = idx & 3;
        int lane = (idx >> 2) & 31;
        int kt = (idx >> 7) % KT_;
        int mt = (idx / (KT_ * 32 * 4)) % MT_;
        int a = idx / (MT_ * KT_ * 32 * 4);
        int gid = lane >> 2, tig = lane & 3;
        int row = mt * 16 + gid + (rr & 1) * 8;
        int k0 = kt * 16 + tig * 2 + ((rr >> 1) & 1) * 8;
        float w0 = (row < GG && k0 < HH) ? wsw[a][row * HH + k0] : 0.f;
        float w1 = (row < GG && k0 + 1 < HH) ? wsw[a][row * HH + k0 + 1] : 0.f;
        __nv_bfloat16 h0 = __float2bfloat16(w0);
        __nv_bfloat16 h1 = __float2bfloat16(w1);
        unsigned int hiw = ((unsigned int)__bfloat16_as_ushort(h1) << 16) |
                           (unsigned int)__bfloat16_as_ushort(h0);
        g_Wf[a][(((size_t)mt * KT_ + kt) * 32 + lane) * 4 + rr] = hiw;
    }
    for (int idx = i0; idx < VOC * KPE; idx += gs) {
        int r = idx / KPE, k = idx - r * KPE;
        g_embB[idx] = __float2bfloat16(k < DD ? emb[r * DD + k] : 0.f);
    }
    for (int idx = i0; idx < GXW * KPE; idx += gs) {
        int r = idx / KPE, k = idx - r * KPE;
        float v = 0.f;
        if (k < DD) v = (r < GG) ? wf_ih[r * DD + k] : wb_ih[(r - GG) * DD + k];
        g_WihB[idx] = __float2bfloat16(v);
    }
    for (int idx = i0; idx < GXW * 400; idx += gs) {
        int r = idx / 400, k = idx - r * 400;
        float v = (r < GG) ? sf_ih[r * 400 + k] : sb_ih[(r - GG) * 400 + k];
        g_SihB[idx] = __float2bfloat16(v);
    }
    for (int s = i0; s < NS; s += gs) {
        int c = 0;
        for (int t = 0; t < TW; t++) c += (x[s * TW + t] != 0);
        g_slen[s] = c;
    }
}

__global__ void k_scan(const int* __restrict__ dl) {
    if (threadIdx.x == 0) {
        int a = 0;
        for (int i = 0; i < ND; i++) { g_offs[i] = a; a += dl[i]; }
    }
}

__global__ __launch_bounds__(128) void k_final(const int* __restrict__ dl,
                                               const float* __restrict__ doc_w,
                                               const float* __restrict__ doc_b,
                                               const float* __restrict__ sent_w,
                                               const float* __restrict__ sent_b,
                                               float* __restrict__ out) {
    __shared__ float d[2 * HH];
    __shared__ float redw[4];
    int doc = blockIdx.x, tid = threadIdx.x;
    int l = dl[doc];
    for (int f = tid; f < 2 * HH; f += 128)
        d[f] = g_poold[doc * 2 * HH + f];
    __syncthreads();
    for (int r = 0; r < 11; r++) {
        const float* w = (r == 0) ? doc_w : sent_w + (r - 1) * 2 * HH;
        float p = 0.f;
        for (int f = tid; f < 2 * HH; f += 128) p += d[f] * w[f];
        for (int o = 16; o; o >>= 1) p += __shfl_down_sync(0xFFFFFFFFu, p, o);
        if ((tid & 31) == 0) redw[tid >> 5] = p;
        __syncthreads();
        if (tid == 0) {
            float s = redw[0] + redw[1] + redw[2] + redw[3];
            if (r == 0) out[doc] = sigmoidf_(s + doc_b[0]);
            else if (r - 1 < l) out[ND + g_offs[doc] + (r - 1)] = sigmoidf_(s + sent_b[r - 1]);
        }
        __syncthreads();
    }
}

// ---------------- host ----------------
extern "C" void kernel_launch(void* const* d_in, const int* in_sizes, int n_in,
                              void* d_out, int out_size) {
    int base = (n_in >= 24) ? 1 : 0;
    const int*   x        = (const int*)d_in[0];
    const int*   doc_lens = (const int*)d_in[1 + base];
    const float* emb      = (const float*)d_in[2 + base];
    const float* wf_ih    = (const float*)d_in[3 + base];
    const float* wf_hh    = (const float*)d_in[4 + base];
    const float* wf_bi    = (const float*)d_in[5 + base];
    const float* wf_bh    = (const float*)d_in[6 + base];
    const float* wb_ih    = (const float*)d_in[7 + base];
    const float* wb_hh    = (const float*)d_in[8 + base];
    const float* wb_bi    = (const float*)d_in[9 + base];
    const float* wb_bh    = (const float*)d_in[10 + base];
    const float* sf_ih    = (const float*)d_in[11 + base];
    const float* sf_hh    = (const float*)d_in[12 + base];
    const float* sf_bi    = (const float*)d_in[13 + base];
    const float* sf_bh    = (const float*)d_in[14 + base];
    const float* sb_ih    = (const float*)d_in[15 + base];
    const float* sb_hh    = (const float*)d_in[16 + base];
    const float* sb_bi    = (const float*)d_in[17 + base];
    const float* sb_bh    = (const float*)d_in[18 + base];
    const float* doc_w    = (const float*)d_in[19 + base];
    const float* doc_b    = (const float*)d_in[20 + base];
    const float* sent_w   = (const float*)d_in[21 + base];
    const float* sent_b   = (const float*)d_in[22 + base];
    float* out = (float*)d_out;

    void *P, *gxs, *pool, *embB, *wihB, *sihB;
    cudaGetSymbolAddress(&P, g_P);
    cudaGetSymbolAddress(&gxs, g_gxs);
    cudaGetSymbolAddress(&pool, g_pool);
    cudaGetSymbolAddress(&embB, g_embB);
    cudaGetSymbolAddress(&wihB, g_WihB);
    cudaGetSymbolAddress(&sihB, g_SihB);

    const int SMB = (2 * 128 * 40 + 2 * 64 * 40) * 2;
    const int SMW = 205920;
    const int SMS = HH * 8 * 8 + 16 * 600 * 4 + 16 * HH * 4 + DT * 16 * 4 + 16 * 4;
    cudaFuncSetAttribute(gemm_bf16<true>,
                         cudaFuncAttributeMaxDynamicSharedMemorySize, SMB);
    cudaFuncSetAttribute(gemm_bf16<false>,
                         cudaFuncAttributeMaxDynamicSharedMemorySize, SMB);
    cudaFuncSetAttribute(gru_tc,
                         cudaFuncAttributeMaxDynamicSharedMemorySize, SMW);
    cudaFuncSetAttribute(gru_seq_s<16>,
                         cudaFuncAttributeMaxDynamicSharedMemorySize, SMS);

    k_prep<<<512, 256>>>(x, emb, wf_ih, wb_ih, sf_ih, sb_ih,
                         wf_hh, wb_hh, sf_hh, sb_hh);

    // P = embB @ WihB^T   (50000 x 1200, K=304) — bf16 mma, bf16 out
    gemm_bf16<true><<<dim3((GXW + 63) / 64, (VOC + 127) / 128), 256, SMB>>>(
        (const __nv_bfloat16*)embB, (const __nv_bfloat16*)wihB, P,
        VOC, GXW, KPE, GXW);

    // word-level BiGRU
    gru_tc<<<dim3(NS / BR_, 2), 512, SMW>>>(x, wf_bi, wf_bh, wb_bi, wb_bh);

    // sentence gates
    gemm_bf16<false><<<dim3((GXW + 63) / 64, (NS + 127) / 128), 256, SMB>>>(
        (const __nv_bfloat16*)pool, (const __nv_bfloat16*)sihB, gxs,
        NS, GXW, 400, GXW);

    // sentence-level BiGRU
    gru_seq_s<16><<<dim3(ND / 16, 2), 512, SMS>>>(
        doc_lens, sf_bi, sf_bh, sb_bi, sb_bh);

    k_scan<<<1, 32>>>(doc_lens);
    k_final<<<ND, 128>>>(doc_lens, doc_w, doc_b, sent_w, sent_b, out);
}

// round 15
// speedup vs baseline: 4.6251x; 1.0767x over previous
#include <cuda_runtime.h>
#include <cuda_bf16.h>
#include <math.h>

#define HH   200
#define DD   300
#define TW   50
#define NS   2560
#define ND   256
#define DT   10
#define GG   600
#define GXW  1200
#define VOC  50000
#define KPE  304

// word-level tensor-core GRU geometry
#define MT_   38
#define KT_   13
#define NT_   5
#define BR_   40
#define KPAD  232
#define GPAD  620    // conflict-free G stores (bcol*620 strides hit distinct banks)

// ---------------- device scratch ----------------
__device__ __nv_bfloat16 g_P[VOC * GXW];
__device__ __nv_bfloat16 g_embB[VOC * KPE];
__device__ __nv_bfloat16 g_WihB[GXW * KPE];
__device__ __nv_bfloat16 g_SihB[GXW * 400];
__device__ __nv_bfloat16 g_pool[NS * 2 * HH];
__device__ float g_gxs[NS * GXW];
__device__ __align__(16) float4 g_wP[2][HH * HH];
__device__ __align__(16) unsigned int g_Wf[2][MT_ * KT_ * 32 * 4];
__device__ float g_poold[ND * 2 * HH];
__device__ int   g_slen[NS];
__device__ int   g_offs[ND];

// ---------------- helpers ----------------
typedef unsigned long long ull;
__device__ __forceinline__ ull pack1(float a) {
    ull r; asm("mov.b64 %0, {%1, %1};" : "=l"(r) : "f"(a)); return r;
}
__device__ __forceinline__ void fma2(ull& d, ull a, ull b) {
    asm("fma.rn.f32x2 %0, %1, %2, %0;" : "+l"(d) : "l"(a), "l"(b));
}
__device__ __forceinline__ void unpack2(ull v, float& a, float& b) {
    asm("mov.b64 {%0, %1}, %2;" : "=f"(a), "=f"(b) : "l"(v));
}
__device__ __forceinline__ float tanha_(float x) {
    float y; asm("tanh.approx.f32 %0, %1;" : "=f"(y) : "f"(x)); return y;
}
__device__ __forceinline__ float sigmoidf_(float x) {
    return fmaf(0.5f, tanha_(0.5f * x), 0.5f);
}
__device__ __forceinline__ void mma_bf16(float* c, uint4 a,
                                         unsigned int b0, unsigned int b1) {
    asm volatile(
        "mma.sync.aligned.m16n8k16.row.col.f32.bf16.bf16.f32 "
        "{%0,%1,%2,%3}, {%4,%5,%6,%7}, {%8,%9}, {%0,%1,%2,%3};"
        : "+f"(c[0]), "+f"(c[1]), "+f"(c[2]), "+f"(c[3])
        : "r"(a.x), "r"(a.y), "r"(a.z), "r"(a.w), "r"(b0), "r"(b1));
}
__device__ __forceinline__ void cpa16(void* dst, const void* src, int sz) {
    unsigned int d = (unsigned int)__cvta_generic_to_shared(dst);
    asm volatile("cp.async.cg.shared.global [%0], [%1], 16, %2;"
                 :: "r"(d), "l"(src), "r"(sz));
}

// -------- bf16 tensor-core GEMM (double-buffered cp.async) --------
template <bool BF16OUT>
__global__ __launch_bounds__(256) void gemm_bf16(
    const __nv_bfloat16* __restrict__ A, const __nv_bfloat16* __restrict__ B,
    void* __restrict__ Cv, int M, int N, int KP, int ldc) {
    extern __shared__ __align__(16) __nv_bfloat16 smh[];
    __nv_bfloat16* As = smh;
    __nv_bfloat16* Bs = smh + 2 * 128 * 40;
    int tid = threadIdx.x;
    int mb = blockIdx.y * 128, nb = blockIdx.x * 64;
    int warp = tid >> 5, lane = tid & 31;
    int wm = warp & 3, wn = warp >> 2;
    int gid = lane >> 2, tig = lane & 3;

    float c[2][4][4];
#pragma unroll
    for (int mt = 0; mt < 2; mt++)
#pragma unroll
        for (int nt = 0; nt < 4; nt++)
#pragma unroll
            for (int i = 0; i < 4; i++) c[mt][nt][i] = 0.f;

    int nk = (KP + 31) / 32;

    auto load_chunk = [&](int i, int buf) {
#pragma unroll
        for (int l = 0; l < 2; l++) {
            int cch = tid + l * 256;
            int row = cch >> 2, seg = cch & 3;
            int col = i * 32 + seg * 8;
            int gm = mb + row;
            int sz = (gm < M && col < KP) ? 16 : 0;
            if (gm >= M) gm = M - 1;
            int cc = (col < KP) ? col : 0;
            cpa16(&As[buf * 128 * 40 + row * 40 + seg * 8],
                  &A[(size_t)gm * KP + cc], sz);
        }
        {
            int row = tid >> 2, seg = tid & 3;
            int col = i * 32 + seg * 8;
            int gn = nb + row;
            int sz = (gn < N && col < KP) ? 16 : 0;
            if (gn >= N) gn = N - 1;
            int cc = (col < KP) ? col : 0;
            cpa16(&Bs[buf * 64 * 40 + row * 40 + seg * 8],
                  &B[(size_t)gn * KP + cc], sz);
        }
        asm volatile("cp.async.commit_group;");
    };

    load_chunk(0, 0);
    for (int i = 0; i < nk; i++) {
        if (i + 1 < nk) {
            load_chunk(i + 1, (i + 1) & 1);
            asm volatile("cp.async.wait_group 1;");
        } else {
            asm volatile("cp.async.wait_group 0;");
        }
        __syncthreads();
        const __nv_bfloat16* Ab = As + (i & 1) * 128 * 40;
        const __nv_bfloat16* Bb = Bs + (i & 1) * 64 * 40;
#pragma unroll
        for (int kc = 0; kc < 2; kc++) {
            int kk = kc * 16 + 2 * tig;
            uint4 af[2];
#pragma unroll
            for (int mt = 0; mt < 2; mt++) {
                int mr = wm * 32 + mt * 16;
                af[mt].x = *(const unsigned int*)&Ab[(mr + gid) * 40 + kk];
                af[mt].y = *(const unsigned int*)&Ab[(mr + gid + 8) * 40 + kk];
                af[mt].z = *(const unsigned int*)&Ab[(mr + gid) * 40 + kk + 8];
                af[mt].w = *(const unsigned int*)&Ab[(mr + gid + 8) * 40 + kk + 8];
            }
            unsigned int bf[4][2];
#pragma unroll
            for (int nt = 0; nt < 4; nt++) {
                int nc = wn * 32 + nt * 8;
                bf[nt][0] = *(const unsigned int*)&Bb[(nc + gid) * 40 + kk];
                bf[nt][1] = *(const unsigned int*)&Bb[(nc + gid) * 40 + kk + 8];
            }
#pragma unroll
            for (int mt = 0; mt < 2; mt++)
#pragma unroll
                for (int nt = 0; nt < 4; nt++)
                    mma_bf16(c[mt][nt], af[mt], bf[nt][0], bf[nt][1]);
        }
        __syncthreads();
    }
#pragma unroll
    for (int mt = 0; mt < 2; mt++)
#pragma unroll
        for (int nt = 0; nt < 4; nt++) {
            int row0 = mb + wm * 32 + mt * 16 + gid;
            int col0 = nb + wn * 32 + nt * 8 + tig * 2;
            if (col0 < N) {
                if (BF16OUT) {
                    __nv_bfloat16* C = (__nv_bfloat16*)Cv;
                    if (row0 < M)
                        *(__nv_bfloat162*)&C[(size_t)row0 * ldc + col0] =
                            __float22bfloat162_rn(
                                make_float2(c[mt][nt][0], c[mt][nt][1]));
                    if (row0 + 8 < M)
                        *(__nv_bfloat162*)&C[(size_t)(row0 + 8) * ldc + col0] =
                            __float22bfloat162_rn(
                                make_float2(c[mt][nt][2], c[mt][nt][3]));
                } else {
                    float* C = (float*)Cv;
                    if (row0 < M)
                        *(float2*)&C[(size_t)row0 * ldc + col0] =
                            make_float2(c[mt][nt][0], c[mt][nt][1]);
                    if (row0 + 8 < M)
                        *(float2*)&C[(size_t)(row0 + 8) * ldc + col0] =
                            make_float2(c[mt][nt][2], c[mt][nt][3]);
                }
            }
        }
}

// ---------------- word-level persistent GRU on tensor cores ----------------
// smem (bytes): G @0: 40*GPAD*4=99,200 | HbHi @99,200: 18,560 |
//               gxS @117,760: 48,640 | gxb @166,400: 8,000 | sln @174,400: 160
//               total = 174,560
__global__ __launch_bounds__(512, 1) void gru_tc(
    const int* __restrict__ toks,
    const float* __restrict__ bi_f, const float* __restrict__ bh_f,
    const float* __restrict__ bi_b, const float* __restrict__ bh_b) {
    extern __shared__ __align__(16) char sm_[];
    float* G = (float*)sm_;
    __nv_bfloat16* HbHi = (__nv_bfloat16*)(sm_ + 99200);
    __nv_bfloat16* gxS = (__nv_bfloat16*)(sm_ + 117760);
    int* gxb = (int*)(sm_ + 166400);
    int* sln = (int*)(sm_ + 174400);

    int dir = blockIdx.y;
    int b0 = blockIdx.x * BR_;
    const unsigned int* wdir = g_Wf[dir];
    const float* bi = dir ? bi_b : bi_f;
    const float* bh = dir ? bh_b : bh_f;
    int tid = threadIdx.x;
    int warp = tid >> 5, lane = tid & 31;
    int gid = lane >> 2, tig = lane & 3;

    for (int idx = tid; idx < 40 * KPAD / 2; idx += 512)
        ((unsigned int*)HbHi)[idx] = 0u;
    for (int idx = tid; idx < TW * BR_; idx += 512) {
        int t = idx / BR_, b = idx % BR_;
        int tt = dir ? (TW - 1 - t) : t;
        int row = toks[(b0 + b) * TW + tt];
        gxb[idx] = row * GXW + dir * GG;
    }
    if (tid < BR_) sln[tid] = g_slen[b0 + tid];
    __syncthreads();

    int ej = tid < 400 ? (tid % 200) : 0;
    int ehalf = tid < 400 ? (tid / 200) : 0;
    float br = 0, bz = 0, bin = 0, bhn = 0;
    if (tid < 400) {
        br = bi[ej] + bh[ej];
        bz = bi[HH + ej] + bh[HH + ej];
        bin = bi[2 * HH + ej];
        bhn = bh[2 * HH + ej];
    }
    float pool_r[20], h_r[20];
#pragma unroll
    for (int i = 0; i < 20; i++) { pool_r[i] = 0.f; h_r[i] = 0.f; }

    // m-tile assignment: pass1 all warps mt={warp, warp+16};
    // pass2 warps 0..5 mt=32+warp.
    const unsigned int* wfb0 = wdir + (size_t)warp * KT_ * 32 * 4;
    const unsigned int* wfb1 = wdir + (size_t)(warp + 16) * KT_ * 32 * 4;
    const unsigned int* wfb2 = (warp < 6)
        ? wdir + (size_t)(warp + 32) * KT_ * 32 * 4 : wdir;

    for (int t = 0; t < TW; t++) {
        int tt = dir ? (TW - 1 - t) : t;
        // ---- stage gx rows (bf16) into smem; overlaps the mma phase ----
        {
            const int* gq = gxb + t * BR_;
            for (int ci = tid; ci < BR_ * 75; ci += 512) {
                int b = ci / 75, off = (ci % 75) * 8;
                cpa16(gxS + b * 608 + off, g_P + gq[b] + off, 16);
            }
            asm volatile("cp.async.commit_group;");
        }
        // ---- pass 1: 2 m-tiles per warp, B-fragments loaded once ----
        {
            float c[2][NT_][4];
#pragma unroll
            for (int q = 0; q < 2; q++)
#pragma unroll
                for (int nt = 0; nt < NT_; nt++)
#pragma unroll
                    for (int i = 0; i < 4; i++) c[q][nt][i] = 0.f;
            uint4 a0c = *(const uint4*)(wfb0 + (size_t)lane * 4);
            uint4 a1c = *(const uint4*)(wfb1 + (size_t)lane * 4);
#pragma unroll
            for (int kt = 0; kt < KT_; kt++) {
                uint4 a0n, a1n;
                if (kt + 1 < KT_) {
                    a0n = *(const uint4*)(wfb0 + ((size_t)(kt + 1) * 32 + lane) * 4);
                    a1n = *(const uint4*)(wfb1 + ((size_t)(kt + 1) * 32 + lane) * 4);
                }
                int koff = kt * 16 + tig * 2;
#pragma unroll
                for (int nt = 0; nt < NT_; nt++) {
                    int n = nt * 8 + gid;
                    unsigned int bh0 = *(const unsigned int*)&HbHi[n * KPAD + koff];
                    unsigned int bh1 = *(const unsigned int*)&HbHi[n * KPAD + koff + 8];
                    mma_bf16(c[0][nt], a0c, bh0, bh1);
                    mma_bf16(c[1][nt], a1c, bh0, bh1);
                }
                a0c = a0n; a1c = a1n;
            }
#pragma unroll
            for (int q = 0; q < 2; q++) {
                int m = (warp + q * 16) * 16 + gid;
#pragma unroll
                for (int nt = 0; nt < NT_; nt++) {
                    int bcol = nt * 8 + tig * 2;
                    G[bcol * GPAD + m] = c[q][nt][0];
                    G[(bcol + 1) * GPAD + m] = c[q][nt][1];
                    G[bcol * GPAD + m + 8] = c[q][nt][2];
                    G[(bcol + 1) * GPAD + m + 8] = c[q][nt][3];
                }
            }
        }
        // ---- pass 2: leftover 6 m-tiles (warps 0..5) ----
        if (warp < 6) {
            float d[NT_][4];
#pragma unroll
            for (int nt = 0; nt < NT_; nt++)
#pragma unroll
                for (int i = 0; i < 4; i++) d[nt][i] = 0.f;
#pragma unroll
            for (int kt = 0; kt < KT_; kt++) {
                uint4 a2 = *(const uint4*)(wfb2 + ((size_t)kt * 32 + lane) * 4);
                int koff = kt * 16 + tig * 2;
#pragma unroll
                for (int nt = 0; nt < NT_; nt++) {
                    int n = nt * 8 + gid;
                    unsigned int bh0 = *(const unsigned int*)&HbHi[n * KPAD + koff];
                    unsigned int bh1 = *(const unsigned int*)&HbHi[n * KPAD + koff + 8];
                    mma_bf16(d[nt], a2, bh0, bh1);
                }
            }
            int m = (warp + 32) * 16 + gid;
#pragma unroll
            for (int nt = 0; nt < NT_; nt++) {
                int bcol = nt * 8 + tig * 2;
                G[bcol * GPAD + m] = d[nt][0];
                G[(bcol + 1) * GPAD + m] = d[nt][1];
                G[bcol * GPAD + m + 8] = d[nt][2];
                G[(bcol + 1) * GPAD + m + 8] = d[nt][3];
            }
        }
        asm volatile("cp.async.wait_group 0;");
        __syncthreads();
        // ---- epilogue: gates, pool, H update (H in registers) ----
        if (tid < 400) {
#pragma unroll 4
            for (int i = 0; i < 20; i++) {
                int b = ehalf * 20 + i;
                float gxr = __bfloat162float(gxS[b * 608 + ej]);
                float gxz = __bfloat162float(gxS[b * 608 + 200 + ej]);
                float gxn = __bfloat162float(gxS[b * 608 + 400 + ej]);
                float gr = G[b * GPAD + ej];
                float gz = G[b * GPAD + ej + 200];
                float gn = G[b * GPAD + ej + 400];
                float r = sigmoidf_(gxr + gr + br);
                float z = sigmoidf_(gxz + gz + bz);
                float nn = tanha_(gxn + bin + r * (gn + bhn));
                float hnew = (1.f - z) * nn + z * h_r[i];
                h_r[i] = hnew;
                if (tt < sln[b]) pool_r[i] += hnew;
                HbHi[b * KPAD + ej] = __float2bfloat16(hnew);
            }
        }
        __syncthreads();
    }

    if (tid < 400) {
#pragma unroll
        for (int i = 0; i < 20; i++) {
            int b = ehalf * 20 + i;
            int l = sln[b];
            float v = l ? pool_r[i] / (float)l : 0.f;
            g_pool[(size_t)(b0 + b) * (2 * HH) + (size_t)dir * HH + ej] =
                __float2bfloat16(v);
        }
    }
}

// ---------------- sentence-level persistent GRU (fp32) ----------
template <int BROWS>
__global__ __launch_bounds__(512, 1) void gru_seq_s(
    const int* __restrict__ dlens,
    const float* __restrict__ bi_f, const float* __restrict__ bh_f,
    const float* __restrict__ bi_b, const float* __restrict__ bh_b) {
    constexpr int PW = BROWS / 2;
    constexpr int BP = PW / 2;
    constexpr int HR = BROWS / 2;
    constexpr int CH = HR * 150;
    constexpr int TLEN = DT;

    extern __shared__ __align__(16) char sm_[];
    float2* hsT   = (float2*)sm_;
    float*  gxs_  = (float*)(sm_ + HH * PW * 8);
    float* pool_s = (float*)(sm_ + HH * PW * 8 + BROWS * 600 * 4);
    int* gxb = (int*)(sm_ + HH * PW * 8 + BROWS * 600 * 4 + BROWS * HH * 4);
    int* sln = gxb + TLEN * BROWS;

    int dir = blockIdx.y;
    int b0 = blockIdx.x * BROWS;
    const float4* wP = g_wP[dir];
    const float* bi = dir ? bi_b : bi_f;
    const float* bh = dir ? bh_b : bh_f;
    int tid = threadIdx.x;
    int half = tid >> 8;
    int j = tid & 255;
    int pbase = half * BP;

    for (int idx = tid; idx < HH * PW; idx += 512) hsT[idx] = make_float2(0.f, 0.f);
    for (int idx = tid; idx < BROWS * HH; idx += 512) pool_s[idx] = 0.f;
    for (int idx = tid; idx < TLEN * BROWS; idx += 512) {
        int t = idx / BROWS, b = idx % BROWS;
        int tt = dir ? (TLEN - 1 - t) : t;
        int row = (b0 + b) * TLEN + tt;
        gxb[idx] = row * GXW + dir * GG;
    }
    if (tid < BROWS) sln[tid] = dlens[b0 + tid];
    __syncthreads();

    float br = 0, bz = 0, bin = 0, bhn = 0;
    if (j < HH) {
        br = bi[j] + bh[j];
        bz = bi[HH + j] + bh[HH + j];
        bin = bi[2 * HH + j];
        bhn = bh[2 * HH + j];
    }

    for (int t = 0; t < TLEN; t++) {
        int tt = dir ? (TLEN - 1 - t) : t;
        {
            const int* gq = gxb + t * BROWS;
#pragma unroll 2
            for (int c = j; c < CH; c += 256) {
                int b = half * HR + c / 150;
                int off = (c % 150) * 4;
                cpa16(gxs_ + b * 600 + off, g_gxs + gq[b] + off, 16);
            }
            asm volatile("cp.async.commit_group;");
        }
        ull aR[BP], aZ[BP], aN[BP];
        if (j < HH) {
#pragma unroll
            for (int p = 0; p < BP; p++) { aR[p] = 0; aZ[p] = 0; aN[p] = 0; }
            const float4* wp = wP + j;
            float4 ra[4];
#pragma unroll
            for (int i = 0; i < 4; i++) ra[i] = wp[i * HH];
#pragma unroll 4
            for (int k = 0; k < HH; k++) {
                float4 wc = ra[k & 3];
                int kp = k + 4;
                if (kp < HH) ra[k & 3] = wp[kp * HH];
                ull w0 = pack1(wc.x), w1 = pack1(wc.y), w2 = pack1(wc.z);
#pragma unroll
                for (int q = 0; q < BP / 2; q++) {
                    ulonglong2 hq =
                        *(const ulonglong2*)&hsT[k * PW + pbase + 2 * q];
                    fma2(aR[2 * q], hq.x, w0);
                    fma2(aZ[2 * q], hq.x, w1);
                    fma2(aN[2 * q], hq.x, w2);
                    fma2(aR[2 * q + 1], hq.y, w0);
                    fma2(aZ[2 * q + 1], hq.y, w1);
                    fma2(aN[2 * q + 1], hq.y, w2);
                }
            }
        }
        asm volatile("cp.async.wait_group 0;");
        asm volatile("bar.sync %0, 256;" :: "r"(1 + half) : "memory");
        if (j < HH) {
#pragma unroll
            for (int p = 0; p < BP; p++) {
                int gp = pbase + p;
                float hr[2], hz[2], hn[2], hnew[2];
                unpack2(aR[p], hr[0], hr[1]);
                unpack2(aZ[p], hz[0], hz[1]);
                unpack2(aN[p], hn[0], hn[1]);
                float2 hold = hsT[j * PW + gp];
#pragma unroll
                for (int l = 0; l < 2; l++) {
                    int b = 2 * gp + l;
                    const float* gx = gxs_ + b * 600;
                    float r = sigmoidf_(gx[j] + hr[l] + br);
                    float z = sigmoidf_(gx[HH + j] + hz[l] + bz);
                    float nn = tanha_(gx[2 * HH + j] + bin + r * (hn[l] + bhn));
                    float ho = l ? hold.y : hold.x;
                    hnew[l] = (1.f - z) * nn + z * ho;
                    if (tt < sln[b]) pool_s[b * HH + j] += hnew[l];
                }
                hsT[j * PW + gp] = make_float2(hnew[0], hnew[1]);
            }
        }
        asm volatile("bar.sync %0, 256;" :: "r"(1 + half) : "memory");
    }

    if (j < HH) {
#pragma unroll
        for (int p = 0; p < BP; p++) {
#pragma unroll
            for (int l = 0; l < 2; l++) {
                int b = 2 * (pbase + p) + l;
                int ln = sln[b];
                float v = pool_s[b * HH + j];
                g_poold[(size_t)(b0 + b) * (2 * HH) + (size_t)dir * HH + j] =
                    ln ? v / (float)ln : 0.f;
            }
        }
    }
}

// ---------------- prep ----------------
__global__ void k_prep(const int* __restrict__ x, const float* __restrict__ emb,
                       const float* __restrict__ wf_ih, const float* __restrict__ wb_ih,
                       const float* __restrict__ sf_ih, const float* __restrict__ sb_ih,
                       const float* __restrict__ wf_hh, const float* __restrict__ wb_hh,
                       const float* __restrict__ sf_hh, const float* __restrict__ sb_hh) {
    int i0 = blockIdx.x * blockDim.x + threadIdx.x;
    int gs = gridDim.x * blockDim.x;
    const float* wss[2] = {sf_hh, sb_hh};
    for (int idx = i0; idx < HH * HH; idx += gs) {
        int k = idx / HH, j = idx % HH;
#pragma unroll
        for (int a = 0; a < 2; a++) {
            g_wP[a][idx] = make_float4(wss[a][j * HH + k],
                                       wss[a][(HH + j) * HH + k],
                                       wss[a][(2 * HH + j) * HH + k], 0.f);
        }
    }
    const float* wsw[2] = {wf_hh, wb_hh};
    const int TOT = 2 * MT_ * KT_ * 32 * 4;
    for (int idx = i0; idx < TOT; idx += gs) {
        int rr = idx & 3;
        int lane = (idx >> 2) & 31;
        int kt = (idx >> 7) % KT_;
        int mt = (idx / (KT_ * 32 * 4)) % MT_;
        int a = idx / (MT_ * KT_ * 32 * 4);
        int gid = lane >> 2, tig = lane & 3;
        int row = mt * 16 + gid + (rr & 1) * 8;
        int k0 = kt * 16 + tig * 2 + ((rr >> 1) & 1) * 8;
        float w0 = (row < GG && k0 < HH) ? wsw[a][row * HH + k0] : 0.f;
        float w1 = (row < GG && k0 + 1 < HH) ? wsw[a][row * HH + k0 + 1] : 0.f;
        __nv_bfloat16 h0 = __float2bfloat16(w0);
        __nv_bfloat16 h1 = __float2bfloat16(w1);
        unsigned int hiw = ((unsigned int)__bfloat16_as_ushort(h1) << 16) |
                           (unsigned int)__bfloat16_as_ushort(h0);
        g_Wf[a][(((size_t)mt * KT_ + kt) * 32 + lane) * 4 + rr] = hiw;
    }
    for (int idx = i0; idx < VOC * KPE; idx += gs) {
        int r = idx / KPE, k = idx - r * KPE;
        g_embB[idx] = __float2bfloat16(k < DD ? emb[r * DD + k] : 0.f);
    }
    for (int idx = i0; idx < GXW * KPE; idx += gs) {
        int r = idx / KPE, k = idx - r * KPE;
        float v = 0.f;
        if (k < DD) v = (r < GG) ? wf_ih[r * DD + k] : wb_ih[(r - GG) * DD + k];
        g_WihB[idx] = __float2bfloat16(v);
    }
    for (int idx = i0; idx < GXW * 400; idx += gs) {
        int r = idx / 400, k = idx - r * 400;
        float v = (r < GG) ? sf_ih[r * 400 + k] : sb_ih[(r - GG) * 400 + k];
        g_SihB[idx] = __float2bfloat16(v);
    }
    for (int s = i0; s < NS; s += gs) {
        int c = 0;
        for (int t = 0; t < TW; t++) c += (x[s * TW + t] != 0);
        g_slen[s] = c;
    }
}

__global__ void k_scan(const int* __restrict__ dl) {
    if (threadIdx.x == 0) {
        int a = 0;
        for (int i = 0; i < ND; i++) { g_offs[i] = a; a += dl[i]; }
    }
}

__global__ __launch_bounds__(128) void k_final(const int* __restrict__ dl,
                                               const float* __restrict__ doc_w,
                                               const float* __restrict__ doc_b,
                                               const float* __restrict__ sent_w,
                                               const float* __restrict__ sent_b,
                                               float* __restrict__ out) {
    __shared__ float d[2 * HH];
    __shared__ float redw[4];
    int doc = blockIdx.x, tid = threadIdx.x;
    int l = dl[doc];
    for (int f = tid; f < 2 * HH; f += 128)
        d[f] = g_poold[doc * 2 * HH + f];
    __syncthreads();
    for (int r = 0; r < 11; r++) {
        const float* w = (r == 0) ? doc_w : sent_w + (r - 1) * 2 * HH;
        float p = 0.f;
        for (int f = tid; f < 2 * HH; f += 128) p += d[f] * w[f];
        for (int o = 16; o; o >>= 1) p += __shfl_down_sync(0xFFFFFFFFu, p, o);
        if ((tid & 31) == 0) redw[tid >> 5] = p;
        __syncthreads();
        if (tid == 0) {
            float s = redw[0] + redw[1] + redw[2] + redw[3];
            if (r == 0) out[doc] = sigmoidf_(s + doc_b[0]);
            else if (r - 1 < l) out[ND + g_offs[doc] + (r - 1)] = sigmoidf_(s + sent_b[r - 1]);
        }
        __syncthreads();
    }
}

// ---------------- host ----------------
extern "C" void kernel_launch(void* const* d_in, const int* in_sizes, int n_in,
                              void* d_out, int out_size) {
    int base = (n_in >= 24) ? 1 : 0;
    const int*   x        = (const int*)d_in[0];
    const int*   doc_lens = (const int*)d_in[1 + base];
    const float* emb      = (const float*)d_in[2 + base];
    const float* wf_ih    = (const float*)d_in[3 + base];
    const float* wf_hh    = (const float*)d_in[4 + base];
    const float* wf_bi    = (const float*)d_in[5 + base];
    const float* wf_bh    = (const float*)d_in[6 + base];
    const float* wb_ih    = (const float*)d_in[7 + base];
    const float* wb_hh    = (const float*)d_in[8 + base];
    const float* wb_bi    = (const float*)d_in[9 + base];
    const float* wb_bh    = (const float*)d_in[10 + base];
    const float* sf_ih    = (const float*)d_in[11 + base];
    const float* sf_hh    = (const float*)d_in[12 + base];
    const float* sf_bi    = (const float*)d_in[13 + base];
    const float* sf_bh    = (const float*)d_in[14 + base];
    const float* sb_ih    = (const float*)d_in[15 + base];
    const float* sb_hh    = (const float*)d_in[16 + base];
    const float* sb_bi    = (const float*)d_in[17 + base];
    const float* sb_bh    = (const float*)d_in[18 + base];
    const float* doc_w    = (const float*)d_in[19 + base];
    const float* doc_b    = (const float*)d_in[20 + base];
    const float* sent_w   = (const float*)d_in[21 + base];
    const float* sent_b   = (const float*)d_in[22 + base];
    float* out = (float*)d_out;

    void *P, *gxs, *pool, *embB, *wihB, *sihB;
    cudaGetSymbolAddress(&P, g_P);
    cudaGetSymbolAddress(&gxs, g_gxs);
    cudaGetSymbolAddress(&pool, g_pool);
    cudaGetSymbolAddress(&embB, g_embB);
    cudaGetSymbolAddress(&wihB, g_WihB);
    cudaGetSymbolAddress(&sihB, g_SihB);

    const int SMB = (2 * 128 * 40 + 2 * 64 * 40) * 2;
    const int SMW = 174560;
    const int SMS = HH * 8 * 8 + 16 * 600 * 4 + 16 * HH * 4 + DT * 16 * 4 + 16 * 4;
    cudaFuncSetAttribute(gemm_bf16<true>,
                         cudaFuncAttributeMaxDynamicSharedMemorySize, SMB);
    cudaFuncSetAttribute(gemm_bf16<false>,
                         cudaFuncAttributeMaxDynamicSharedMemorySize, SMB);
    cudaFuncSetAttribute(gru_tc,
                         cudaFuncAttributeMaxDynamicSharedMemorySize, SMW);
    cudaFuncSetAttribute(gru_seq_s<16>,
                         cudaFuncAttributeMaxDynamicSharedMemorySize, SMS);

    k_prep<<<512, 256>>>(x, emb, wf_ih, wb_ih, sf_ih, sb_ih,
                         wf_hh, wb_hh, sf_hh, sb_hh);

    // P = embB @ WihB^T   (50000 x 1200, K=304) — bf16 mma, bf16 out
    gemm_bf16<true><<<dim3((GXW + 63) / 64, (VOC + 127) / 128), 256, SMB>>>(
        (const __nv_bfloat16*)embB, (const __nv_bfloat16*)wihB, P,
        VOC, GXW, KPE, GXW);

    // word-level BiGRU
    gru_tc<<<dim3(NS / BR_, 2), 512, SMW>>>(x, wf_bi, wf_bh, wb_bi, wb_bh);

    // sentence gates
    gemm_bf16<false><<<dim3((GXW + 63) / 64, (NS + 127) / 128), 256, SMB>>>(
        (const __nv_bfloat16*)pool, (const __nv_bfloat16*)sihB, gxs,
        NS, GXW, 400, GXW);

    // sentence-level BiGRU
    gru_seq_s<16><<<dim3(ND / 16, 2), 512, SMS>>>(
        doc_lens, sf_bi, sf_bh, sb_bi, sb_bh);

    k_scan<<<1, 32>>>(doc_lens);
    k_final<<<ND, 128>>>(doc_lens, doc_w, doc_b, sent_w, sent_b, out);
}

// round 16
// speedup vs baseline: 4.7836x; 1.0343x over previous
#include <cuda_runtime.h>
#include <cuda_bf16.h>
#include <math.h>

#define HH   200
#define DD   300
#define TW   50
#define NS   2560
#define ND   256
#define DT   10
#define GG   600
#define GXW  1200
#define VOC  50000
#define KPE  304
#define SA   328    // smem row stride (bf16) for strip GEMM: conflict-free

// word-level tensor-core GRU geometry
#define MT_   38
#define KT_   13
#define NT_   5
#define BR_   40
#define KPAD  232
#define GPAD  620

// ---------------- device scratch ----------------
__device__ __nv_bfloat16 g_P[VOC * GXW];
__device__ __nv_bfloat16 g_embB[VOC * KPE];
__device__ __nv_bfloat16 g_WihB[GXW * KPE];
__device__ __nv_bfloat16 g_SihB[GXW * 400];
__device__ __nv_bfloat16 g_pool[NS * 2 * HH];
__device__ float g_gxs[NS * GXW];
__device__ __align__(16) float4 g_wP[2][HH * HH];
__device__ __align__(16) unsigned int g_Wf[2][MT_ * KT_ * 32 * 4];
__device__ float g_poold[ND * 2 * HH];
__device__ int   g_slen[NS];
__device__ int   g_offs[ND];

// ---------------- helpers ----------------
typedef unsigned long long ull;
__device__ __forceinline__ ull pack1(float a) {
    ull r; asm("mov.b64 %0, {%1, %1};" : "=l"(r) : "f"(a)); return r;
}
__device__ __forceinline__ void fma2(ull& d, ull a, ull b) {
    asm("fma.rn.f32x2 %0, %1, %2, %0;" : "+l"(d) : "l"(a), "l"(b));
}
__device__ __forceinline__ void unpack2(ull v, float& a, float& b) {
    asm("mov.b64 {%0, %1}, %2;" : "=f"(a), "=f"(b) : "l"(v));
}
__device__ __forceinline__ float tanha_(float x) {
    float y; asm("tanh.approx.f32 %0, %1;" : "=f"(y) : "f"(x)); return y;
}
__device__ __forceinline__ float sigmoidf_(float x) {
    return fmaf(0.5f, tanha_(0.5f * x), 0.5f);
}
__device__ __forceinline__ void mma_bf16(float* c, uint4 a,
                                         unsigned int b0, unsigned int b1) {
    asm volatile(
        "mma.sync.aligned.m16n8k16.row.col.f32.bf16.bf16.f32 "
        "{%0,%1,%2,%3}, {%4,%5,%6,%7}, {%8,%9}, {%0,%1,%2,%3};"
        : "+f"(c[0]), "+f"(c[1]), "+f"(c[2]), "+f"(c[3])
        : "r"(a.x), "r"(a.y), "r"(a.z), "r"(a.w), "r"(b0), "r"(b1));
}
__device__ __forceinline__ void cpa16(void* dst, const void* src, int sz) {
    unsigned int d = (unsigned int)__cvta_generic_to_shared(dst);
    asm volatile("cp.async.cg.shared.global [%0], [%1], 16, %2;"
                 :: "r"(d), "l"(src), "r"(sz));
}

// -------- strip GEMM for P: C[M,1200] = A[M,304] @ B[1200,304]^T (bf16) -----
// grid = M/128 strips. A strip staged once in smem; B in 64-wide double-
// buffered chunks. 8 warps, warp tile 32m x 32n (4m x 2n grid).
__global__ __launch_bounds__(256) void gemm_strip(
    const __nv_bfloat16* __restrict__ A, const __nv_bfloat16* __restrict__ B,
    __nv_bfloat16* __restrict__ C, int M) {
    extern __shared__ __align__(16) __nv_bfloat16 smh[];
    __nv_bfloat16* As = smh;                  // [128][SA]
    __nv_bfloat16* Bs = smh + 128 * SA;       // [2][64][SA]
    const int NC = (GXW + 63) / 64;           // 19
    int tid = threadIdx.x;
    int mb = blockIdx.x * 128;
    int warp = tid >> 5, lane = tid & 31;
    int wm = warp & 3, wn = warp >> 2;
    int gid = lane >> 2, tig = lane & 3;

    // stage A strip (once)
    for (int idx = tid; idx < 128 * 38; idx += 256) {
        int row = idx / 38, seg = idx % 38;
        int gm = mb + row;
        int sz = (gm < M) ? 16 : 0;
        if (gm >= M) gm = M - 1;
        cpa16(&As[row * SA + seg * 8], &A[(size_t)gm * KPE + seg * 8], sz);
    }
    asm volatile("cp.async.commit_group;");

    auto stageB = [&](int nc, int buf) {
        for (int idx = tid; idx < 64 * 38; idx += 256) {
            int row = idx / 38, seg = idx % 38;
            int gn = nc * 64 + row;
            int sz = (gn < GXW) ? 16 : 0;
            if (gn >= GXW) gn = GXW - 1;
            cpa16(&Bs[buf * 64 * SA + row * SA + seg * 8],
                  &B[(size_t)gn * KPE + seg * 8], sz);
        }
        asm volatile("cp.async.commit_group;");
    };

    stageB(0, 0);
    for (int nc = 0; nc < NC; nc++) {
        __syncthreads();   // done reading buf (nc+1)&1 from compute nc-1
        if (nc + 1 < NC) {
            stageB(nc + 1, (nc + 1) & 1);
            asm volatile("cp.async.wait_group 1;");
        } else {
            asm volatile("cp.async.wait_group 0;");
        }
        __syncthreads();
        const __nv_bfloat16* Bb = Bs + (nc & 1) * 64 * SA;

        float c[2][4][4];
#pragma unroll
        for (int mt = 0; mt < 2; mt++)
#pragma unroll
            for (int nt = 0; nt < 4; nt++)
#pragma unroll
                for (int i = 0; i < 4; i++) c[mt][nt][i] = 0.f;

#pragma unroll 4
        for (int kt = 0; kt < 19; kt++) {
            int kk = kt * 16 + 2 * tig;
            uint4 af[2];
#pragma unroll
            for (int mt = 0; mt < 2; mt++) {
                int mr = wm * 32 + mt * 16;
                af[mt].x = *(const unsigned int*)&As[(mr + gid) * SA + kk];
                af[mt].y = *(const unsigned int*)&As[(mr + gid + 8) * SA + kk];
                af[mt].z = *(const unsigned int*)&As[(mr + gid) * SA + kk + 8];
                af[mt].w = *(const unsigned int*)&As[(mr + gid + 8) * SA + kk + 8];
            }
#pragma unroll
            for (int nt = 0; nt < 4; nt++) {
                int nr = wn * 32 + nt * 8 + gid;
                unsigned int b0 = *(const unsigned int*)&Bb[nr * SA + kk];
                unsigned int b1 = *(const unsigned int*)&Bb[nr * SA + kk + 8];
                mma_bf16(c[0][nt], af[0], b0, b1);
                mma_bf16(c[1][nt], af[1], b0, b1);
            }
        }
        // store this n-chunk
#pragma unroll
        for (int mt = 0; mt < 2; mt++)
#pragma unroll
            for (int nt = 0; nt < 4; nt++) {
                int row0 = mb + wm * 32 + mt * 16 + gid;
                int col0 = nc * 64 + wn * 32 + nt * 8 + tig * 2;
                if (col0 < GXW) {
                    if (row0 < M)
                        *(__nv_bfloat162*)&C[(size_t)row0 * GXW + col0] =
                            __float22bfloat162_rn(
                                make_float2(c[mt][nt][0], c[mt][nt][1]));
                    if (row0 + 8 < M)
                        *(__nv_bfloat162*)&C[(size_t)(row0 + 8) * GXW + col0] =
                            __float22bfloat162_rn(
                                make_float2(c[mt][nt][2], c[mt][nt][3]));
                }
            }
    }
}

// -------- bf16 tensor-core GEMM (double-buffered cp.async) — gates GEMM -----
__global__ __launch_bounds__(256) void gemm_bf16(
    const __nv_bfloat16* __restrict__ A, const __nv_bfloat16* __restrict__ B,
    float* __restrict__ Cv, int M, int N, int KP, int ldc) {
    extern __shared__ __align__(16) __nv_bfloat16 smh[];
    __nv_bfloat16* As = smh;
    __nv_bfloat16* Bs = smh + 2 * 128 * 40;
    int tid = threadIdx.x;
    int mb = blockIdx.y * 128, nb = blockIdx.x * 64;
    int warp = tid >> 5, lane = tid & 31;
    int wm = warp & 3, wn = warp >> 2;
    int gid = lane >> 2, tig = lane & 3;

    float c[2][4][4];
#pragma unroll
    for (int mt = 0; mt < 2; mt++)
#pragma unroll
        for (int nt = 0; nt < 4; nt++)
#pragma unroll
            for (int i = 0; i < 4; i++) c[mt][nt][i] = 0.f;

    int nk = (KP + 31) / 32;

    auto load_chunk = [&](int i, int buf) {
#pragma unroll
        for (int l = 0; l < 2; l++) {
            int cch = tid + l * 256;
            int row = cch >> 2, seg = cch & 3;
            int col = i * 32 + seg * 8;
            int gm = mb + row;
            int sz = (gm < M && col < KP) ? 16 : 0;
            if (gm >= M) gm = M - 1;
            int cc = (col < KP) ? col : 0;
            cpa16(&As[buf * 128 * 40 + row * 40 + seg * 8],
                  &A[(size_t)gm * KP + cc], sz);
        }
        {
            int row = tid >> 2, seg = tid & 3;
            int col = i * 32 + seg * 8;
            int gn = nb + row;
            int sz = (gn < N && col < KP) ? 16 : 0;
            if (gn >= N) gn = N - 1;
            int cc = (col < KP) ? col : 0;
            cpa16(&Bs[buf * 64 * 40 + row * 40 + seg * 8],
                  &B[(size_t)gn * KP + cc], sz);
        }
        asm volatile("cp.async.commit_group;");
    };

    load_chunk(0, 0);
    for (int i = 0; i < nk; i++) {
        if (i + 1 < nk) {
            load_chunk(i + 1, (i + 1) & 1);
            asm volatile("cp.async.wait_group 1;");
        } else {
            asm volatile("cp.async.wait_group 0;");
        }
        __syncthreads();
        const __nv_bfloat16* Ab = As + (i & 1) * 128 * 40;
        const __nv_bfloat16* Bb = Bs + (i & 1) * 64 * 40;
#pragma unroll
        for (int kc = 0; kc < 2; kc++) {
            int kk = kc * 16 + 2 * tig;
            uint4 af[2];
#pragma unroll
            for (int mt = 0; mt < 2; mt++) {
                int mr = wm * 32 + mt * 16;
                af[mt].x = *(const unsigned int*)&Ab[(mr + gid) * 40 + kk];
                af[mt].y = *(const unsigned int*)&Ab[(mr + gid + 8) * 40 + kk];
                af[mt].z = *(const unsigned int*)&Ab[(mr + gid) * 40 + kk + 8];
                af[mt].w = *(const unsigned int*)&Ab[(mr + gid + 8) * 40 + kk + 8];
            }
            unsigned int bf[4][2];
#pragma unroll
            for (int nt = 0; nt < 4; nt++) {
                int nc = wn * 32 + nt * 8;
                bf[nt][0] = *(const unsigned int*)&Bb[(nc + gid) * 40 + kk];
                bf[nt][1] = *(const unsigned int*)&Bb[(nc + gid) * 40 + kk + 8];
            }
#pragma unroll
            for (int mt = 0; mt < 2; mt++)
#pragma unroll
                for (int nt = 0; nt < 4; nt++)
                    mma_bf16(c[mt][nt], af[mt], bf[nt][0], bf[nt][1]);
        }
        __syncthreads();
    }
#pragma unroll
    for (int mt = 0; mt < 2; mt++)
#pragma unroll
        for (int nt = 0; nt < 4; nt++) {
            int row0 = mb + wm * 32 + mt * 16 + gid;
            int col0 = nb + wn * 32 + nt * 8 + tig * 2;
            if (col0 < N) {
                if (row0 < M)
                    *(float2*)&Cv[(size_t)row0 * ldc + col0] =
                        make_float2(c[mt][nt][0], c[mt][nt][1]);
                if (row0 + 8 < M)
                    *(float2*)&Cv[(size_t)(row0 + 8) * ldc + col0] =
                        make_float2(c[mt][nt][2], c[mt][nt][3]);
            }
        }
}

// ---------------- word-level persistent GRU on tensor cores ----------------
__global__ __launch_bounds__(512, 1) void gru_tc(
    const int* __restrict__ toks,
    const float* __restrict__ bi_f, const float* __restrict__ bh_f,
    const float* __restrict__ bi_b, const float* __restrict__ bh_b) {
    extern __shared__ __align__(16) char sm_[];
    float* G = (float*)sm_;
    __nv_bfloat16* HbHi = (__nv_bfloat16*)(sm_ + 99200);
    __nv_bfloat16* gxS = (__nv_bfloat16*)(sm_ + 117760);
    int* gxb = (int*)(sm_ + 166400);
    int* sln = (int*)(sm_ + 174400);

    int dir = blockIdx.y;
    int b0 = blockIdx.x * BR_;
    const unsigned int* wdir = g_Wf[dir];
    const float* bi = dir ? bi_b : bi_f;
    const float* bh = dir ? bh_b : bh_f;
    int tid = threadIdx.x;
    int warp = tid >> 5, lane = tid & 31;
    int gid = lane >> 2, tig = lane & 3;

    for (int idx = tid; idx < 40 * KPAD / 2; idx += 512)
        ((unsigned int*)HbHi)[idx] = 0u;
    for (int idx = tid; idx < TW * BR_; idx += 512) {
        int t = idx / BR_, b = idx % BR_;
        int tt = dir ? (TW - 1 - t) : t;
        int row = toks[(b0 + b) * TW + tt];
        gxb[idx] = row * GXW + dir * GG;
    }
    if (tid < BR_) sln[tid] = g_slen[b0 + tid];
    __syncthreads();

    int ej = tid < 400 ? (tid % 200) : 0;
    int ehalf = tid < 400 ? (tid / 200) : 0;
    float br = 0, bz = 0, bin = 0, bhn = 0;
    if (tid < 400) {
        br = bi[ej] + bh[ej];
        bz = bi[HH + ej] + bh[HH + ej];
        bin = bi[2 * HH + ej];
        bhn = bh[2 * HH + ej];
    }
    float pool_r[20], h_r[20];
#pragma unroll
    for (int i = 0; i < 20; i++) { pool_r[i] = 0.f; h_r[i] = 0.f; }

    const unsigned int* wfb0 = wdir + (size_t)warp * KT_ * 32 * 4;
    const unsigned int* wfb1 = wdir + (size_t)(warp + 16) * KT_ * 32 * 4;
    const unsigned int* wfb2 = (warp < 6)
        ? wdir + (size_t)(warp + 32) * KT_ * 32 * 4 : wdir;

    for (int t = 0; t < TW; t++) {
        int tt = dir ? (TW - 1 - t) : t;
        {
            const int* gq = gxb + t * BR_;
            for (int ci = tid; ci < BR_ * 75; ci += 512) {
                int b = ci / 75, off = (ci % 75) * 8;
                cpa16(gxS + b * 608 + off, g_P + gq[b] + off, 16);
            }
            asm volatile("cp.async.commit_group;");
        }
        {
            float c[2][NT_][4];
#pragma unroll
            for (int q = 0; q < 2; q++)
#pragma unroll
                for (int nt = 0; nt < NT_; nt++)
#pragma unroll
                    for (int i = 0; i < 4; i++) c[q][nt][i] = 0.f;
            uint4 a0c = *(const uint4*)(wfb0 + (size_t)lane * 4);
            uint4 a1c = *(const uint4*)(wfb1 + (size_t)lane * 4);
#pragma unroll
            for (int kt = 0; kt < KT_; kt++) {
                uint4 a0n, a1n;
                if (kt + 1 < KT_) {
                    a0n = *(const uint4*)(wfb0 + ((size_t)(kt + 1) * 32 + lane) * 4);
                    a1n = *(const uint4*)(wfb1 + ((size_t)(kt + 1) * 32 + lane) * 4);
                }
                int koff = kt * 16 + tig * 2;
#pragma unroll
                for (int nt = 0; nt < NT_; nt++) {
                    int n = nt * 8 + gid;
                    unsigned int bh0 = *(const unsigned int*)&HbHi[n * KPAD + koff];
                    unsigned int bh1 = *(const unsigned int*)&HbHi[n * KPAD + koff + 8];
                    mma_bf16(c[0][nt], a0c, bh0, bh1);
                    mma_bf16(c[1][nt], a1c, bh0, bh1);
                }
                a0c = a0n; a1c = a1n;
            }
#pragma unroll
            for (int q = 0; q < 2; q++) {
                int m = (warp + q * 16) * 16 + gid;
#pragma unroll
                for (int nt = 0; nt < NT_; nt++) {
                    int bcol = nt * 8 + tig * 2;
                    G[bcol * GPAD + m] = c[q][nt][0];
                    G[(bcol + 1) * GPAD + m] = c[q][nt][1];
                    G[bcol * GPAD + m + 8] = c[q][nt][2];
                    G[(bcol + 1) * GPAD + m + 8] = c[q][nt][3];
                }
            }
        }
        if (warp < 6) {
            float d[NT_][4];
#pragma unroll
            for (int nt = 0; nt < NT_; nt++)
#pragma unroll
                for (int i = 0; i < 4; i++) d[nt][i] = 0.f;
#pragma unroll
            for (int kt = 0; kt < KT_; kt++) {
                uint4 a2 = *(const uint4*)(wfb2 + ((size_t)kt * 32 + lane) * 4);
                int koff = kt * 16 + tig * 2;
#pragma unroll
                for (int nt = 0; nt < NT_; nt++) {
                    int n = nt * 8 + gid;
                    unsigned int bh0 = *(const unsigned int*)&HbHi[n * KPAD + koff];
                    unsigned int bh1 = *(const unsigned int*)&HbHi[n * KPAD + koff + 8];
                    mma_bf16(d[nt], a2, bh0, bh1);
                }
            }
            int m = (warp + 32) * 16 + gid;
#pragma unroll
            for (int nt = 0; nt < NT_; nt++) {
                int bcol = nt * 8 + tig * 2;
                G[bcol * GPAD + m] = d[nt][0];
                G[(bcol + 1) * GPAD + m] = d[nt][1];
                G[bcol * GPAD + m + 8] = d[nt][2];
                G[(bcol + 1) * GPAD + m + 8] = d[nt][3];
            }
        }
        asm volatile("cp.async.wait_group 0;");
        __syncthreads();
        if (tid < 400) {
#pragma unroll 4
            for (int i = 0; i < 20; i++) {
                int b = ehalf * 20 + i;
                float gxr = __bfloat162float(gxS[b * 608 + ej]);
                float gxz = __bfloat162float(gxS[b * 608 + 200 + ej]);
                float gxn = __bfloat162float(gxS[b * 608 + 400 + ej]);
                float gr = G[b * GPAD + ej];
                float gz = G[b * GPAD + ej + 200];
                float gn = G[b * GPAD + ej + 400];
                float r = sigmoidf_(gxr + gr + br);
                float z = sigmoidf_(gxz + gz + bz);
                float nn = tanha_(gxn + bin + r * (gn + bhn));
                float hnew = (1.f - z) * nn + z * h_r[i];
                h_r[i] = hnew;
                if (tt < sln[b]) pool_r[i] += hnew;
                HbHi[b * KPAD + ej] = __float2bfloat16(hnew);
            }
        }
        __syncthreads();
    }

    if (tid < 400) {
#pragma unroll
        for (int i = 0; i < 20; i++) {
            int b = ehalf * 20 + i;
            int l = sln[b];
            float v = l ? pool_r[i] / (float)l : 0.f;
            g_pool[(size_t)(b0 + b) * (2 * HH) + (size_t)dir * HH + ej] =
                __float2bfloat16(v);
        }
    }
}

// ---------------- sentence-level persistent GRU (fp32) ----------
template <int BROWS>
__global__ __launch_bounds__(512, 1) void gru_seq_s(
    const int* __restrict__ dlens,
    const float* __restrict__ bi_f, const float* __restrict__ bh_f,
    const float* __restrict__ bi_b, const float* __restrict__ bh_b) {
    constexpr int PW = BROWS / 2;
    constexpr int BP = PW / 2;
    constexpr int HR = BROWS / 2;
    constexpr int CH = HR * 150;
    constexpr int TLEN = DT;

    extern __shared__ __align__(16) char sm_[];
    float2* hsT   = (float2*)sm_;
    float*  gxs_  = (float*)(sm_ + HH * PW * 8);
    float* pool_s = (float*)(sm_ + HH * PW * 8 + BROWS * 600 * 4);
    int* gxb = (int*)(sm_ + HH * PW * 8 + BROWS * 600 * 4 + BROWS * HH * 4);
    int* sln = gxb + TLEN * BROWS;

    int dir = blockIdx.y;
    int b0 = blockIdx.x * BROWS;
    const float4* wP = g_wP[dir];
    const float* bi = dir ? bi_b : bi_f;
    const float* bh = dir ? bh_b : bh_f;
    int tid = threadIdx.x;
    int half = tid >> 8;
    int j = tid & 255;
    int pbase = half * BP;

    for (int idx = tid; idx < HH * PW; idx += 512) hsT[idx] = make_float2(0.f, 0.f);
    for (int idx = tid; idx < BROWS * HH; idx += 512) pool_s[idx] = 0.f;
    for (int idx = tid; idx < TLEN * BROWS; idx += 512) {
        int t = idx / BROWS, b = idx % BROWS;
        int tt = dir ? (TLEN - 1 - t) : t;
        int row = (b0 + b) * TLEN + tt;
        gxb[idx] = row * GXW + dir * GG;
    }
    if (tid < BROWS) sln[tid] = dlens[b0 + tid];
    __syncthreads();

    float br = 0, bz = 0, bin = 0, bhn = 0;
    if (j < HH) {
        br = bi[j] + bh[j];
        bz = bi[HH + j] + bh[HH + j];
        bin = bi[2 * HH + j];
        bhn = bh[2 * HH + j];
    }

    for (int t = 0; t < TLEN; t++) {
        int tt = dir ? (TLEN - 1 - t) : t;
        {
            const int* gq = gxb + t * BROWS;
#pragma unroll 2
            for (int c = j; c < CH; c += 256) {
                int b = half * HR + c / 150;
                int off = (c % 150) * 4;
                cpa16(gxs_ + b * 600 + off, g_gxs + gq[b] + off, 16);
            }
            asm volatile("cp.async.commit_group;");
        }
        ull aR[BP], aZ[BP], aN[BP];
        if (j < HH) {
#pragma unroll
            for (int p = 0; p < BP; p++) { aR[p] = 0; aZ[p] = 0; aN[p] = 0; }
            const float4* wp = wP + j;
            float4 ra[4];
#pragma unroll
            for (int i = 0; i < 4; i++) ra[i] = wp[i * HH];
#pragma unroll 4
            for (int k = 0; k < HH; k++) {
                float4 wc = ra[k & 3];
                int kp = k + 4;
                if (kp < HH) ra[k & 3] = wp[kp * HH];
                ull w0 = pack1(wc.x), w1 = pack1(wc.y), w2 = pack1(wc.z);
#pragma unroll
                for (int q = 0; q < BP / 2; q++) {
                    ulonglong2 hq =
                        *(const ulonglong2*)&hsT[k * PW + pbase + 2 * q];
                    fma2(aR[2 * q], hq.x, w0);
                    fma2(aZ[2 * q], hq.x, w1);
                    fma2(aN[2 * q], hq.x, w2);
                    fma2(aR[2 * q + 1], hq.y, w0);
                    fma2(aZ[2 * q + 1], hq.y, w1);
                    fma2(aN[2 * q + 1], hq.y, w2);
                }
            }
        }
        asm volatile("cp.async.wait_group 0;");
        asm volatile("bar.sync %0, 256;" :: "r"(1 + half) : "memory");
        if (j < HH) {
#pragma unroll
            for (int p = 0; p < BP; p++) {
                int gp = pbase + p;
                float hr[2], hz[2], hn[2], hnew[2];
                unpack2(aR[p], hr[0], hr[1]);
                unpack2(aZ[p], hz[0], hz[1]);
                unpack2(aN[p], hn[0], hn[1]);
                float2 hold = hsT[j * PW + gp];
#pragma unroll
                for (int l = 0; l < 2; l++) {
                    int b = 2 * gp + l;
                    const float* gx = gxs_ + b * 600;
                    float r = sigmoidf_(gx[j] + hr[l] + br);
                    float z = sigmoidf_(gx[HH + j] + hz[l] + bz);
                    float nn = tanha_(gx[2 * HH + j] + bin + r * (hn[l] + bhn));
                    float ho = l ? hold.y : hold.x;
                    hnew[l] = (1.f - z) * nn + z * ho;
                    if (tt < sln[b]) pool_s[b * HH + j] += hnew[l];
                }
                hsT[j * PW + gp] = make_float2(hnew[0], hnew[1]);
            }
        }
        asm volatile("bar.sync %0, 256;" :: "r"(1 + half) : "memory");
    }

    if (j < HH) {
#pragma unroll
        for (int p = 0; p < BP; p++) {
#pragma unroll
            for (int l = 0; l < 2; l++) {
                int b = 2 * (pbase + p) + l;
                int ln = sln[b];
                float v = pool_s[b * HH + j];
                g_poold[(size_t)(b0 + b) * (2 * HH) + (size_t)dir * HH + j] =
                    ln ? v / (float)ln : 0.f;
            }
        }
    }
}

// ---------------- prep ----------------
__global__ void k_prep(const int* __restrict__ x, const float* __restrict__ emb,
                       const float* __restrict__ wf_ih, const float* __restrict__ wb_ih,
                       const float* __restrict__ sf_ih, const float* __restrict__ sb_ih,
                       const float* __restrict__ wf_hh, const float* __restrict__ wb_hh,
                       const float* __restrict__ sf_hh, const float* __restrict__ sb_hh) {
    int i0 = blockIdx.x * blockDim.x + threadIdx.x;
    int gs = gridDim.x * blockDim.x;
    const float* wss[2] = {sf_hh, sb_hh};
    for (int idx = i0; idx < HH * HH; idx += gs) {
        int k = idx / HH, j = idx % HH;
#pragma unroll
        for (int a = 0; a < 2; a++) {
            g_wP[a][idx] = make_float4(wss[a][j * HH + k],
                                       wss[a][(HH + j) * HH + k],
                                       wss[a][(2 * HH + j) * HH + k], 0.f);
        }
    }
    const float* wsw[2] = {wf_hh, wb_hh};
    const int TOT = 2 * MT_ * KT_ * 32 * 4;
    for (int idx = i0; idx < TOT; idx += gs) {
        int rr = idx & 3;
        int lane = (idx >> 2) & 31;
        int kt = (idx >> 7) % KT_;
        int mt = (idx / (KT_ * 32 * 4)) % MT_;
        int a = idx / (MT_ * KT_ * 32 * 4);
        int gid = lane >> 2, tig = lane & 3;
        int row = mt * 16 + gid + (rr & 1) * 8;
        int k0 = kt * 16 + tig * 2 + ((rr >> 1) & 1) * 8;
        float w0 = (row < GG && k0 < HH) ? wsw[a][row * HH + k0] : 0.f;
        float w1 = (row < GG && k0 + 1 < HH) ? wsw[a][row * HH + k0 + 1] : 0.f;
        __nv_bfloat16 h0 = __float2bfloat16(w0);
        __nv_bfloat16 h1 = __float2bfloat16(w1);
        unsigned int hiw = ((unsigned int)__bfloat16_as_ushort(h1) << 16) |
                           (unsigned int)__bfloat16_as_ushort(h0);
        g_Wf[a][(((size_t)mt * KT_ + kt) * 32 + lane) * 4 + rr] = hiw;
    }
    for (int idx = i0; idx < VOC * KPE; idx += gs) {
        int r = idx / KPE, k = idx - r * KPE;
        g_embB[idx] = __float2bfloat16(k < DD ? emb[r * DD + k] : 0.f);
    }
    for (int idx = i0; idx < GXW * KPE; idx += gs) {
        int r = idx / KPE, k = idx - r * KPE;
        float v = 0.f;
        if (k < DD) v = (r < GG) ? wf_ih[r * DD + k] : wb_ih[(r - GG) * DD + k];
        g_WihB[idx] = __float2bfloat16(v);
    }
    for (int idx = i0; idx < GXW * 400; idx += gs) {
        int r = idx / 400, k = idx - r * 400;
        float v = (r < GG) ? sf_ih[r * 400 + k] : sb_ih[(r - GG) * 400 + k];
        g_SihB[idx] = __float2bfloat16(v);
    }
    for (int s = i0; s < NS; s += gs) {
        int c = 0;
        for (int t = 0; t < TW; t++) c += (x[s * TW + t] != 0);
        g_slen[s] = c;
    }
}

__global__ void k_scan(const int* __restrict__ dl) {
    if (threadIdx.x == 0) {
        int a = 0;
        for (int i = 0; i < ND; i++) { g_offs[i] = a; a += dl[i]; }
    }
}

__global__ __launch_bounds__(128) void k_final(const int* __restrict__ dl,
                                               const float* __restrict__ doc_w,
                                               const float* __restrict__ doc_b,
                                               const float* __restrict__ sent_w,
                                               const float* __restrict__ sent_b,
                                               float* __restrict__ out) {
    __shared__ float d[2 * HH];
    __shared__ float redw[4];
    int doc = blockIdx.x, tid = threadIdx.x;
    int l = dl[doc];
    for (int f = tid; f < 2 * HH; f += 128)
        d[f] = g_poold[doc * 2 * HH + f];
    __syncthreads();
    for (int r = 0; r < 11; r++) {
        const float* w = (r == 0) ? doc_w : sent_w + (r - 1) * 2 * HH;
        float p = 0.f;
        for (int f = tid; f < 2 * HH; f += 128) p += d[f] * w[f];
        for (int o = 16; o; o >>= 1) p += __shfl_down_sync(0xFFFFFFFFu, p, o);
        if ((tid & 31) == 0) redw[tid >> 5] = p;
        __syncthreads();
        if (tid == 0) {
            float s = redw[0] + redw[1] + redw[2] + redw[3];
            if (r == 0) out[doc] = sigmoidf_(s + doc_b[0]);
            else if (r - 1 < l) out[ND + g_offs[doc] + (r - 1)] = sigmoidf_(s + sent_b[r - 1]);
        }
        __syncthreads();
    }
}

// ---------------- host ----------------
extern "C" void kernel_launch(void* const* d_in, const int* in_sizes, int n_in,
                              void* d_out, int out_size) {
    int base = (n_in >= 24) ? 1 : 0;
    const int*   x        = (const int*)d_in[0];
    const int*   doc_lens = (const int*)d_in[1 + base];
    const float* emb      = (const float*)d_in[2 + base];
    const float* wf_ih    = (const float*)d_in[3 + base];
    const float* wf_hh    = (const float*)d_in[4 + base];
    const float* wf_bi    = (const float*)d_in[5 + base];
    const float* wf_bh    = (const float*)d_in[6 + base];
    const float* wb_ih    = (const float*)d_in[7 + base];
    const float* wb_hh    = (const float*)d_in[8 + base];
    const float* wb_bi    = (const float*)d_in[9 + base];
    const float* wb_bh    = (const float*)d_in[10 + base];
    const float* sf_ih    = (const float*)d_in[11 + base];
    const float* sf_hh    = (const float*)d_in[12 + base];
    const float* sf_bi    = (const float*)d_in[13 + base];
    const float* sf_bh    = (const float*)d_in[14 + base];
    const float* sb_ih    = (const float*)d_in[15 + base];
    const float* sb_hh    = (const float*)d_in[16 + base];
    const float* sb_bi    = (const float*)d_in[17 + base];
    const float* sb_bh    = (const float*)d_in[18 + base];
    const float* doc_w    = (const float*)d_in[19 + base];
    const float* doc_b    = (const float*)d_in[20 + base];
    const float* sent_w   = (const float*)d_in[21 + base];
    const float* sent_b   = (const float*)d_in[22 + base];
    float* out = (float*)d_out;

    void *P, *gxs, *pool, *embB, *wihB, *sihB;
    cudaGetSymbolAddress(&P, g_P);
    cudaGetSymbolAddress(&gxs, g_gxs);
    cudaGetSymbolAddress(&pool, g_pool);
    cudaGetSymbolAddress(&embB, g_embB);
    cudaGetSymbolAddress(&wihB, g_WihB);
    cudaGetSymbolAddress(&sihB, g_SihB);

    const int SMB = (2 * 128 * 40 + 2 * 64 * 40) * 2;
    const int SMP = (128 * SA + 2 * 64 * SA) * 2;   // 167,936
    const int SMW = 174560;
    const int SMS = HH * 8 * 8 + 16 * 600 * 4 + 16 * HH * 4 + DT * 16 * 4 + 16 * 4;
    cudaFuncSetAttribute(gemm_strip,
                         cudaFuncAttributeMaxDynamicSharedMemorySize, SMP);
    cudaFuncSetAttribute(gemm_bf16,
                         cudaFuncAttributeMaxDynamicSharedMemorySize, SMB);
    cudaFuncSetAttribute(gru_tc,
                         cudaFuncAttributeMaxDynamicSharedMemorySize, SMW);
    cudaFuncSetAttribute(gru_seq_s<16>,
                         cudaFuncAttributeMaxDynamicSharedMemorySize, SMS);

    k_prep<<<512, 256>>>(x, emb, wf_ih, wb_ih, sf_ih, sb_ih,
                         wf_hh, wb_hh, sf_hh, sb_hh);

    // P = embB @ WihB^T — strip-persistent bf16 GEMM (A staged once per block)
    gemm_strip<<<(VOC + 127) / 128, 256, SMP>>>(
        (const __nv_bfloat16*)embB, (const __nv_bfloat16*)wihB,
        (__nv_bfloat16*)P, VOC);

    // word-level BiGRU
    gru_tc<<<dim3(NS / BR_, 2), 512, SMW>>>(x, wf_bi, wf_bh, wb_bi, wb_bh);

    // sentence gates
    gemm_bf16<<<dim3((GXW + 63) / 64, (NS + 127) / 128), 256, SMB>>>(
        (const __nv_bfloat16*)pool, (const __nv_bfloat16*)sihB, (float*)gxs,
        NS, GXW, 400, GXW);

    // sentence-level BiGRU
    gru_seq_s<16><<<dim3(ND / 16, 2), 512, SMS>>>(
        doc_lens, sf_bi, sf_bh, sb_bi, sb_bh);

    k_scan<<<1, 32>>>(doc_lens);
    k_final<<<ND, 128>>>(doc_lens, doc_w, doc_b, sent_w, sent_b, out);
}

// round 17
// speedup vs baseline: 4.9409x; 1.0329x over previous
#include <cuda_runtime.h>
#include <cuda_bf16.h>
#include <math.h>

#define HH   200
#define DD   300
#define TW   50
#define NS   2560
#define ND   256
#define DT   10
#define GG   600
#define GXW  1200
#define VOC  50000
#define KPE  304
#define SA   328

// word-level tensor-core GRU geometry
#define MT_   38
#define KT_   13
#define NT_   5
#define BR_   40
#define KPAD  232
#define GPAD  620

// ---------------- device scratch ----------------
__device__ __nv_bfloat16 g_P[VOC * GXW];
__device__ __nv_bfloat16 g_WihB[GXW * KPE];
__device__ __nv_bfloat16 g_SihB[GXW * 400];
__device__ __nv_bfloat16 g_pool[NS * 2 * HH];
__device__ float g_gxs[NS * GXW];
__device__ __align__(16) float4 g_wP[2][HH * HH];
__device__ __align__(16) unsigned int g_Wf[2][MT_ * KT_ * 32 * 4];
__device__ float g_poold[ND * 2 * HH];
__device__ int   g_slen[NS];
__device__ int   g_offs[ND];

// ---------------- helpers ----------------
typedef unsigned long long ull;
__device__ __forceinline__ ull pack1(float a) {
    ull r; asm("mov.b64 %0, {%1, %1};" : "=l"(r) : "f"(a)); return r;
}
__device__ __forceinline__ void fma2(ull& d, ull a, ull b) {
    asm("fma.rn.f32x2 %0, %1, %2, %0;" : "+l"(d) : "l"(a), "l"(b));
}
__device__ __forceinline__ void unpack2(ull v, float& a, float& b) {
    asm("mov.b64 {%0, %1}, %2;" : "=f"(a), "=f"(b) : "l"(v));
}
__device__ __forceinline__ float tanha_(float x) {
    float y; asm("tanh.approx.f32 %0, %1;" : "=f"(y) : "f"(x)); return y;
}
__device__ __forceinline__ float sigmoidf_(float x) {
    return fmaf(0.5f, tanha_(0.5f * x), 0.5f);
}
__device__ __forceinline__ void mma_bf16(float* c, uint4 a,
                                         unsigned int b0, unsigned int b1) {
    asm volatile(
        "mma.sync.aligned.m16n8k16.row.col.f32.bf16.bf16.f32 "
        "{%0,%1,%2,%3}, {%4,%5,%6,%7}, {%8,%9}, {%0,%1,%2,%3};"
        : "+f"(c[0]), "+f"(c[1]), "+f"(c[2]), "+f"(c[3])
        : "r"(a.x), "r"(a.y), "r"(a.z), "r"(a.w), "r"(b0), "r"(b1));
}
__device__ __forceinline__ void cpa16(void* dst, const void* src, int sz) {
    unsigned int d = (unsigned int)__cvta_generic_to_shared(dst);
    asm volatile("cp.async.cg.shared.global [%0], [%1], 16, %2;"
                 :: "r"(d), "l"(src), "r"(sz));
}

// -------- strip GEMM for P: C[M,1200] = emb[M,300](fp32) @ B[1200,304]^T ----
// A converted to bf16 during once-per-block staging. B (bf16) in 64-wide
// double-buffered chunks. 8 warps, warp tile 32m x 32n.
__global__ __launch_bounds__(256) void gemm_strip(
    const float* __restrict__ A, const __nv_bfloat16* __restrict__ B,
    __nv_bfloat16* __restrict__ C, int M) {
    extern __shared__ __align__(16) __nv_bfloat16 smh[];
    __nv_bfloat16* As = smh;                  // [128][SA]
    __nv_bfloat16* Bs = smh + 128 * SA;       // [2][64][SA]
    const int NC = (GXW + 63) / 64;           // 19
    int tid = threadIdx.x;
    int mb = blockIdx.x * 128;
    int warp = tid >> 5, lane = tid & 31;
    int wm = warp & 3, wn = warp >> 2;
    int gid = lane >> 2, tig = lane & 3;

    // stage A strip once: fp32 -> bf16 (rn), zero-pad cols 300..303
    for (int idx = tid; idx < 128 * 76; idx += 256) {
        int row = idx / 76, seg = idx % 76;
        int gm = mb + row;
        float4 v = make_float4(0.f, 0.f, 0.f, 0.f);
        if (seg < 75 && gm < M) v = *(const float4*)&A[(size_t)gm * DD + seg * 4];
        __nv_bfloat162 p0 = __float22bfloat162_rn(make_float2(v.x, v.y));
        __nv_bfloat162 p1 = __float22bfloat162_rn(make_float2(v.z, v.w));
        *(__nv_bfloat162*)&As[row * SA + seg * 4] = p0;
        *(__nv_bfloat162*)&As[row * SA + seg * 4 + 2] = p1;
    }

    auto stageB = [&](int nc, int buf) {
        for (int idx = tid; idx < 64 * 38; idx += 256) {
            int row = idx / 38, seg = idx % 38;
            int gn = nc * 64 + row;
            int sz = (gn < GXW) ? 16 : 0;
            if (gn >= GXW) gn = GXW - 1;
            cpa16(&Bs[buf * 64 * SA + row * SA + seg * 8],
                  &B[(size_t)gn * KPE + seg * 8], sz);
        }
        asm volatile("cp.async.commit_group;");
    };

    stageB(0, 0);
    for (int nc = 0; nc < NC; nc++) {
        __syncthreads();
        if (nc + 1 < NC) {
            stageB(nc + 1, (nc + 1) & 1);
            asm volatile("cp.async.wait_group 1;");
        } else {
            asm volatile("cp.async.wait_group 0;");
        }
        __syncthreads();
        const __nv_bfloat16* Bb = Bs + (nc & 1) * 64 * SA;

        float c[2][4][4];
#pragma unroll
        for (int mt = 0; mt < 2; mt++)
#pragma unroll
            for (int nt = 0; nt < 4; nt++)
#pragma unroll
                for (int i = 0; i < 4; i++) c[mt][nt][i] = 0.f;

#pragma unroll 4
        for (int kt = 0; kt < 19; kt++) {
            int kk = kt * 16 + 2 * tig;
            uint4 af[2];
#pragma unroll
            for (int mt = 0; mt < 2; mt++) {
                int mr = wm * 32 + mt * 16;
                af[mt].x = *(const unsigned int*)&As[(mr + gid) * SA + kk];
                af[mt].y = *(const unsigned int*)&As[(mr + gid + 8) * SA + kk];
                af[mt].z = *(const unsigned int*)&As[(mr + gid) * SA + kk + 8];
                af[mt].w = *(const unsigned int*)&As[(mr + gid + 8) * SA + kk + 8];
            }
#pragma unroll
            for (int nt = 0; nt < 4; nt++) {
                int nr = wn * 32 + nt * 8 + gid;
                unsigned int b0 = *(const unsigned int*)&Bb[nr * SA + kk];
                unsigned int b1 = *(const unsigned int*)&Bb[nr * SA + kk + 8];
                mma_bf16(c[0][nt], af[0], b0, b1);
                mma_bf16(c[1][nt], af[1], b0, b1);
            }
        }
#pragma unroll
        for (int mt = 0; mt < 2; mt++)
#pragma unroll
            for (int nt = 0; nt < 4; nt++) {
                int row0 = mb + wm * 32 + mt * 16 + gid;
                int col0 = nc * 64 + wn * 32 + nt * 8 + tig * 2;
                if (col0 < GXW) {
                    if (row0 < M)
                        *(__nv_bfloat162*)&C[(size_t)row0 * GXW + col0] =
                            __float22bfloat162_rn(
                                make_float2(c[mt][nt][0], c[mt][nt][1]));
                    if (row0 + 8 < M)
                        *(__nv_bfloat162*)&C[(size_t)(row0 + 8) * GXW + col0] =
                            __float22bfloat162_rn(
                                make_float2(c[mt][nt][2], c[mt][nt][3]));
                }
            }
    }
}

// -------- bf16 tensor-core GEMM — sentence gates --------
__global__ __launch_bounds__(256) void gemm_bf16(
    const __nv_bfloat16* __restrict__ A, const __nv_bfloat16* __restrict__ B,
    float* __restrict__ Cv, int M, int N, int KP, int ldc) {
    extern __shared__ __align__(16) __nv_bfloat16 smh[];
    __nv_bfloat16* As = smh;
    __nv_bfloat16* Bs = smh + 2 * 128 * 40;
    int tid = threadIdx.x;
    int mb = blockIdx.y * 128, nb = blockIdx.x * 64;
    int warp = tid >> 5, lane = tid & 31;
    int wm = warp & 3, wn = warp >> 2;
    int gid = lane >> 2, tig = lane & 3;

    float c[2][4][4];
#pragma unroll
    for (int mt = 0; mt < 2; mt++)
#pragma unroll
        for (int nt = 0; nt < 4; nt++)
#pragma unroll
            for (int i = 0; i < 4; i++) c[mt][nt][i] = 0.f;

    int nk = (KP + 31) / 32;

    auto load_chunk = [&](int i, int buf) {
#pragma unroll
        for (int l = 0; l < 2; l++) {
            int cch = tid + l * 256;
            int row = cch >> 2, seg = cch & 3;
            int col = i * 32 + seg * 8;
            int gm = mb + row;
            int sz = (gm < M && col < KP) ? 16 : 0;
            if (gm >= M) gm = M - 1;
            int cc = (col < KP) ? col : 0;
            cpa16(&As[buf * 128 * 40 + row * 40 + seg * 8],
                  &A[(size_t)gm * KP + cc], sz);
        }
        {
            int row = tid >> 2, seg = tid & 3;
            int col = i * 32 + seg * 8;
            int gn = nb + row;
            int sz = (gn < N && col < KP) ? 16 : 0;
            if (gn >= N) gn = N - 1;
            int cc = (col < KP) ? col : 0;
            cpa16(&Bs[buf * 64 * 40 + row * 40 + seg * 8],
                  &B[(size_t)gn * KP + cc], sz);
        }
        asm volatile("cp.async.commit_group;");
    };

    load_chunk(0, 0);
    for (int i = 0; i < nk; i++) {
        if (i + 1 < nk) {
            load_chunk(i + 1, (i + 1) & 1);
            asm volatile("cp.async.wait_group 1;");
        } else {
            asm volatile("cp.async.wait_group 0;");
        }
        __syncthreads();
        const __nv_bfloat16* Ab = As + (i & 1) * 128 * 40;
        const __nv_bfloat16* Bb = Bs + (i & 1) * 64 * 40;
#pragma unroll
        for (int kc = 0; kc < 2; kc++) {
            int kk = kc * 16 + 2 * tig;
            uint4 af[2];
#pragma unroll
            for (int mt = 0; mt < 2; mt++) {
                int mr = wm * 32 + mt * 16;
                af[mt].x = *(const unsigned int*)&Ab[(mr + gid) * 40 + kk];
                af[mt].y = *(const unsigned int*)&Ab[(mr + gid + 8) * 40 + kk];
                af[mt].z = *(const unsigned int*)&Ab[(mr + gid) * 40 + kk + 8];
                af[mt].w = *(const unsigned int*)&Ab[(mr + gid + 8) * 40 + kk + 8];
            }
            unsigned int bf[4][2];
#pragma unroll
            for (int nt = 0; nt < 4; nt++) {
                int nc = wn * 32 + nt * 8;
                bf[nt][0] = *(const unsigned int*)&Bb[(nc + gid) * 40 + kk];
                bf[nt][1] = *(const unsigned int*)&Bb[(nc + gid) * 40 + kk + 8];
            }
#pragma unroll
            for (int mt = 0; mt < 2; mt++)
#pragma unroll
                for (int nt = 0; nt < 4; nt++)
                    mma_bf16(c[mt][nt], af[mt], bf[nt][0], bf[nt][1]);
        }
        __syncthreads();
    }
#pragma unroll
    for (int mt = 0; mt < 2; mt++)
#pragma unroll
        for (int nt = 0; nt < 4; nt++) {
            int row0 = mb + wm * 32 + mt * 16 + gid;
            int col0 = nb + wn * 32 + nt * 8 + tig * 2;
            if (col0 < N) {
                if (row0 < M)
                    *(float2*)&Cv[(size_t)row0 * ldc + col0] =
                        make_float2(c[mt][nt][0], c[mt][nt][1]);
                if (row0 + 8 < M)
                    *(float2*)&Cv[(size_t)(row0 + 8) * ldc + col0] =
                        make_float2(c[mt][nt][2], c[mt][nt][3]);
            }
        }
}

// ---------------- word-level persistent GRU on tensor cores ----------------
// Balanced single-pass mma: warps 0-5 own 3 m-tiles, warps 6-15 own 2;
// B-fragments loaded once per warp. h state lives in bf16 HbHi.
__global__ __launch_bounds__(512, 1) void gru_tc(
    const int* __restrict__ toks,
    const float* __restrict__ bi_f, const float* __restrict__ bh_f,
    const float* __restrict__ bi_b, const float* __restrict__ bh_b) {
    extern __shared__ __align__(16) char sm_[];
    float* G = (float*)sm_;
    __nv_bfloat16* HbHi = (__nv_bfloat16*)(sm_ + 99200);
    __nv_bfloat16* gxS = (__nv_bfloat16*)(sm_ + 117760);
    int* gxb = (int*)(sm_ + 166400);
    int* sln = (int*)(sm_ + 174400);

    int dir = blockIdx.y;
    int b0 = blockIdx.x * BR_;
    const unsigned int* wdir = g_Wf[dir];
    const float* bi = dir ? bi_b : bi_f;
    const float* bh = dir ? bh_b : bh_f;
    int tid = threadIdx.x;
    int warp = tid >> 5, lane = tid & 31;
    int gid = lane >> 2, tig = lane & 3;

    for (int idx = tid; idx < 40 * KPAD / 2; idx += 512)
        ((unsigned int*)HbHi)[idx] = 0u;
    for (int idx = tid; idx < TW * BR_; idx += 512) {
        int t = idx / BR_, b = idx % BR_;
        int tt = dir ? (TW - 1 - t) : t;
        int row = toks[(b0 + b) * TW + tt];
        gxb[idx] = row * GXW + dir * GG;
    }
    if (tid < BR_) sln[tid] = g_slen[b0 + tid];
    __syncthreads();

    int ej = tid < 400 ? (tid % 200) : 0;
    int ehalf = tid < 400 ? (tid / 200) : 0;
    float br = 0, bz = 0, bin = 0, bhn = 0;
    if (tid < 400) {
        br = bi[ej] + bh[ej];
        bz = bi[HH + ej] + bh[HH + ej];
        bin = bi[2 * HH + ej];
        bhn = bh[2 * HH + ej];
    }
    float pool_r[20];
#pragma unroll
    for (int i = 0; i < 20; i++) pool_r[i] = 0.f;

    const bool t3 = (warp < 6);
    const unsigned int* wf0 = wdir + (size_t)warp * KT_ * 128;
    const unsigned int* wf1 = wdir + (size_t)(warp + 16) * KT_ * 128;
    const unsigned int* wf2 = wdir + (size_t)(t3 ? warp + 32 : warp) * KT_ * 128;

    for (int t = 0; t < TW; t++) {
        int tt = dir ? (TW - 1 - t) : t;
        {
            const int* gq = gxb + t * BR_;
            for (int ci = tid; ci < BR_ * 75; ci += 512) {
                int b = ci / 75, off = (ci % 75) * 8;
                cpa16(gxS + b * 608 + off, g_P + gq[b] + off, 16);
            }
            asm volatile("cp.async.commit_group;");
        }
        // ---- single balanced mma pass ----
        {
            float c[3][NT_][4];
#pragma unroll
            for (int q = 0; q < 3; q++)
#pragma unroll
                for (int nt = 0; nt < NT_; nt++)
#pragma unroll
                    for (int i = 0; i < 4; i++) c[q][nt][i] = 0.f;
            uint4 a0 = *(const uint4*)(wf0 + (size_t)lane * 4);
            uint4 a1 = *(const uint4*)(wf1 + (size_t)lane * 4);
            uint4 a2 = make_uint4(0, 0, 0, 0);
            if (t3) a2 = *(const uint4*)(wf2 + (size_t)lane * 4);
#pragma unroll
            for (int kt = 0; kt < KT_; kt++) {
                uint4 n0, n1, n2;
                if (kt + 1 < KT_) {
                    n0 = *(const uint4*)(wf0 + ((size_t)(kt + 1) * 32 + lane) * 4);
                    n1 = *(const uint4*)(wf1 + ((size_t)(kt + 1) * 32 + lane) * 4);
                    if (t3)
                        n2 = *(const uint4*)(wf2 + ((size_t)(kt + 1) * 32 + lane) * 4);
                }
                int koff = kt * 16 + tig * 2;
#pragma unroll
                for (int nt = 0; nt < NT_; nt++) {
                    int n = nt * 8 + gid;
                    unsigned int bh0 = *(const unsigned int*)&HbHi[n * KPAD + koff];
                    unsigned int bh1 = *(const unsigned int*)&HbHi[n * KPAD + koff + 8];
                    mma_bf16(c[0][nt], a0, bh0, bh1);
                    mma_bf16(c[1][nt], a1, bh0, bh1);
                    if (t3) mma_bf16(c[2][nt], a2, bh0, bh1);
                }
                a0 = n0; a1 = n1;
                if (t3) a2 = n2;
            }
#pragma unroll
            for (int q = 0; q < 2; q++) {
                int m = (warp + q * 16) * 16 + gid;
#pragma unroll
                for (int nt = 0; nt < NT_; nt++) {
                    int bcol = nt * 8 + tig * 2;
                    G[bcol * GPAD + m] = c[q][nt][0];
                    G[(bcol + 1) * GPAD + m] = c[q][nt][1];
                    G[bcol * GPAD + m + 8] = c[q][nt][2];
                    G[(bcol + 1) * GPAD + m + 8] = c[q][nt][3];
                }
            }
            if (t3) {
                int m = (warp + 32) * 16 + gid;
#pragma unroll
                for (int nt = 0; nt < NT_; nt++) {
                    int bcol = nt * 8 + tig * 2;
                    G[bcol * GPAD + m] = c[2][nt][0];
                    G[(bcol + 1) * GPAD + m] = c[2][nt][1];
                    G[bcol * GPAD + m + 8] = c[2][nt][2];
                    G[(bcol + 1) * GPAD + m + 8] = c[2][nt][3];
                }
            }
        }
        asm volatile("cp.async.wait_group 0;");
        __syncthreads();
        if (tid < 400) {
#pragma unroll 4
            for (int i = 0; i < 20; i++) {
                int b = ehalf * 20 + i;
                float gxr = __bfloat162float(gxS[b * 608 + ej]);
                float gxz = __bfloat162float(gxS[b * 608 + 200 + ej]);
                float gxn = __bfloat162float(gxS[b * 608 + 400 + ej]);
                float gr = G[b * GPAD + ej];
                float gz = G[b * GPAD + ej + 200];
                float gn = G[b * GPAD + ej + 400];
                float r = sigmoidf_(gxr + gr + br);
                float z = sigmoidf_(gxz + gz + bz);
                float nn = tanha_(gxn + bin + r * (gn + bhn));
                float ho = __bfloat162float(HbHi[b * KPAD + ej]);
                float hnew = (1.f - z) * nn + z * ho;
                if (tt < sln[b]) pool_r[i] += hnew;
                HbHi[b * KPAD + ej] = __float2bfloat16(hnew);
            }
        }
        __syncthreads();
    }

    if (tid < 400) {
#pragma unroll
        for (int i = 0; i < 20; i++) {
            int b = ehalf * 20 + i;
            int l = sln[b];
            float v = l ? pool_r[i] / (float)l : 0.f;
            g_pool[(size_t)(b0 + b) * (2 * HH) + (size_t)dir * HH + ej] =
                __float2bfloat16(v);
        }
    }
}

// ---------------- sentence-level persistent GRU (fp32) ----------
template <int BROWS>
__global__ __launch_bounds__(512, 1) void gru_seq_s(
    const int* __restrict__ dlens,
    const float* __restrict__ bi_f, const float* __restrict__ bh_f,
    const float* __restrict__ bi_b, const float* __restrict__ bh_b) {
    constexpr int PW = BROWS / 2;
    constexpr int BP = PW / 2;
    constexpr int HR = BROWS / 2;
    constexpr int CH = HR * 150;
    constexpr int TLEN = DT;

    extern __shared__ __align__(16) char sm_[];
    float2* hsT   = (float2*)sm_;
    float*  gxs_  = (float*)(sm_ + HH * PW * 8);
    float* pool_s = (float*)(sm_ + HH * PW * 8 + BROWS * 600 * 4);
    int* gxb = (int*)(sm_ + HH * PW * 8 + BROWS * 600 * 4 + BROWS * HH * 4);
    int* sln = gxb + TLEN * BROWS;

    int dir = blockIdx.y;
    int b0 = blockIdx.x * BROWS;
    const float4* wP = g_wP[dir];
    const float* bi = dir ? bi_b : bi_f;
    const float* bh = dir ? bh_b : bh_f;
    int tid = threadIdx.x;
    int half = tid >> 8;
    int j = tid & 255;
    int pbase = half * BP;

    for (int idx = tid; idx < HH * PW; idx += 512) hsT[idx] = make_float2(0.f, 0.f);
    for (int idx = tid; idx < BROWS * HH; idx += 512) pool_s[idx] = 0.f;
    for (int idx = tid; idx < TLEN * BROWS; idx += 512) {
        int t = idx / BROWS, b = idx % BROWS;
        int tt = dir ? (TLEN - 1 - t) : t;
        int row = (b0 + b) * TLEN + tt;
        gxb[idx] = row * GXW + dir * GG;
    }
    if (tid < BROWS) sln[tid] = dlens[b0 + tid];
    __syncthreads();

    float br = 0, bz = 0, bin = 0, bhn = 0;
    if (j < HH) {
        br = bi[j] + bh[j];
        bz = bi[HH + j] + bh[HH + j];
        bin = bi[2 * HH + j];
        bhn = bh[2 * HH + j];
    }

    for (int t = 0; t < TLEN; t++) {
        int tt = dir ? (TLEN - 1 - t) : t;
        {
            const int* gq = gxb + t * BROWS;
#pragma unroll 2
            for (int c = j; c < CH; c += 256) {
                int b = half * HR + c / 150;
                int off = (c % 150) * 4;
                cpa16(gxs_ + b * 600 + off, g_gxs + gq[b] + off, 16);
            }
            asm volatile("cp.async.commit_group;");
        }
        ull aR[BP], aZ[BP], aN[BP];
        if (j < HH) {
#pragma unroll
            for (int p = 0; p < BP; p++) { aR[p] = 0; aZ[p] = 0; aN[p] = 0; }
            const float4* wp = wP + j;
            float4 ra[4];
#pragma unroll
            for (int i = 0; i < 4; i++) ra[i] = wp[i * HH];
#pragma unroll 4
            for (int k = 0; k < HH; k++) {
                float4 wc = ra[k & 3];
                int kp = k + 4;
                if (kp < HH) ra[k & 3] = wp[kp * HH];
                ull w0 = pack1(wc.x), w1 = pack1(wc.y), w2 = pack1(wc.z);
#pragma unroll
                for (int q = 0; q < BP / 2; q++) {
                    ulonglong2 hq =
                        *(const ulonglong2*)&hsT[k * PW + pbase + 2 * q];
                    fma2(aR[2 * q], hq.x, w0);
                    fma2(aZ[2 * q], hq.x, w1);
                    fma2(aN[2 * q], hq.x, w2);
                    fma2(aR[2 * q + 1], hq.y, w0);
                    fma2(aZ[2 * q + 1], hq.y, w1);
                    fma2(aN[2 * q + 1], hq.y, w2);
                }
            }
        }
        asm volatile("cp.async.wait_group 0;");
        asm volatile("bar.sync %0, 256;" :: "r"(1 + half) : "memory");
        if (j < HH) {
#pragma unroll
            for (int p = 0; p < BP; p++) {
                int gp = pbase + p;
                float hr[2], hz[2], hn[2], hnew[2];
                unpack2(aR[p], hr[0], hr[1]);
                unpack2(aZ[p], hz[0], hz[1]);
                unpack2(aN[p], hn[0], hn[1]);
                float2 hold = hsT[j * PW + gp];
#pragma unroll
                for (int l = 0; l < 2; l++) {
                    int b = 2 * gp + l;
                    const float* gx = gxs_ + b * 600;
                    float r = sigmoidf_(gx[j] + hr[l] + br);
                    float z = sigmoidf_(gx[HH + j] + hz[l] + bz);
                    float nn = tanha_(gx[2 * HH + j] + bin + r * (hn[l] + bhn));
                    float ho = l ? hold.y : hold.x;
                    hnew[l] = (1.f - z) * nn + z * ho;
                    if (tt < sln[b]) pool_s[b * HH + j] += hnew[l];
                }
                hsT[j * PW + gp] = make_float2(hnew[0], hnew[1]);
            }
        }
        asm volatile("bar.sync %0, 256;" :: "r"(1 + half) : "memory");
    }

    if (j < HH) {
#pragma unroll
        for (int p = 0; p < BP; p++) {
#pragma unroll
            for (int l = 0; l < 2; l++) {
                int b = 2 * (pbase + p) + l;
                int ln = sln[b];
                float v = pool_s[b * HH + j];
                g_poold[(size_t)(b0 + b) * (2 * HH) + (size_t)dir * HH + j] =
                    ln ? v / (float)ln : 0.f;
            }
        }
    }
}

// ---------------- prep ----------------
__global__ void k_prep(const int* __restrict__ x,
                       const float* __restrict__ wf_ih, const float* __restrict__ wb_ih,
                       const float* __restrict__ sf_ih, const float* __restrict__ sb_ih,
                       const float* __restrict__ wf_hh, const float* __restrict__ wb_hh,
                       const float* __restrict__ sf_hh, const float* __restrict__ sb_hh) {
    int i0 = blockIdx.x * blockDim.x + threadIdx.x;
    int gs = gridDim.x * blockDim.x;
    const float* wss[2] = {sf_hh, sb_hh};
    for (int idx = i0; idx < HH * HH; idx += gs) {
        int k = idx / HH, j = idx % HH;
#pragma unroll
        for (int a = 0; a < 2; a++) {
            g_wP[a][idx] = make_float4(wss[a][j * HH + k],
                                       wss[a][(HH + j) * HH + k],
                                       wss[a][(2 * HH + j) * HH + k], 0.f);
        }
    }
    const float* wsw[2] = {wf_hh, wb_hh};
    const int TOT = 2 * MT_ * KT_ * 32 * 4;
    for (int idx = i0; idx < TOT; idx += gs) {
        int rr = idx & 3;
        int lane = (idx >> 2) & 31;
        int kt = (idx >> 7) % KT_;
        int mt = (idx / (KT_ * 32 * 4)) % MT_;
        int a = idx / (MT_ * KT_ * 32 * 4);
        int gid = lane >> 2, tig = lane & 3;
        int row = mt * 16 + gid + (rr & 1) * 8;
        int k0 = kt * 16 + tig * 2 + ((rr >> 1) & 1) * 8;
        float w0 = (row < GG && k0 < HH) ? wsw[a][row * HH + k0] : 0.f;
        float w1 = (row < GG && k0 + 1 < HH) ? wsw[a][row * HH + k0 + 1] : 0.f;
        __nv_bfloat16 h0 = __float2bfloat16(w0);
        __nv_bfloat16 h1 = __float2bfloat16(w1);
        unsigned int hiw = ((unsigned int)__bfloat16_as_ushort(h1) << 16) |
                           (unsigned int)__bfloat16_as_ushort(h0);
        g_Wf[a][(((size_t)mt * KT_ + kt) * 32 + lane) * 4 + rr] = hiw;
    }
    for (int idx = i0; idx < GXW * KPE; idx += gs) {
        int r = idx / KPE, k = idx - r * KPE;
        float v = 0.f;
        if (k < DD) v = (r < GG) ? wf_ih[r * DD + k] : wb_ih[(r - GG) * DD + k];
        g_WihB[idx] = __float2bfloat16(v);
    }
    for (int idx = i0; idx < GXW * 400; idx += gs) {
        int r = idx / 400, k = idx - r * 400;
        float v = (r < GG) ? sf_ih[r * 400 + k] : sb_ih[(r - GG) * 400 + k];
        g_SihB[idx] = __float2bfloat16(v);
    }
    for (int s = i0; s < NS; s += gs) {
        int c = 0;
        for (int t = 0; t < TW; t++) c += (x[s * TW + t] != 0);
        g_slen[s] = c;
    }
}

__global__ void k_scan(const int* __restrict__ dl) {
    if (threadIdx.x == 0) {
        int a = 0;
        for (int i = 0; i < ND; i++) { g_offs[i] = a; a += dl[i]; }
    }
}

__global__ __launch_bounds__(128) void k_final(const int* __restrict__ dl,
                                               const float* __restrict__ doc_w,
                                               const float* __restrict__ doc_b,
                                               const float* __restrict__ sent_w,
                                               const float* __restrict__ sent_b,
                                               float* __restrict__ out) {
    __shared__ float d[2 * HH];
    __shared__ float redw[4];
    int doc = blockIdx.x, tid = threadIdx.x;
    int l = dl[doc];
    for (int f = tid; f < 2 * HH; f += 128)
        d[f] = g_poold[doc * 2 * HH + f];
    __syncthreads();
    for (int r = 0; r < 11; r++) {
        const float* w = (r == 0) ? doc_w : sent_w + (r - 1) * 2 * HH;
        float p = 0.f;
        for (int f = tid; f < 2 * HH; f += 128) p += d[f] * w[f];
        for (int o = 16; o; o >>= 1) p += __shfl_down_sync(0xFFFFFFFFu, p, o);
        if ((tid & 31) == 0) redw[tid >> 5] = p;
        __syncthreads();
        if (tid == 0) {
            float s = redw[0] + redw[1] + redw[2] + redw[3];
            if (r == 0) out[doc] = sigmoidf_(s + doc_b[0]);
            else if (r - 1 < l) out[ND + g_offs[doc] + (r - 1)] = sigmoidf_(s + sent_b[r - 1]);
        }
        __syncthreads();
    }
}

// ---------------- host ----------------
extern "C" void kernel_launch(void* const* d_in, const int* in_sizes, int n_in,
                              void* d_out, int out_size) {
    int base = (n_in >= 24) ? 1 : 0;
    const int*   x        = (const int*)d_in[0];
    const int*   doc_lens = (const int*)d_in[1 + base];
    const float* emb      = (const float*)d_in[2 + base];
    const float* wf_ih    = (const float*)d_in[3 + base];
    const float* wf_hh    = (const float*)d_in[4 + base];
    const float* wf_bi    = (const float*)d_in[5 + base];
    const float* wf_bh    = (const float*)d_in[6 + base];
    const float* wb_ih    = (const float*)d_in[7 + base];
    const float* wb_hh    = (const float*)d_in[8 + base];
    const float* wb_bi    = (const float*)d_in[9 + base];
    const float* wb_bh    = (const float*)d_in[10 + base];
    const float* sf_ih    = (const float*)d_in[11 + base];
    const float* sf_hh    = (const float*)d_in[12 + base];
    const float* sf_bi    = (const float*)d_in[13 + base];
    const float* sf_bh    = (const float*)d_in[14 + base];
    const float* sb_ih    = (const float*)d_in[15 + base];
    const float* sb_hh    = (const float*)d_in[16 + base];
    const float* sb_bi    = (const float*)d_in[17 + base];
    const float* sb_bh    = (const float*)d_in[18 + base];
    const float* doc_w    = (const float*)d_in[19 + base];
    const float* doc_b    = (const float*)d_in[20 + base];
    const float* sent_w   = (const float*)d_in[21 + base];
    const float* sent_b   = (const float*)d_in[22 + base];
    float* out = (float*)d_out;

    void *P, *gxs, *pool, *wihB, *sihB;
    cudaGetSymbolAddress(&P, g_P);
    cudaGetSymbolAddress(&gxs, g_gxs);
    cudaGetSymbolAddress(&pool, g_pool);
    cudaGetSymbolAddress(&wihB, g_WihB);
    cudaGetSymbolAddress(&sihB, g_SihB);

    const int SMB = (2 * 128 * 40 + 2 * 64 * 40) * 2;
    const int SMP = (128 * SA + 2 * 64 * SA) * 2;
    const int SMW = 174560;
    const int SMS = HH * 8 * 8 + 16 * 600 * 4 + 16 * HH * 4 + DT * 16 * 4 + 16 * 4;
    cudaFuncSetAttribute(gemm_strip,
                         cudaFuncAttributeMaxDynamicSharedMemorySize, SMP);
    cudaFuncSetAttribute(gemm_bf16,
                         cudaFuncAttributeMaxDynamicSharedMemorySize, SMB);
    cudaFuncSetAttribute(gru_tc,
                         cudaFuncAttributeMaxDynamicSharedMemorySize, SMW);
    cudaFuncSetAttribute(gru_seq_s<16>,
                         cudaFuncAttributeMaxDynamicSharedMemorySize, SMS);

    k_prep<<<512, 256>>>(x, wf_ih, wb_ih, sf_ih, sb_ih,
                         wf_hh, wb_hh, sf_hh, sb_hh);

    // P = emb(fp32) @ WihB^T — strip GEMM with in-kernel bf16 conversion
    gemm_strip<<<(VOC + 127) / 128, 256, SMP>>>(
        emb, (const __nv_bfloat16*)wihB, (__nv_bfloat16*)P, VOC);

    // word-level BiGRU
    gru_tc<<<dim3(NS / BR_, 2), 512, SMW>>>(x, wf_bi, wf_bh, wb_bi, wb_bh);

    // sentence gates
    gemm_bf16<<<dim3((GXW + 63) / 64, (NS + 127) / 128), 256, SMB>>>(
        (const __nv_bfloat16*)pool, (const __nv_bfloat16*)sihB, (float*)gxs,
        NS, GXW, 400, GXW);

    // sentence-level BiGRU
    gru_seq_s<16><<<dim3(ND / 16, 2), 512, SMS>>>(
        doc_lens, sf_bi, sf_bh, sb_bi, sb_bh);

    k_scan<<<1, 32>>>(doc_lens);
    k_final<<<ND, 128>>>(doc_lens, doc_w, doc_b, sent_w, sent_b, out);
}